// round 1
// baseline (speedup 1.0000x reference)
#include <cuda_runtime.h>
#include <math.h>

#define BN 4096
#define DD 512
#define NT 4
#define NC 65
#define TC 69          // NT + NC
#define NS 4165        // TC + BN

// ---------------- scratch (device globals; no allocations) ----------------
__device__ float g_xm[BN*DD];
__device__ float g_q[BN*DD];
__device__ float g_kall[NS*DD];
__device__ float g_hA[NS*DD];
__device__ float g_hB[NS*DD];
__device__ float g_hw[NS*DD];
__device__ float g_tsum[NT*DD];
__device__ float g_csum[NC*DD];
__device__ int   g_cntT[NT];
__device__ int   g_cntC[NC];
__device__ float g_adj[TC*TC];
__device__ float g_cross[NT*NC];
__device__ float g_cf[BN*TC];
__device__ float g_l69[BN*TC];
__device__ float g_mp[2*BN];
__device__ float g_zp[2*BN];
__device__ float g_C69[TC*DD];

// ---------------- xm = mean over 7x7; also write src rows 69.. -------------
__global__ void k_xm(const float* __restrict__ x) {
    __shared__ float buf[4][32*49];
    int w = threadIdx.x >> 5, lane = threadIdx.x & 31;
    int base = (blockIdx.x*4 + w) * 32;              // first segment for this warp
    const float* src = x + (size_t)base*49;
    float* b = buf[w];
    #pragma unroll
    for (int t = 0; t < 49; t++) b[lane + 32*t] = src[lane + 32*t];
    __syncwarp();
    float s = 0.f;
    #pragma unroll
    for (int t = 0; t < 49; t++) s += b[lane*49 + t]; // stride 49 -> conflict-free
    s *= (1.f/49.f);
    int seg = base + lane;                            // seg = b*512 + d
    g_xm[seg] = s;
    g_hA[TC*DD + seg] = s;
}

// ---------------- zeroing kernels ----------------
__global__ void k_zero_seg() {
    int i = blockIdx.x*256 + threadIdx.x;
    if (i < NT*DD) g_tsum[i] = 0.f;
    if (i < NC*DD) g_csum[i] = 0.f;
    if (i < NT) g_cntT[i] = 0;
    if (i < NC) g_cntC[i] = 0;
}
__global__ void k_zero_c69() {
    int i = blockIdx.x*256 + threadIdx.x;
    if (i < TC*DD) g_C69[i] = 0.f;
}

// ---------------- segment counts ----------------
__global__ void k_count(const int* __restrict__ to, const int* __restrict__ lb) {
    int i = blockIdx.x*256 + threadIdx.x;
    if (i < BN) { atomicAdd(&g_cntT[to[i]], 1); atomicAdd(&g_cntC[lb[i]], 1); }
}

// ---------------- segment sums (smem tile + gmem atomics) ----------------
__global__ void k_segsum(const int* __restrict__ to, const int* __restrict__ lb) {
    __shared__ float sT[NT][64];
    __shared__ float sC[NC][64];
    int t = threadIdx.x;
    int cr = t & 63, rr = t >> 6;
    int r0 = blockIdx.y * 256, c0 = blockIdx.x * 64;
    for (int i = t; i < NT*64; i += 256) ((float*)sT)[i] = 0.f;
    for (int i = t; i < NC*64; i += 256) ((float*)sC)[i] = 0.f;
    __syncthreads();
    for (int r = r0 + rr; r < r0 + 256; r += 4) {
        int tt = to[r], cc = lb[r];
        float v = g_xm[r*DD + c0 + cr];
        atomicAdd(&sT[tt][cr], v);
        atomicAdd(&sC[cc][cr], v);
    }
    __syncthreads();
    for (int i = t; i < NT*64; i += 256)
        atomicAdd(&g_tsum[(i>>6)*DD + c0 + (i&63)], ((float*)sT)[i]);
    for (int i = t; i < NC*64; i += 256)
        atomicAdd(&g_csum[(i>>6)*DD + c0 + (i&63)], ((float*)sC)[i]);
}

// ---------------- t1/c1 -> src rows 0..68 ----------------
__global__ void k_t1c1(const float* __restrict__ trep, const float* __restrict__ cpro) {
    int i = blockIdx.x*256 + threadIdx.x;
    if (i >= TC*DD) return;
    int seg = i / DD, d = i % DD;
    float v;
    if (seg < NT) {
        float cnt = fmaxf((float)g_cntT[seg], 1.f);
        v = 0.9f*trep[i] + 0.1f*g_tsum[i]/cnt;
    } else {
        int c = seg - NT;
        float cnt = fmaxf((float)g_cntC[c], 1.f);
        v = 0.9f*cpro[c*DD+d] + 0.1f*g_csum[c*DD+d]/cnt;
    }
    g_hA[i] = v;
}

// ---------------- d2 -> cross_graph (softmax over tasks) + adj cross blocks --
__global__ void k_d2cross() {
    int c = blockIdx.x;                    // 65 blocks, 128 threads (4 warps)
    int w = threadIdx.x >> 5, lane = threadIdx.x & 31;
    __shared__ float sd2[NT];
    const float* t1 = g_hA;
    const float* c1 = g_hA + NT*DD;
    float s = 0.f;
    for (int d = lane; d < DD; d += 32) {
        float df = t1[w*DD+d] - c1[c*DD+d];
        s += df*df;
    }
    #pragma unroll
    for (int o = 16; o; o >>= 1) s += __shfl_xor_sync(0xffffffffu, s, o);
    if (lane == 0) sd2[w] = s;
    __syncthreads();
    if (threadIdx.x == 0) {
        float l[NT], mx = -1e30f;
        for (int t = 0; t < NT; t++) { l[t] = -sd2[t]*(1.f/16.f); mx = fmaxf(mx, l[t]); }
        float Z = 0.f;
        for (int t = 0; t < NT; t++) { l[t] = expf(l[t]-mx); Z += l[t]; }
        for (int t = 0; t < NT; t++) {
            float p = l[t]/Z;
            g_cross[t*NC + c] = p;
            g_adj[t*TC + NT + c] = p;
            g_adj[(NT+c)*TC + t] = p;
        }
    }
}

// ---------------- tg (4x4) ----------------
__global__ void k_tg(const float* __restrict__ tw, const float* __restrict__ tb) {
    int i = blockIdx.x >> 2, j = blockIdx.x & 3;
    int lane = threadIdx.x;
    const float* t1 = g_hA;
    float s = 0.f;
    for (int d = lane; d < DD; d += 32)
        s += fabsf(t1[i*DD+d]-t1[j*DD+d]) * tw[d];
    #pragma unroll
    for (int o = 16; o; o >>= 1) s += __shfl_xor_sync(0xffffffffu, s, o);
    if (lane == 0) {
        float v = 1.f/(1.f+expf(-(s + tb[0])));
        if (i == j) v = 0.f;
        g_adj[i*TC+j] = v;
    }
}

// ---------------- cg (65x65) ----------------
__global__ void k_cg(const float* __restrict__ cw, const float* __restrict__ cb) {
    int i = blockIdx.x, j = blockIdx.y;
    int lane = threadIdx.x;
    const float* c1 = g_hA + NT*DD;
    float s = 0.f;
    for (int d = lane; d < DD; d += 32)
        s += fabsf(c1[i*DD+d]-c1[j*DD+d]) * cw[d];
    #pragma unroll
    for (int o = 16; o; o >>= 1) s += __shfl_xor_sync(0xffffffffu, s, o);
    if (lane == 0) {
        float v = 1.f/(1.f+expf(-(s + cb[0])));
        if (i == j) v = 0.f;
        g_adj[(NT+i)*TC + NT+j] = v;
    }
}

// ---------------- ae_loss ----------------
__global__ void k_ae(float* out) {
    __shared__ float s[NC];
    int c = threadIdx.x;   // 65 threads
    float a = 0.f;
    for (int t = 0; t < NT; t++) { float p = g_cross[t*NC+c]; a += p*logf(p); }
    s[c] = a;
    __syncthreads();
    if (c == 0) { float r = 0.f; for (int i = 0; i < NC; i++) r += s[i]; out[0] = r/(float)NC; }
}

// ---------------- generic tiled fp32 GEMM: C = A@B ----------------
// asel: 0=g_xm  1=g_hA  2=g_hB ; csel: 0=g_q 1=g_kall 2=g_kall+TC*DD 3=g_hw
__global__ void k_gemm(int asel, const float* __restrict__ Bm, int csel,
                       int M, int N, int K) {
    const float* A = (asel==0) ? g_xm : (asel==1) ? g_hA : g_hB;
    float* C = (csel==0) ? g_q : (csel==1) ? g_kall : (csel==2) ? (g_kall + TC*DD) : g_hw;
    __shared__ float As[16][68];
    __shared__ float Bs[16][68];
    int t = threadIdx.x, tx = t & 15, ty = t >> 4;
    int m0 = blockIdx.y*64, n0 = blockIdx.x*64;
    float acc[4][4] = {};
    for (int k0 = 0; k0 < K; k0 += 16) {
        #pragma unroll
        for (int i = t; i < 1024; i += 256) {
            int m = i >> 4, kk = i & 15;
            float v = 0.f;
            if (m0+m < M && k0+kk < K) v = A[(size_t)(m0+m)*K + k0+kk];
            As[kk][m] = v;
        }
        #pragma unroll
        for (int i = t; i < 1024; i += 256) {
            int kk = i >> 6, n = i & 63;
            float v = 0.f;
            if (n0+n < N && k0+kk < K) v = Bm[(size_t)(k0+kk)*N + n0+n];
            Bs[kk][n] = v;
        }
        __syncthreads();
        #pragma unroll
        for (int kk = 0; kk < 16; kk++) {
            float a4[4], b4[4];
            *(float4*)a4 = *(const float4*)&As[kk][ty*4];
            *(float4*)b4 = *(const float4*)&Bs[kk][tx*4];
            #pragma unroll
            for (int i = 0; i < 4; i++)
                #pragma unroll
                for (int j = 0; j < 4; j++)
                    acc[i][j] += a4[i]*b4[j];
        }
        __syncthreads();
    }
    #pragma unroll
    for (int i = 0; i < 4; i++)
        #pragma unroll
        for (int j = 0; j < 4; j++) {
            int m = m0+ty*4+i, n = n0+tx*4+j;
            if (m < M && n < N) C[(size_t)m*N + n] = acc[i][j];
        }
}

// ---------------- attention: streaming softmax stats + first-69 logits -----
// grid (64 row-tiles, 2 j-splits), 256 threads, dynamic smem
#define AJT 33
#define SMEM_ATTN ((512*68 + 16*68 + 64*16 + 128)*4)
__global__ void k_attn() {
    extern __shared__ float sm[];
    float* Qs = sm;                  // [512][68] transposed q tile
    float* Ks = Qs + 512*68;         // [16][68]
    float* red = Ks + 16*68;         // [64][16]
    float* ms  = red + 64*16;        // [64]
    float* zs  = ms + 64;            // [64]
    int t = threadIdx.x, tx = t & 15, ty = t >> 4;
    int i0 = blockIdx.x * 64;
    int split = blockIdx.y;
    for (int i = t; i < 64*512; i += 256) {
        int k = i & 511, r = i >> 9;
        Qs[k*68 + r] = g_q[(size_t)(i0+r)*DD + k];
    }
    if (t < 64) { ms[t] = -1e30f; zs[t] = 0.f; }
    __syncthreads();
    const float sc = 0.044194173824159216f;   // 1/sqrt(512)
    int jt0 = split*AJT, jt1 = jt0 + AJT;
    for (int jt = jt0; jt < jt1; jt++) {
        int j0 = jt*64;
        float acc[4][4] = {};
        for (int k0 = 0; k0 < DD; k0 += 16) {
            #pragma unroll
            for (int i = t; i < 1024; i += 256) {
                int kk = i >> 6, j = i & 63;
                float v = 0.f;
                int jr = j0 + j;
                if (jr < NS) v = g_kall[(size_t)jr*DD + k0 + kk];
                Ks[kk*68 + j] = v;
            }
            __syncthreads();
            #pragma unroll
            for (int kk = 0; kk < 16; kk++) {
                float a4[4], b4[4];
                *(float4*)a4 = *(const float4*)&Qs[(k0+kk)*68 + ty*4];
                *(float4*)b4 = *(const float4*)&Ks[kk*68 + tx*4];
                #pragma unroll
                for (int i = 0; i < 4; i++)
                    #pragma unroll
                    for (int j = 0; j < 4; j++)
                        acc[i][j] += a4[i]*b4[j];
            }
            __syncthreads();
        }
        #pragma unroll
        for (int i = 0; i < 4; i++) {
            float rmax = -1e30f;
            #pragma unroll
            for (int j = 0; j < 4; j++) {
                int jg = j0 + tx*4 + j;
                float s = (jg < NS) ? acc[i][j]*sc : -1e30f;
                acc[i][j] = s;
                rmax = fmaxf(rmax, s);
                if (jg < TC) g_l69[(size_t)(i0+ty*4+i)*TC + jg] = s;
            }
            red[(ty*4+i)*16 + tx] = rmax;
        }
        __syncthreads();
        if (t < 64) {
            float tm = -1e30f;
            #pragma unroll
            for (int x = 0; x < 16; x++) tm = fmaxf(tm, red[t*16+x]);
            float old = ms[t];
            float nm = fmaxf(old, tm);
            zs[t] *= expf(old - nm);      // old=-1e30 -> factor 0, zs was 0
            ms[t] = nm;
        }
        __syncthreads();
        #pragma unroll
        for (int i = 0; i < 4; i++) {
            float m = ms[ty*4+i];
            float ps = 0.f;
            #pragma unroll
            for (int j = 0; j < 4; j++) ps += expf(acc[i][j] - m);
            red[(ty*4+i)*16 + tx] = ps;
        }
        __syncthreads();
        if (t < 64) {
            float s = 0.f;
            #pragma unroll
            for (int x = 0; x < 16; x++) s += red[t*16+x];
            zs[t] += s;
        }
        __syncthreads();
    }
    if (t < 64) {
        g_mp[split*BN + i0 + t] = ms[t];
        g_zp[split*BN + i0 + t] = zs[t];
    }
}

// ---------------- combine splits -> cross_feat ----------------
__global__ void k_cf() {
    int i = blockIdx.x;         // 4096
    int j = threadIdx.x;        // 96
    __shared__ float sh[2];
    if (j == 0) {
        float m0 = g_mp[i], m1 = g_mp[BN+i];
        float mm = fmaxf(m0, m1);
        float z = g_zp[i]*expf(m0-mm) + g_zp[BN+i]*expf(m1-mm);
        sh[0] = mm; sh[1] = 1.f/z;
    }
    __syncthreads();
    if (j < TC) g_cf[i*TC + j] = expf(g_l69[i*TC+j] - sh[0]) * sh[1];
}

// ---------------- GNN x-rows: relu(cross_feat @ hw_tc + b) -----------------
__global__ void k_outx(int dst, const float* __restrict__ gb) {
    float* H = (dst == 0) ? g_hB : g_hA;
    __shared__ float cfs[64][72];
    __shared__ float hws[69][68];
    int t = threadIdx.x, tx = t & 15, ty = t >> 4;
    int b0 = blockIdx.y*64, n0 = blockIdx.x*64;
    for (int i = t; i < 64*TC; i += 256) {
        int r = i/TC, k = i%TC;
        cfs[r][k] = g_cf[(size_t)(b0+r)*TC + k];
    }
    for (int i = t; i < TC*64; i += 256) {
        int k = i >> 6, n = i & 63;
        hws[k][n] = g_hw[(size_t)k*DD + n0 + n];
    }
    __syncthreads();
    float acc[4][4] = {};
    for (int k = 0; k < TC; k++) {
        float a4[4], b4[4];
        #pragma unroll
        for (int i = 0; i < 4; i++) a4[i] = cfs[ty*4+i][k];
        *(float4*)b4 = *(const float4*)&hws[k][tx*4];
        #pragma unroll
        for (int i = 0; i < 4; i++)
            #pragma unroll
            for (int j = 0; j < 4; j++)
                acc[i][j] += a4[i]*b4[j];
    }
    #pragma unroll
    for (int i = 0; i < 4; i++)
        #pragma unroll
        for (int j = 0; j < 4; j++) {
            int b = b0+ty*4+i, n = n0+tx*4+j;
            float v = acc[i][j] + gb[n];
            H[(size_t)(TC+b)*DD + n] = fmaxf(v, 0.f);
        }
}

// ---------------- GNN tc-rows partial: C69 += cross_feat.T @ hw_x ----------
__global__ void k_outtc() {
    __shared__ float cfs[64][72];
    __shared__ float hws[64][64];
    int t = threadIdx.x, tx = t & 63, ty = t >> 6;
    int n0 = blockIdx.x*64;
    int b0 = blockIdx.y*256;
    float acc[18];
    #pragma unroll
    for (int k = 0; k < 18; k++) acc[k] = 0.f;
    for (int bc = 0; bc < 256; bc += 64) {
        int bb = b0 + bc;
        for (int i = t; i < 64*TC; i += 256) {
            int r = i/TC, k = i%TC;
            cfs[r][k] = g_cf[(size_t)(bb+r)*TC + k];
        }
        for (int i = t; i < 64*64; i += 256) {
            int r = i >> 6, n = i & 63;
            hws[r][n] = g_hw[(size_t)(TC+bb+r)*DD + n0 + n];
        }
        __syncthreads();
        for (int r = 0; r < 64; r++) {
            float hv = hws[r][tx];
            #pragma unroll
            for (int k = 0; k < 18; k++) {
                int m = ty + 4*k;
                if (m < TC) acc[k] += cfs[r][m]*hv;
            }
        }
        __syncthreads();
    }
    #pragma unroll
    for (int k = 0; k < 18; k++) {
        int m = ty + 4*k;
        if (m < TC) atomicAdd(&g_C69[m*DD + n0 + tx], acc[k]);
    }
}

// ---------------- finalize tc rows: + adj@hw_tc + bias, relu ---------------
__global__ void k_fintc(int dst, const float* __restrict__ gb) {
    float* H = (dst == 0) ? g_hB : g_hA;
    int m = blockIdx.x;      // 69
    int n = threadIdx.x;     // 512
    float v = g_C69[m*DD + n];
    for (int j = 0; j < TC; j++)
        v += g_adj[m*TC+j] * g_hw[j*DD + n];
    v += gb[n];
    H[m*DD + n] = fmaxf(v, 0.f);
}

// ---------------- y = tcw[to] * (h_x @ base_w + base_b) --------------------
__global__ void k_y(const float* __restrict__ bw, const float* __restrict__ bb,
                    const float* __restrict__ tcw, const int* __restrict__ to,
                    float* out, int y_off) {
    __shared__ float Hs[64][17];
    __shared__ float Ws[16][65];
    int t = threadIdx.x;                 // 260 threads
    int c = t % 65, ry = t / 65;         // ry 0..3
    int b0 = blockIdx.x * 64;
    float acc[16];
    #pragma unroll
    for (int i = 0; i < 16; i++) acc[i] = 0.f;
    for (int d0 = 0; d0 < DD; d0 += 16) {
        for (int i = t; i < 64*16; i += 260) {
            int r = i >> 4, dd = i & 15;
            Hs[r][dd] = g_hA[(size_t)(TC + b0 + r)*DD + d0 + dd];
        }
        for (int i = t; i < 16*65; i += 260) {
            int dd = i / 65, cc = i % 65;
            Ws[dd][cc] = bw[(size_t)(d0+dd)*NC + cc];
        }
        __syncthreads();
        #pragma unroll
        for (int dd = 0; dd < 16; dd++) {
            float wv = Ws[dd][c];
            #pragma unroll
            for (int i = 0; i < 16; i++)
                acc[i] += Hs[ry + 4*i][dd] * wv;
        }
        __syncthreads();
    }
    float bbv = bb[c];
    #pragma unroll
    for (int i = 0; i < 16; i++) {
        int b = b0 + ry + 4*i;
        float scl = tcw[to[b]*NC + c];
        out[y_off + (size_t)b*NC + c] = scl * (acc[i] + bbv);
    }
}

// ---------------- labels passthrough ----------------
__global__ void k_labels(const int* __restrict__ lb, float* out, int off, int out_size) {
    int i = blockIdx.x*256 + threadIdx.x;
    if (i < BN && off + i < out_size) out[off + i] = (float)lb[i];
}

// ======================== host ========================
extern "C" void kernel_launch(void* const* d_in, const int* in_sizes, int n_in,
                              void* d_out, int out_size) {
    const float* x    = (const float*)d_in[0];
    const int*   lb   = (const int*)d_in[1];
    const int*   to   = (const int*)d_in[2];
    const float* trep = (const float*)d_in[3];
    const float* cpro = (const float*)d_in[4];
    const float* tw   = (const float*)d_in[5];
    const float* tb   = (const float*)d_in[6];
    const float* cw   = (const float*)d_in[7];
    const float* cb   = (const float*)d_in[8];
    const float* wq   = (const float*)d_in[9];
    const float* wk   = (const float*)d_in[10];
    const float* gw   = (const float*)d_in[11];
    const float* gb   = (const float*)d_in[12];
    const float* bw   = (const float*)d_in[13];
    const float* bb   = (const float*)d_in[14];
    const float* tcw  = (const float*)d_in[15];
    float* out = (float*)d_out;

    cudaFuncSetAttribute(k_attn, cudaFuncAttributeMaxDynamicSharedMemorySize, SMEM_ATTN);

    int y_off = (out_size > BN*NC) ? 1 : 0;
    int lbl_off = y_off + BN*NC;

    // 1. xm + src x-rows
    k_xm<<<16384, 128>>>(x);
    // 2. segment means
    k_zero_seg<<<(NC*DD + 255)/256, 256>>>();
    k_count<<<16, 256>>>(to, lb);
    k_segsum<<<dim3(8, 16), 256>>>(to, lb);
    k_t1c1<<<(TC*DD + 255)/256, 256>>>(trep, cpro);
    // 3. graphs
    k_d2cross<<<65, 128>>>();
    k_tg<<<16, 32>>>(tw, tb);
    k_cg<<<dim3(65, 65), 32>>>(cw, cb);
    if (y_off) k_ae<<<1, 65>>>(out);
    // 4. projections: q, k_x, k_tc
    k_gemm<<<dim3(8, 64), 256>>>(0, wq, 0, BN, DD, DD);
    k_gemm<<<dim3(8, 64), 256>>>(0, wk, 2, BN, DD, DD);
    k_gemm<<<dim3(8, 2),  256>>>(1, wk, 1, TC, DD, DD);
    // 5. attention softmax stats + cross_feat
    k_attn<<<dim3(64, 2), 256, SMEM_ATTN>>>();
    k_cf<<<4096, 96>>>();
    // 6. GNN layer 0: hA -> hB
    k_gemm<<<dim3(8, 66), 256>>>(1, gw, 3, NS, DD, DD);
    k_zero_c69<<<(TC*DD + 255)/256, 256>>>();
    k_outtc<<<dim3(8, 16), 256>>>();
    k_outx<<<dim3(8, 64), 256>>>(0, gb);
    k_fintc<<<69, 512>>>(0, gb);
    // 7. GNN layer 1: hB -> hA
    k_gemm<<<dim3(8, 66), 256>>>(2, gw + DD*DD, 3, NS, DD, DD);
    k_zero_c69<<<(TC*DD + 255)/256, 256>>>();
    k_outtc<<<dim3(8, 16), 256>>>();
    k_outx<<<dim3(8, 64), 256>>>(1, gb + DD);
    k_fintc<<<69, 512>>>(1, gb + DD);
    // 8. outputs
    k_y<<<64, 260>>>(bw, bb, tcw, to, out, y_off);
    k_labels<<<16, 256>>>(lb, out, lbl_off, out_size);
}

// round 2
// speedup vs baseline: 3.1191x; 3.1191x over previous
#include <cuda_runtime.h>
#include <math.h>
#include <stdint.h>

#define BN 4096
#define DD 512
#define NT 4
#define NC 65
#define TC 69          // NT + NC
#define NS 4165        // TC + BN
#define CFLD 72        // padded cf row stride

// ---------------- scratch (device globals; no allocations) ----------------
__device__ float g_xm[BN*DD];
__device__ float g_q[BN*DD];
__device__ float g_kall[NS*DD];
__device__ float g_hA[NS*DD];
__device__ float g_hB[NS*DD];
__device__ float g_hw[NS*DD];
__device__ float g_tsum[NT*DD];
__device__ float g_csum[NC*DD];
__device__ int   g_cntT[NT];
__device__ int   g_cntC[NC];
__device__ float g_adj[TC*TC];
__device__ float g_cross[NT*NC];
__device__ float g_cf[BN*CFLD];
__device__ float g_l69[BN*TC];
__device__ float g_mp[8*BN];
__device__ float g_zp[8*BN];
__device__ float g_C69[TC*DD];
__device__ float g_wqT[DD*DD];
__device__ float g_wkT[DD*DD];
__device__ float g_gwT[2*DD*DD];
__device__ float g_bwT[NC*DD];
__device__ float g_hwtcT[DD*CFLD];
__device__ float g_yraw[BN*NC];

// ---------------- tf32 helpers ----------------
__device__ __forceinline__ float tf32r(float x) {
    uint32_t u;
    asm("cvt.rna.tf32.f32 %0, %1;" : "=r"(u) : "f"(x));
    return __uint_as_float(u);
}
__device__ __forceinline__ void mma8(float* c, uint32_t a0, uint32_t a1,
                                     uint32_t a2, uint32_t a3,
                                     uint32_t b0, uint32_t b1) {
    asm("mma.sync.aligned.m16n8k8.row.col.f32.tf32.tf32.f32 "
        "{%0,%1,%2,%3},{%4,%5,%6,%7},{%8,%9},{%0,%1,%2,%3};"
        : "+f"(c[0]), "+f"(c[1]), "+f"(c[2]), "+f"(c[3])
        : "r"(a0), "r"(a1), "r"(a2), "r"(a3), "r"(b0), "r"(b1));
}
__device__ __forceinline__ uint32_t fb(float x) { return __float_as_uint(x); }

// ---------------- pointer selectors ----------------
__device__ __forceinline__ const float* selA(int s) {
    switch (s) {
        case 0: return g_xm;   case 1: return g_hA;   case 2: return g_hB;
        case 3: return g_q;    case 4: return g_kall; case 6: return g_wqT;
        case 7: return g_wkT;  case 8: return g_gwT;  case 9: return g_gwT + DD*DD;
        case 10: return g_bwT; case 11: return g_hwtcT; case 12: return g_cf;
        case 17: return g_hA + TC*DD; case 18: return g_hB + TC*DD;
    }
    return g_xm;
}
__device__ __forceinline__ float* selC(int s) {
    switch (s) {
        case 3: return g_q;   case 4: return g_kall; case 5: return g_hw;
        case 13: return g_l69; case 14: return g_yraw;
        case 15: return g_hB + TC*DD; case 16: return g_hA + TC*DD;
    }
    return g_q;
}
__device__ __forceinline__ float* selT(int s) {
    switch (s) {
        case 0: return g_wqT; case 1: return g_wkT; case 2: return g_gwT;
        case 3: return g_gwT + DD*DD; case 4: return g_bwT; case 5: return g_hwtcT;
    }
    return g_wqT;
}

// ---------------- xm = mean over 7x7; also write src rows 69.. -------------
__global__ void k_xm(const float* __restrict__ x) {
    __shared__ float buf[4][32*49];
    int w = threadIdx.x >> 5, lane = threadIdx.x & 31;
    int base = (blockIdx.x*4 + w) * 32;
    const float* src = x + (size_t)base*49;
    float* b = buf[w];
    #pragma unroll
    for (int t = 0; t < 49; t++) b[lane + 32*t] = src[lane + 32*t];
    __syncwarp();
    float s = 0.f;
    #pragma unroll
    for (int t = 0; t < 49; t++) s += b[lane*49 + t];
    s *= (1.f/49.f);
    int seg = base + lane;
    g_xm[seg] = s;
    g_hA[TC*DD + seg] = s;
}

// ---------------- zero / counts / segsum / t1c1 (unchanged) ----------------
__global__ void k_zero_seg() {
    int i = blockIdx.x*256 + threadIdx.x;
    if (i < NT*DD) g_tsum[i] = 0.f;
    if (i < NC*DD) g_csum[i] = 0.f;
    if (i < NT) g_cntT[i] = 0;
    if (i < NC) g_cntC[i] = 0;
}
__global__ void k_zero_c69() {
    int i = blockIdx.x*256 + threadIdx.x;
    if (i < TC*DD) g_C69[i] = 0.f;
}
__global__ void k_count(const int* __restrict__ to, const int* __restrict__ lb) {
    int i = blockIdx.x*256 + threadIdx.x;
    if (i < BN) { atomicAdd(&g_cntT[to[i]], 1); atomicAdd(&g_cntC[lb[i]], 1); }
}
__global__ void k_segsum(const int* __restrict__ to, const int* __restrict__ lb) {
    __shared__ float sT[NT][64];
    __shared__ float sC[NC][64];
    int t = threadIdx.x;
    int cr = t & 63, rr = t >> 6;
    int r0 = blockIdx.y * 256, c0 = blockIdx.x * 64;
    for (int i = t; i < NT*64; i += 256) ((float*)sT)[i] = 0.f;
    for (int i = t; i < NC*64; i += 256) ((float*)sC)[i] = 0.f;
    __syncthreads();
    for (int r = r0 + rr; r < r0 + 256; r += 4) {
        int tt = to[r], cc = lb[r];
        float v = g_xm[r*DD + c0 + cr];
        atomicAdd(&sT[tt][cr], v);
        atomicAdd(&sC[cc][cr], v);
    }
    __syncthreads();
    for (int i = t; i < NT*64; i += 256)
        atomicAdd(&g_tsum[(i>>6)*DD + c0 + (i&63)], ((float*)sT)[i]);
    for (int i = t; i < NC*64; i += 256)
        atomicAdd(&g_csum[(i>>6)*DD + c0 + (i&63)], ((float*)sC)[i]);
}
__global__ void k_t1c1(const float* __restrict__ trep, const float* __restrict__ cpro) {
    int i = blockIdx.x*256 + threadIdx.x;
    if (i >= TC*DD) return;
    int seg = i / DD, d = i % DD;
    float v;
    if (seg < NT) {
        float cnt = fmaxf((float)g_cntT[seg], 1.f);
        v = 0.9f*trep[i] + 0.1f*g_tsum[i]/cnt;
    } else {
        int c = seg - NT;
        float cnt = fmaxf((float)g_cntC[c], 1.f);
        v = 0.9f*cpro[c*DD+d] + 0.1f*g_csum[c*DD+d]/cnt;
    }
    g_hA[i] = v;
}

// ---------------- graph kernels (unchanged) ----------------
__global__ void k_d2cross() {
    int c = blockIdx.x;
    int w = threadIdx.x >> 5, lane = threadIdx.x & 31;
    __shared__ float sd2[NT];
    const float* t1 = g_hA;
    const float* c1 = g_hA + NT*DD;
    float s = 0.f;
    for (int d = lane; d < DD; d += 32) {
        float df = t1[w*DD+d] - c1[c*DD+d];
        s += df*df;
    }
    #pragma unroll
    for (int o = 16; o; o >>= 1) s += __shfl_xor_sync(0xffffffffu, s, o);
    if (lane == 0) sd2[w] = s;
    __syncthreads();
    if (threadIdx.x == 0) {
        float l[NT], mx = -1e30f;
        for (int t = 0; t < NT; t++) { l[t] = -sd2[t]*(1.f/16.f); mx = fmaxf(mx, l[t]); }
        float Z = 0.f;
        for (int t = 0; t < NT; t++) { l[t] = expf(l[t]-mx); Z += l[t]; }
        for (int t = 0; t < NT; t++) {
            float p = l[t]/Z;
            g_cross[t*NC + c] = p;
            g_adj[t*TC + NT + c] = p;
            g_adj[(NT+c)*TC + t] = p;
        }
    }
}
__global__ void k_tg(const float* __restrict__ tw, const float* __restrict__ tb) {
    int i = blockIdx.x >> 2, j = blockIdx.x & 3;
    int lane = threadIdx.x;
    const float* t1 = g_hA;
    float s = 0.f;
    for (int d = lane; d < DD; d += 32)
        s += fabsf(t1[i*DD+d]-t1[j*DD+d]) * tw[d];
    #pragma unroll
    for (int o = 16; o; o >>= 1) s += __shfl_xor_sync(0xffffffffu, s, o);
    if (lane == 0) {
        float v = 1.f/(1.f+expf(-(s + tb[0])));
        if (i == j) v = 0.f;
        g_adj[i*TC+j] = v;
    }
}
__global__ void k_cg(const float* __restrict__ cw, const float* __restrict__ cb) {
    int i = blockIdx.x, j = blockIdx.y;
    int lane = threadIdx.x;
    const float* c1 = g_hA + NT*DD;
    float s = 0.f;
    for (int d = lane; d < DD; d += 32)
        s += fabsf(c1[i*DD+d]-c1[j*DD+d]) * cw[d];
    #pragma unroll
    for (int o = 16; o; o >>= 1) s += __shfl_xor_sync(0xffffffffu, s, o);
    if (lane == 0) {
        float v = 1.f/(1.f+expf(-(s + cb[0])));
        if (i == j) v = 0.f;
        g_adj[(NT+i)*TC + NT+j] = v;
    }
}
__global__ void k_ae(float* out) {
    __shared__ float s[NC];
    int c = threadIdx.x;
    float a = 0.f;
    for (int t = 0; t < NT; t++) { float p = g_cross[t*NC+c]; a += p*logf(p); }
    s[c] = a;
    __syncthreads();
    if (c == 0) { float r = 0.f; for (int i = 0; i < NC; i++) r += s[i]; out[0] = r/(float)NC; }
}

// ---------------- transpose: dst[n][k] = (k<K ? src[k][n] : 0), dst N x Kpad
__global__ void k_tr(const float* src, int useHw, int dstSel, int K, int N, int Kpad) {
    if (useHw) src = g_hw;
    float* dst = selT(dstSel);
    __shared__ float s[32][33];
    int kb = blockIdx.x*32, nb = blockIdx.y*32;
    int tx = threadIdx.x, ty = threadIdx.y;   // 32, 8
    #pragma unroll
    for (int r = 0; r < 32; r += 8) {
        int k = kb + ty + r, n = nb + tx;
        s[ty+r][tx] = (k < K && n < N) ? src[(size_t)k*N + n] : 0.f;
    }
    __syncthreads();
    #pragma unroll
    for (int r = 0; r < 32; r += 8) {
        int n = nb + ty + r, k = kb + tx;
        if (n < N && k < Kpad) dst[(size_t)n*Kpad + k] = s[tx][ty+r];
    }
}

// ---------------- tf32 tensor-core GEMM: C = A @ Bt^T ----------------
// A: M x K (lda), Bt: N x K (ldb), C: M x N (ldc). Block tile 128x64, 8 warps
// (warp = 16 rows x 64 cols). K staged in 32-chunks, smem rows padded to 36
// (conflict-free fragment loads: bank = 4*group + tid).
__global__ void k_gemm_tc(int aSel, int bSel, int cSel, int M, int N, int K,
                          int lda, int ldb, int ldc,
                          const float* bias, int relu) {
    const float* A = selA(aSel);
    const float* B = selA(bSel);
    float* C = selC(cSel);
    __shared__ float As[128][36];
    __shared__ float Bs[64][36];
    int tid = threadIdx.x;
    int w = tid >> 5, lane = tid & 31, g = lane >> 2, t = lane & 3;
    int m0 = blockIdx.y*128, n0 = blockIdx.x*64;
    float acc[8][4] = {};
    for (int k0 = 0; k0 < K; k0 += 32) {
        #pragma unroll
        for (int r = 0; r < 4; r++) {
            int idx = tid + 256*r;
            int row = idx >> 3, fc = idx & 7;
            int gm = m0 + row, gk = k0 + fc*4;
            float4 v = make_float4(0.f, 0.f, 0.f, 0.f);
            if (gm < M && gk + 3 < K) v = *(const float4*)&A[(size_t)gm*lda + gk];
            As[row][fc*4+0] = tf32r(v.x); As[row][fc*4+1] = tf32r(v.y);
            As[row][fc*4+2] = tf32r(v.z); As[row][fc*4+3] = tf32r(v.w);
        }
        #pragma unroll
        for (int r = 0; r < 2; r++) {
            int idx = tid + 256*r;
            int row = idx >> 3, fc = idx & 7;
            int gn = n0 + row, gk = k0 + fc*4;
            float4 v = make_float4(0.f, 0.f, 0.f, 0.f);
            if (gn < N && gk + 3 < K) v = *(const float4*)&B[(size_t)gn*ldb + gk];
            Bs[row][fc*4+0] = tf32r(v.x); Bs[row][fc*4+1] = tf32r(v.y);
            Bs[row][fc*4+2] = tf32r(v.z); Bs[row][fc*4+3] = tf32r(v.w);
        }
        __syncthreads();
        #pragma unroll
        for (int kk = 0; kk < 32; kk += 8) {
            uint32_t a0 = fb(As[w*16+g  ][kk+t]);
            uint32_t a1 = fb(As[w*16+g+8][kk+t]);
            uint32_t a2 = fb(As[w*16+g  ][kk+t+4]);
            uint32_t a3 = fb(As[w*16+g+8][kk+t+4]);
            #pragma unroll
            for (int nt = 0; nt < 8; nt++) {
                uint32_t b0 = fb(Bs[nt*8+g][kk+t]);
                uint32_t b1 = fb(Bs[nt*8+g][kk+t+4]);
                mma8(acc[nt], a0, a1, a2, a3, b0, b1);
            }
        }
        __syncthreads();
    }
    int r0 = m0 + w*16 + g, r1 = r0 + 8;
    #pragma unroll
    for (int nt = 0; nt < 8; nt++) {
        int n = n0 + nt*8 + 2*t;
        float bv0 = 0.f, bv1 = 0.f;
        if (bias) { if (n < N) bv0 = bias[n]; if (n+1 < N) bv1 = bias[n+1]; }
        float v00 = acc[nt][0] + bv0, v01 = acc[nt][1] + bv1;
        float v10 = acc[nt][2] + bv0, v11 = acc[nt][3] + bv1;
        if (relu) {
            v00 = fmaxf(v00, 0.f); v01 = fmaxf(v01, 0.f);
            v10 = fmaxf(v10, 0.f); v11 = fmaxf(v11, 0.f);
        }
        if (r0 < M) {
            if (n < N)   C[(size_t)r0*ldc + n]   = v00;
            if (n+1 < N) C[(size_t)r0*ldc + n+1] = v01;
        }
        if (r1 < M) {
            if (n < N)   C[(size_t)r1*ldc + n]   = v10;
            if (n+1 < N) C[(size_t)r1*ldc + n+1] = v11;
        }
    }
}

// ---------------- attention softmax stats (tf32 mma, streaming) ----------
// grid (32 row-blocks, 8 splits). Block 128 q-rows x 128 key-tile.
// Each warp owns 16 rows exclusively; online softmax stats in registers.
#define NJT 33
#define JPT 5
__global__ void k_attn_tc() {
    __shared__ float Qs[128][36];
    __shared__ float Ks[128][36];
    int tid = threadIdx.x;
    int w = tid >> 5, lane = tid & 31, g = lane >> 2, t = lane & 3;
    int i0 = blockIdx.x*128;
    int split = blockIdx.y;
    const float sc = 0.044194173824159216f;   // 1/sqrt(512)
    float m0r = -1e30f, m1r = -1e30f, z0r = 0.f, z1r = 0.f;
    int jt0 = split*JPT;
    int jt1 = jt0 + JPT; if (jt1 > NJT) jt1 = NJT;
    for (int jt = jt0; jt < jt1; jt++) {
        int j0 = jt*128;
        float acc[16][4] = {};
        for (int k0 = 0; k0 < DD; k0 += 32) {
            #pragma unroll
            for (int r = 0; r < 4; r++) {
                int idx = tid + 256*r;
                int row = idx >> 3, fc = idx & 7;
                float4 v = *(const float4*)&g_q[(size_t)(i0+row)*DD + k0 + fc*4];
                Qs[row][fc*4+0] = tf32r(v.x); Qs[row][fc*4+1] = tf32r(v.y);
                Qs[row][fc*4+2] = tf32r(v.z); Qs[row][fc*4+3] = tf32r(v.w);
            }
            #pragma unroll
            for (int r = 0; r < 4; r++) {
                int idx = tid + 256*r;
                int row = idx >> 3, fc = idx & 7;
                int gj = j0 + row;
                float4 v = make_float4(0.f, 0.f, 0.f, 0.f);
                if (gj < NS) v = *(const float4*)&g_kall[(size_t)gj*DD + k0 + fc*4];
                Ks[row][fc*4+0] = tf32r(v.x); Ks[row][fc*4+1] = tf32r(v.y);
                Ks[row][fc*4+2] = tf32r(v.z); Ks[row][fc*4+3] = tf32r(v.w);
            }
            __syncthreads();
            #pragma unroll
            for (int kk = 0; kk < 32; kk += 8) {
                uint32_t a0 = fb(Qs[w*16+g  ][kk+t]);
                uint32_t a1 = fb(Qs[w*16+g+8][kk+t]);
                uint32_t a2 = fb(Qs[w*16+g  ][kk+t+4]);
                uint32_t a3 = fb(Qs[w*16+g+8][kk+t+4]);
                #pragma unroll
                for (int nt = 0; nt < 16; nt++) {
                    uint32_t b0 = fb(Ks[nt*8+g][kk+t]);
                    uint32_t b1 = fb(Ks[nt*8+g][kk+t+4]);
                    mma8(acc[nt], a0, a1, a2, a3, b0, b1);
                }
            }
            __syncthreads();
        }
        // epilogue: scale, mask, row max + exp-sum (quad-wide rows)
        float lm0 = -1e30f, lm1 = -1e30f;
        #pragma unroll
        for (int nt = 0; nt < 16; nt++) {
            int base = j0 + nt*8 + 2*t;
            float v0 = (base   < NS) ? acc[nt][0]*sc : -1e30f;
            float v1 = (base+1 < NS) ? acc[nt][1]*sc : -1e30f;
            float v2 = (base   < NS) ? acc[nt][2]*sc : -1e30f;
            float v3 = (base+1 < NS) ? acc[nt][3]*sc : -1e30f;
            acc[nt][0] = v0; acc[nt][1] = v1; acc[nt][2] = v2; acc[nt][3] = v3;
            lm0 = fmaxf(lm0, fmaxf(v0, v1));
            lm1 = fmaxf(lm1, fmaxf(v2, v3));
        }
        lm0 = fmaxf(lm0, __shfl_xor_sync(0xffffffffu, lm0, 1));
        lm0 = fmaxf(lm0, __shfl_xor_sync(0xffffffffu, lm0, 2));
        lm1 = fmaxf(lm1, __shfl_xor_sync(0xffffffffu, lm1, 1));
        lm1 = fmaxf(lm1, __shfl_xor_sync(0xffffffffu, lm1, 2));
        float nm0 = fmaxf(m0r, lm0), nm1 = fmaxf(m1r, lm1);
        float p0 = 0.f, p1 = 0.f;
        #pragma unroll
        for (int nt = 0; nt < 16; nt++) {
            p0 += __expf(acc[nt][0]-nm0) + __expf(acc[nt][1]-nm0);
            p1 += __expf(acc[nt][2]-nm1) + __expf(acc[nt][3]-nm1);
        }
        p0 += __shfl_xor_sync(0xffffffffu, p0, 1);
        p0 += __shfl_xor_sync(0xffffffffu, p0, 2);
        p1 += __shfl_xor_sync(0xffffffffu, p1, 1);
        p1 += __shfl_xor_sync(0xffffffffu, p1, 2);
        z0r = z0r*__expf(m0r - nm0) + p0; m0r = nm0;
        z1r = z1r*__expf(m1r - nm1) + p1; m1r = nm1;
    }
    if (t == 0) {
        int r0 = i0 + w*16 + g;
        g_mp[split*BN + r0]     = m0r;  g_zp[split*BN + r0]     = z0r;
        g_mp[split*BN + r0 + 8] = m1r;  g_zp[split*BN + r0 + 8] = z1r;
    }
}

// ---------------- combine splits + first-69 softmax -> cf (padded) --------
__global__ void k_cf() {
    int i = blockIdx.x;
    int j = threadIdx.x;          // 96 threads
    __shared__ float sh[2];
    if (j == 0) {
        float m = -1e30f;
        #pragma unroll
        for (int s = 0; s < 8; s++) m = fmaxf(m, g_mp[s*BN + i]);
        float z = 0.f;
        #pragma unroll
        for (int s = 0; s < 8; s++) z += g_zp[s*BN + i]*__expf(g_mp[s*BN + i] - m);
        sh[0] = m; sh[1] = 1.f/z;
    }
    __syncthreads();
    const float sc = 0.044194173824159216f;
    if (j < CFLD)
        g_cf[i*CFLD + j] = (j < TC) ? __expf(g_l69[i*TC + j]*sc - sh[0]) * sh[1] : 0.f;
}

// ---------------- GNN tc-rows partial: C69 += cf^T @ hw_x ----------------
__global__ void k_outtc() {
    __shared__ float cfs[64][72];
    __shared__ float hws[64][64];
    int t = threadIdx.x, tx = t & 63, ty = t >> 6;
    int n0 = blockIdx.x*64;
    int b0 = blockIdx.y*256;
    float acc[18];
    #pragma unroll
    for (int k = 0; k < 18; k++) acc[k] = 0.f;
    for (int bc = 0; bc < 256; bc += 64) {
        int bb = b0 + bc;
        for (int i = t; i < 64*TC; i += 256) {
            int r = i/TC, k = i%TC;
            cfs[r][k] = g_cf[(size_t)(bb+r)*CFLD + k];
        }
        for (int i = t; i < 64*64; i += 256) {
            int r = i >> 6, n = i & 63;
            hws[r][n] = g_hw[(size_t)(TC+bb+r)*DD + n0 + n];
        }
        __syncthreads();
        for (int r = 0; r < 64; r++) {
            float hv = hws[r][tx];
            #pragma unroll
            for (int k = 0; k < 18; k++) {
                int m = ty + 4*k;
                if (m < TC) acc[k] += cfs[r][m]*hv;
            }
        }
        __syncthreads();
    }
    #pragma unroll
    for (int k = 0; k < 18; k++) {
        int m = ty + 4*k;
        if (m < TC) atomicAdd(&g_C69[m*DD + n0 + tx], acc[k]);
    }
}

// ---------------- finalize tc rows ----------------
__global__ void k_fintc(int dst, const float* __restrict__ gb) {
    float* H = (dst == 0) ? g_hB : g_hA;
    int m = blockIdx.x;      // 69
    int n = threadIdx.x;     // 512
    float v = g_C69[m*DD + n];
    for (int j = 0; j < TC; j++)
        v += g_adj[m*TC+j] * g_hw[j*DD + n];
    v += gb[n];
    H[m*DD + n] = fmaxf(v, 0.f);
}

// ---------------- y scale + labels ----------------
__global__ void k_yscale(const float* __restrict__ tcw, const int* __restrict__ to,
                         float* out, int y_off) {
    int i = blockIdx.x*256 + threadIdx.x;
    if (i < BN*NC) {
        int b = i/NC, c = i - b*NC;
        out[y_off + i] = tcw[to[b]*NC + c] * g_yraw[i];
    }
}
__global__ void k_labels(const int* __restrict__ lb, float* out, int off, int out_size) {
    int i = blockIdx.x*256 + threadIdx.x;
    if (i < BN && off + i < out_size) out[off + i] = (float)lb[i];
}

// ======================== host ========================
extern "C" void kernel_launch(void* const* d_in, const int* in_sizes, int n_in,
                              void* d_out, int out_size) {
    const float* x    = (const float*)d_in[0];
    const int*   lb   = (const int*)d_in[1];
    const int*   to   = (const int*)d_in[2];
    const float* trep = (const float*)d_in[3];
    const float* cpro = (const float*)d_in[4];
    const float* tw   = (const float*)d_in[5];
    const float* tb   = (const float*)d_in[6];
    const float* cw   = (const float*)d_in[7];
    const float* cb   = (const float*)d_in[8];
    const float* wq   = (const float*)d_in[9];
    const float* wk   = (const float*)d_in[10];
    const float* gw   = (const float*)d_in[11];
    const float* gb   = (const float*)d_in[12];
    const float* bw   = (const float*)d_in[13];
    const float* bb   = (const float*)d_in[14];
    const float* tcw  = (const float*)d_in[15];
    float* out = (float*)d_out;

    int y_off = (out_size > BN*NC) ? 1 : 0;
    int lbl_off = y_off + BN*NC;

    dim3 trb(32, 8);

    // weight transposes (independent of data)
    k_tr<<<dim3(16,16), trb>>>(wq, 0, 0, DD, DD, DD);
    k_tr<<<dim3(16,16), trb>>>(wk, 0, 1, DD, DD, DD);
    k_tr<<<dim3(16,16), trb>>>(gw, 0, 2, DD, DD, DD);
    k_tr<<<dim3(16,16), trb>>>(gw + DD*DD, 0, 3, DD, DD, DD);
    k_tr<<<dim3(16,3),  trb>>>(bw, 0, 4, DD, NC, DD);

    // 1. xm + src x-rows
    k_xm<<<16384, 128>>>(x);
    // 2. segment means -> t1/c1
    k_zero_seg<<<(NC*DD + 255)/256, 256>>>();
    k_count<<<16, 256>>>(to, lb);
    k_segsum<<<dim3(8, 16), 256>>>(to, lb);
    k_t1c1<<<(TC*DD + 255)/256, 256>>>(trep, cpro);
    // 3. graphs
    k_d2cross<<<65, 128>>>();
    k_tg<<<16, 32>>>(tw, tb);
    k_cg<<<dim3(65, 65), 32>>>(cw, cb);
    if (y_off) k_ae<<<1, 65>>>(out);
    // 4. projections (tensor core): q = xm@wq, k = src@wk
    k_gemm_tc<<<dim3(8, 32), 256>>>(0, 6, 3, BN, DD, DD, DD, DD, DD, nullptr, 0);
    k_gemm_tc<<<dim3(8, 33), 256>>>(1, 7, 4, NS, DD, DD, DD, DD, DD, nullptr, 0);
    // 5. attention stats + first-69 logits + cross_feat
    k_attn_tc<<<dim3(32, 8), 256>>>();
    k_gemm_tc<<<dim3(2, 32), 256>>>(3, 4, 13, BN, TC, DD, DD, DD, TC, nullptr, 0);
    k_cf<<<4096, 96>>>();
    // 6. GNN layer 0: hA -> hB
    k_gemm_tc<<<dim3(8, 33), 256>>>(1, 8, 5, NS, DD, DD, DD, DD, DD, nullptr, 0);
    k_tr<<<dim3(3, 16), trb>>>(nullptr, 1, 5, TC, DD, CFLD);
    k_gemm_tc<<<dim3(8, 32), 256>>>(12, 11, 15, BN, DD, CFLD, CFLD, CFLD, DD, gb, 1);
    k_zero_c69<<<(TC*DD + 255)/256, 256>>>();
    k_outtc<<<dim3(8, 16), 256>>>();
    k_fintc<<<69, 512>>>(0, gb);
    // 7. GNN layer 1: hB -> hA
    k_gemm_tc<<<dim3(8, 33), 256>>>(2, 9, 5, NS, DD, DD, DD, DD, DD, nullptr, 0);
    k_tr<<<dim3(3, 16), trb>>>(nullptr, 1, 5, TC, DD, CFLD);
    k_gemm_tc<<<dim3(8, 32), 256>>>(12, 11, 16, BN, DD, CFLD, CFLD, CFLD, DD, gb + DD, 1);
    k_zero_c69<<<(TC*DD + 255)/256, 256>>>();
    k_outtc<<<dim3(8, 16), 256>>>();
    k_fintc<<<69, 512>>>(1, gb + DD);
    // 8. outputs: y = h_x @ bw + bb, task scale, labels
    k_gemm_tc<<<dim3(2, 32), 256>>>(17, 10, 14, BN, NC, DD, DD, DD, NC, bb, 0);
    k_yscale<<<(BN*NC + 255)/256, 256>>>(tcw, to, out, y_off);
    k_labels<<<16, 256>>>(lb, out, lbl_off, out_size);
}

// round 5
// speedup vs baseline: 3.2372x; 1.0378x over previous
#include <cuda_runtime.h>
#include <math.h>
#include <stdint.h>

#define BN 4096
#define DD 512
#define NT 4
#define NC 65
#define TC 69          // NT + NC
#define NS 4165        // TC + BN
#define CFLD 72        // padded cf row stride

// ---------------- scratch (device globals; no allocations) ----------------
__device__ float g_xm[BN*DD];
__device__ float g_q[BN*DD];
__device__ float g_kall[NS*DD];
__device__ float g_hA[NS*DD];
__device__ float g_hB[NS*DD];
__device__ float g_hw[NS*DD];
__device__ float g_tsum[NT*DD];
__device__ float g_csum[NC*DD];
__device__ int   g_cntT[NT];
__device__ int   g_cntC[NC];
__device__ float g_adj[TC*TC];
__device__ float g_cross[NT*NC];
__device__ float g_cf[BN*CFLD];
__device__ float g_l69[BN*TC];
__device__ float g_mp[8*BN];
__device__ float g_zp[8*BN];
__device__ float g_C69[TC*DD];

// ---------------- tf32 helpers ----------------
__device__ __forceinline__ float tf32r(float x) {
    uint32_t u;
    asm("cvt.rna.tf32.f32 %0, %1;" : "=r"(u) : "f"(x));
    return __uint_as_float(u);
}
__device__ __forceinline__ void mma8(float* c, uint32_t a0, uint32_t a1,
                                     uint32_t a2, uint32_t a3,
                                     uint32_t b0, uint32_t b1) {
    asm("mma.sync.aligned.m16n8k8.row.col.f32.tf32.tf32.f32 "
        "{%0,%1,%2,%3},{%4,%5,%6,%7},{%8,%9},{%0,%1,%2,%3};"
        : "+f"(c[0]), "+f"(c[1]), "+f"(c[2]), "+f"(c[3])
        : "r"(a0), "r"(a1), "r"(a2), "r"(a3), "r"(b0), "r"(b1));
}
__device__ __forceinline__ uint32_t fb(float x) { return __float_as_uint(x); }

// ---------------- selectors ----------------
__device__ __forceinline__ const float* selA3(int s) {
    switch (s) {
        case 0: return g_xm;  case 1: return g_hA;  case 2: return g_hB;
        case 3: return g_cf;  case 4: return g_hA + TC*DD;
    }
    return g_xm;
}
__device__ __forceinline__ float* selC3(int s) {
    switch (s) {
        case 0: return g_q;  case 1: return g_kall;  case 2: return g_hw;
        case 3: return g_hB + TC*DD;  case 4: return g_hA + TC*DD;
    }
    return g_q;
}

// ---------------- xm = mean over 7x7; also write src rows 69.. -------------
__global__ void k_xm(const float* __restrict__ x) {
    __shared__ float buf[4][32*49];
    int w = threadIdx.x >> 5, lane = threadIdx.x & 31;
    int base = (blockIdx.x*4 + w) * 32;
    const float* src = x + (size_t)base*49;
    float* b = buf[w];
    #pragma unroll
    for (int t = 0; t < 49; t++) b[lane + 32*t] = src[lane + 32*t];
    __syncwarp();
    float s = 0.f;
    #pragma unroll
    for (int t = 0; t < 49; t++) s += b[lane*49 + t];
    s *= (1.f/49.f);
    int seg = base + lane;
    g_xm[seg] = s;
    g_hA[TC*DD + seg] = s;
}

// ---------------- zero / counts / segsum / t1c1 ----------------
__global__ void k_zero_seg() {
    int i = blockIdx.x*256 + threadIdx.x;
    if (i < NT*DD) g_tsum[i] = 0.f;
    if (i < NC*DD) g_csum[i] = 0.f;
    if (i < NT) g_cntT[i] = 0;
    if (i < NC) g_cntC[i] = 0;
}
__global__ void k_zero_c69() {
    int i = blockIdx.x*256 + threadIdx.x;
    if (i < TC*DD) g_C69[i] = 0.f;
}
__global__ void k_count(const int* __restrict__ to, const int* __restrict__ lb) {
    int i = blockIdx.x*256 + threadIdx.x;
    if (i < BN) { atomicAdd(&g_cntT[to[i]], 1); atomicAdd(&g_cntC[lb[i]], 1); }
}
__global__ void k_segsum(const int* __restrict__ to, const int* __restrict__ lb) {
    __shared__ float sT[NT][64];
    __shared__ float sC[NC][64];
    int t = threadIdx.x;
    int cr = t & 63, rr = t >> 6;
    int r0 = blockIdx.y * 64, c0 = blockIdx.x * 64;
    for (int i = t; i < NT*64; i += 256) ((float*)sT)[i] = 0.f;
    for (int i = t; i < NC*64; i += 256) ((float*)sC)[i] = 0.f;
    __syncthreads();
    for (int r = r0 + rr; r < r0 + 64; r += 4) {
        int tt = to[r], cc = lb[r];
        float v = g_xm[r*DD + c0 + cr];
        atomicAdd(&sT[tt][cr], v);
        atomicAdd(&sC[cc][cr], v);
    }
    __syncthreads();
    for (int i = t; i < NT*64; i += 256)
        atomicAdd(&g_tsum[(i>>6)*DD + c0 + (i&63)], ((float*)sT)[i]);
    for (int i = t; i < NC*64; i += 256)
        atomicAdd(&g_csum[(i>>6)*DD + c0 + (i&63)], ((float*)sC)[i]);
}
__global__ void k_t1c1(const float* __restrict__ trep, const float* __restrict__ cpro) {
    int i = blockIdx.x*256 + threadIdx.x;
    if (i >= TC*DD) return;
    int seg = i / DD, d = i % DD;
    float v;
    if (seg < NT) {
        float cnt = fmaxf((float)g_cntT[seg], 1.f);
        v = 0.9f*trep[i] + 0.1f*g_tsum[i]/cnt;
    } else {
        int c = seg - NT;
        float cnt = fmaxf((float)g_cntC[c], 1.f);
        v = 0.9f*cpro[c*DD+d] + 0.1f*g_csum[c*DD+d]/cnt;
    }
    g_hA[i] = v;
}

// ---------------- graph kernels ----------------
__global__ void k_d2cross() {
    int c = blockIdx.x;
    int w = threadIdx.x >> 5, lane = threadIdx.x & 31;
    __shared__ float sd2[NT];
    const float* t1 = g_hA;
    const float* c1 = g_hA + NT*DD;
    float s = 0.f;
    for (int d = lane; d < DD; d += 32) {
        float df = t1[w*DD+d] - c1[c*DD+d];
        s += df*df;
    }
    #pragma unroll
    for (int o = 16; o; o >>= 1) s += __shfl_xor_sync(0xffffffffu, s, o);
    if (lane == 0) sd2[w] = s;
    __syncthreads();
    if (threadIdx.x == 0) {
        float l[NT], mx = -1e30f;
        for (int t = 0; t < NT; t++) { l[t] = -sd2[t]*(1.f/16.f); mx = fmaxf(mx, l[t]); }
        float Z = 0.f;
        for (int t = 0; t < NT; t++) { l[t] = expf(l[t]-mx); Z += l[t]; }
        for (int t = 0; t < NT; t++) {
            float p = l[t]/Z;
            g_cross[t*NC + c] = p;
            g_adj[t*TC + NT + c] = p;
            g_adj[(NT+c)*TC + t] = p;
        }
    }
}
__global__ void k_tg(const float* __restrict__ tw, const float* __restrict__ tb) {
    int i = blockIdx.x >> 2, j = blockIdx.x & 3;
    int lane = threadIdx.x;
    const float* t1 = g_hA;
    float s = 0.f;
    for (int d = lane; d < DD; d += 32)
        s += fabsf(t1[i*DD+d]-t1[j*DD+d]) * tw[d];
    #pragma unroll
    for (int o = 16; o; o >>= 1) s += __shfl_xor_sync(0xffffffffu, s, o);
    if (lane == 0) {
        float v = 1.f/(1.f+expf(-(s + tb[0])));
        if (i == j) v = 0.f;
        g_adj[i*TC+j] = v;
    }
}
__global__ void k_cg(const float* __restrict__ cw, const float* __restrict__ cb) {
    int i = blockIdx.x, j = blockIdx.y;
    int lane = threadIdx.x;
    const float* c1 = g_hA + NT*DD;
    float s = 0.f;
    for (int d = lane; d < DD; d += 32)
        s += fabsf(c1[i*DD+d]-c1[j*DD+d]) * cw[d];
    #pragma unroll
    for (int o = 16; o; o >>= 1) s += __shfl_xor_sync(0xffffffffu, s, o);
    if (lane == 0) {
        float v = 1.f/(1.f+expf(-(s + cb[0])));
        if (i == j) v = 0.f;
        g_adj[(NT+i)*TC + NT+j] = v;
    }
}
__global__ void k_ae(float* out) {
    __shared__ float s[NC];
    int c = threadIdx.x;
    float a = 0.f;
    for (int t = 0; t < NT; t++) { float p = g_cross[t*NC+c]; a += p*logf(p); }
    s[c] = a;
    __syncthreads();
    if (c == 0) { float r = 0.f; for (int i = 0; i < NC; i++) r += s[i]; out[0] = r/(float)NC; }
}

// ---------------- tf32 GEMM: C = A(MxK,row) @ B(KxN,row) -------------------
// Block 128x128, 8 warps (4m x 2n), warp tile 32x64. 1.5 LDS per mma.
// Bp==nullptr -> B = g_hw. yout!=nullptr -> y-mode (tcw scaling, ldc=NC).
// B float4 path requires (ldb & 3) == 0; otherwise scalar fallback.
__global__ void k_gemm3(int aSel, const float* __restrict__ Bp, int cSel,
                        int M, int N, int K, int lda, int ldb, int ldc,
                        const float* __restrict__ bias, int relu,
                        const float* __restrict__ tcw, const int* __restrict__ to,
                        float* yout) {
    const float* A = selA3(aSel);
    const float* B = Bp ? Bp : g_hw;
    float* C = yout ? yout : selC3(cSel);
    __shared__ float As[128][36];
    __shared__ float Bs[32][136];
    int tid = threadIdx.x;
    int w = tid >> 5, lane = tid & 31, g = lane >> 2, t = lane & 3;
    int wm = (w & 3) * 32, wn = (w >> 2) * 64;
    int m0 = blockIdx.y*128, n0 = blockIdx.x*128;
    int bAligned = ((ldb & 3) == 0);
    float acc[2][8][4] = {};
    for (int k0 = 0; k0 < K; k0 += 32) {
        #pragma unroll
        for (int r = 0; r < 4; r++) {
            int idx = tid + 256*r;
            int row = idx >> 3, fc = idx & 7;
            int gm = m0 + row, gk = k0 + fc*4;
            float4 v = make_float4(0.f, 0.f, 0.f, 0.f);
            if (gm < M && gk + 3 < K) v = *(const float4*)&A[(size_t)gm*lda + gk];
            As[row][fc*4+0] = tf32r(v.x); As[row][fc*4+1] = tf32r(v.y);
            As[row][fc*4+2] = tf32r(v.z); As[row][fc*4+3] = tf32r(v.w);
        }
        #pragma unroll
        for (int r = 0; r < 4; r++) {
            int idx = tid + 256*r;
            int row = idx >> 5, c4 = (idx & 31) * 4;
            int gk = k0 + row, gn = n0 + c4;
            float4 v = make_float4(0.f, 0.f, 0.f, 0.f);
            if (gk < K) {
                if (bAligned && gn + 3 < N) {
                    v = *(const float4*)&B[(size_t)gk*ldb + gn];
                } else {
                    const float* brow = &B[(size_t)gk*ldb];
                    if (gn   < N) v.x = brow[gn];
                    if (gn+1 < N) v.y = brow[gn+1];
                    if (gn+2 < N) v.z = brow[gn+2];
                    if (gn+3 < N) v.w = brow[gn+3];
                }
            }
            Bs[row][c4+0] = tf32r(v.x); Bs[row][c4+1] = tf32r(v.y);
            Bs[row][c4+2] = tf32r(v.z); Bs[row][c4+3] = tf32r(v.w);
        }
        __syncthreads();
        #pragma unroll
        for (int kk = 0; kk < 32; kk += 8) {
            uint32_t a[2][4];
            #pragma unroll
            for (int mi = 0; mi < 2; mi++) {
                a[mi][0] = fb(As[wm+mi*16+g  ][kk+t]);
                a[mi][1] = fb(As[wm+mi*16+g+8][kk+t]);
                a[mi][2] = fb(As[wm+mi*16+g  ][kk+t+4]);
                a[mi][3] = fb(As[wm+mi*16+g+8][kk+t+4]);
            }
            uint32_t b[8][2];
            #pragma unroll
            for (int ni = 0; ni < 8; ni++) {
                b[ni][0] = fb(Bs[kk+t  ][wn+ni*8+g]);
                b[ni][1] = fb(Bs[kk+t+4][wn+ni*8+g]);
            }
            #pragma unroll
            for (int mi = 0; mi < 2; mi++)
                #pragma unroll
                for (int ni = 0; ni < 8; ni++)
                    mma8(acc[mi][ni], a[mi][0], a[mi][1], a[mi][2], a[mi][3],
                         b[ni][0], b[ni][1]);
        }
        __syncthreads();
    }
    #pragma unroll
    for (int mi = 0; mi < 2; mi++) {
        int r0 = m0 + wm + mi*16 + g, r1 = r0 + 8;
        #pragma unroll
        for (int ni = 0; ni < 8; ni++) {
            int n = n0 + wn + ni*8 + 2*t;
            float bv0 = 0.f, bv1 = 0.f;
            if (bias) { if (n < N) bv0 = bias[n]; if (n+1 < N) bv1 = bias[n+1]; }
            float v00 = acc[mi][ni][0] + bv0, v01 = acc[mi][ni][1] + bv1;
            float v10 = acc[mi][ni][2] + bv0, v11 = acc[mi][ni][3] + bv1;
            if (relu) {
                v00 = fmaxf(v00, 0.f); v01 = fmaxf(v01, 0.f);
                v10 = fmaxf(v10, 0.f); v11 = fmaxf(v11, 0.f);
            }
            if (yout) {
                if (r0 < M) {
                    if (n < N)   C[(size_t)r0*ldc + n]   = tcw[to[r0]*NC + n]   * v00;
                    if (n+1 < N) C[(size_t)r0*ldc + n+1] = tcw[to[r0]*NC + n+1] * v01;
                }
                if (r1 < M) {
                    if (n < N)   C[(size_t)r1*ldc + n]   = tcw[to[r1]*NC + n]   * v10;
                    if (n+1 < N) C[(size_t)r1*ldc + n+1] = tcw[to[r1]*NC + n+1] * v11;
                }
            } else {
                if (r0 < M) {
                    if (n < N)   C[(size_t)r0*ldc + n]   = v00;
                    if (n+1 < N) C[(size_t)r0*ldc + n+1] = v01;
                }
                if (r1 < M) {
                    if (n < N)   C[(size_t)r1*ldc + n]   = v10;
                    if (n+1 < N) C[(size_t)r1*ldc + n+1] = v11;
                }
            }
        }
    }
}

// ---------------- l69 = q @ kall^T (first TC cols, unscaled) -----
// Block 128 rows; warp = 16 rows x 72 cols (9 n-tiles covers TC=69).
__global__ void k_l69() {
    __shared__ float As[128][36];
    __shared__ float Bs[128][36];
    int tid = threadIdx.x;
    int w = tid >> 5, lane = tid & 31, g = lane >> 2, t = lane & 3;
    int m0 = blockIdx.x*128;
    float acc[9][4] = {};
    for (int k0 = 0; k0 < DD; k0 += 32) {
        #pragma unroll
        for (int r = 0; r < 4; r++) {
            int idx = tid + 256*r;
            int row = idx >> 3, fc = idx & 7;
            float4 v = *(const float4*)&g_q[(size_t)(m0+row)*DD + k0 + fc*4];
            As[row][fc*4+0] = tf32r(v.x); As[row][fc*4+1] = tf32r(v.y);
            As[row][fc*4+2] = tf32r(v.z); As[row][fc*4+3] = tf32r(v.w);
        }
        #pragma unroll
        for (int r = 0; r < 4; r++) {
            int idx = tid + 256*r;
            int row = idx >> 3, fc = idx & 7;
            float4 v = make_float4(0.f, 0.f, 0.f, 0.f);
            if (row < TC) v = *(const float4*)&g_kall[(size_t)row*DD + k0 + fc*4];
            Bs[row][fc*4+0] = tf32r(v.x); Bs[row][fc*4+1] = tf32r(v.y);
            Bs[row][fc*4+2] = tf32r(v.z); Bs[row][fc*4+3] = tf32r(v.w);
        }
        __syncthreads();
        #pragma unroll
        for (int kk = 0; kk < 32; kk += 8) {
            uint32_t a0 = fb(As[w*16+g  ][kk+t]);
            uint32_t a1 = fb(As[w*16+g+8][kk+t]);
            uint32_t a2 = fb(As[w*16+g  ][kk+t+4]);
            uint32_t a3 = fb(As[w*16+g+8][kk+t+4]);
            #pragma unroll
            for (int nt = 0; nt < 9; nt++) {
                uint32_t b0 = fb(Bs[nt*8+g][kk+t]);
                uint32_t b1 = fb(Bs[nt*8+g][kk+t+4]);
                mma8(acc[nt], a0, a1, a2, a3, b0, b1);
            }
        }
        __syncthreads();
    }
    int r0 = m0 + w*16 + g, r1 = r0 + 8;
    #pragma unroll
    for (int nt = 0; nt < 9; nt++) {
        int n = nt*8 + 2*t;
        if (n < TC)   { g_l69[(size_t)r0*TC + n]   = acc[nt][0];
                        g_l69[(size_t)r1*TC + n]   = acc[nt][2]; }
        if (n+1 < TC) { g_l69[(size_t)r0*TC + n+1] = acc[nt][1];
                        g_l69[(size_t)r1*TC + n+1] = acc[nt][3]; }
    }
}

// ---------------- attention softmax stats (tf32 mma, streaming) ----------
// grid (32 row-blocks, 7 splits). Block 128 q x 128 keys, warp tile 32x64.
// Rows are covered by TWO warps (column halves); partial (m,z) merged via smem.
#define NJT 33
#define JPT 5
__global__ void k_attn3() {
    __shared__ float Qs[128][36];
    __shared__ float Ks[128][36];
    __shared__ float sm_m[2][128];
    __shared__ float sm_z[2][128];
    int tid = threadIdx.x;
    int w = tid >> 5, lane = tid & 31, g = lane >> 2, t = lane & 3;
    int wm = (w & 3) * 32, wn = (w >> 2) * 64;
    int half = w >> 2;
    int i0 = blockIdx.x*128;
    int split = blockIdx.y;
    const float sc = 0.044194173824159216f;   // 1/sqrt(512)
    float mr[2][2] = {{-1e30f,-1e30f},{-1e30f,-1e30f}};
    float zr[2][2] = {{0.f,0.f},{0.f,0.f}};
    int jt0 = split*JPT;
    int jt1 = jt0 + JPT; if (jt1 > NJT) jt1 = NJT;
    for (int jt = jt0; jt < jt1; jt++) {
        int j0 = jt*128;
        float acc[2][8][4] = {};
        for (int k0 = 0; k0 < DD; k0 += 32) {
            #pragma unroll
            for (int r = 0; r < 4; r++) {
                int idx = tid + 256*r;
                int row = idx >> 3, fc = idx & 7;
                float4 v = *(const float4*)&g_q[(size_t)(i0+row)*DD + k0 + fc*4];
                Qs[row][fc*4+0] = tf32r(v.x); Qs[row][fc*4+1] = tf32r(v.y);
                Qs[row][fc*4+2] = tf32r(v.z); Qs[row][fc*4+3] = tf32r(v.w);
            }
            #pragma unroll
            for (int r = 0; r < 4; r++) {
                int idx = tid + 256*r;
                int row = idx >> 3, fc = idx & 7;
                int gj = j0 + row;
                float4 v = make_float4(0.f, 0.f, 0.f, 0.f);
                if (gj < NS) v = *(const float4*)&g_kall[(size_t)gj*DD + k0 + fc*4];
                Ks[row][fc*4+0] = tf32r(v.x); Ks[row][fc*4+1] = tf32r(v.y);
                Ks[row][fc*4+2] = tf32r(v.z); Ks[row][fc*4+3] = tf32r(v.w);
            }
            __syncthreads();
            #pragma unroll
            for (int kk = 0; kk < 32; kk += 8) {
                uint32_t a[2][4];
                #pragma unroll
                for (int mi = 0; mi < 2; mi++) {
                    a[mi][0] = fb(Qs[wm+mi*16+g  ][kk+t]);
                    a[mi][1] = fb(Qs[wm+mi*16+g+8][kk+t]);
                    a[mi][2] = fb(Qs[wm+mi*16+g  ][kk+t+4]);
                    a[mi][3] = fb(Qs[wm+mi*16+g+8][kk+t+4]);
                }
                uint32_t b[8][2];
                #pragma unroll
                for (int ni = 0; ni < 8; ni++) {
                    b[ni][0] = fb(Ks[wn+ni*8+g][kk+t]);
                    b[ni][1] = fb(Ks[wn+ni*8+g][kk+t+4]);
                }
                #pragma unroll
                for (int mi = 0; mi < 2; mi++)
                    #pragma unroll
                    for (int ni = 0; ni < 8; ni++)
                        mma8(acc[mi][ni], a[mi][0], a[mi][1], a[mi][2], a[mi][3],
                             b[ni][0], b[ni][1]);
            }
            __syncthreads();
        }
        // scale, mask, online softmax update (rows r0=wm+mi*16+g, r1=+8)
        #pragma unroll
        for (int mi = 0; mi < 2; mi++) {
            float lm0 = -1e30f, lm1 = -1e30f;
            #pragma unroll
            for (int ni = 0; ni < 8; ni++) {
                int base = j0 + wn + ni*8 + 2*t;
                float v0 = (base   < NS) ? acc[mi][ni][0]*sc : -1e30f;
                float v1 = (base+1 < NS) ? acc[mi][ni][1]*sc : -1e30f;
                float v2 = (base   < NS) ? acc[mi][ni][2]*sc : -1e30f;
                float v3 = (base+1 < NS) ? acc[mi][ni][3]*sc : -1e30f;
                acc[mi][ni][0] = v0; acc[mi][ni][1] = v1;
                acc[mi][ni][2] = v2; acc[mi][ni][3] = v3;
                lm0 = fmaxf(lm0, fmaxf(v0, v1));
                lm1 = fmaxf(lm1, fmaxf(v2, v3));
            }
            lm0 = fmaxf(lm0, __shfl_xor_sync(0xffffffffu, lm0, 1));
            lm0 = fmaxf(lm0, __shfl_xor_sync(0xffffffffu, lm0, 2));
            lm1 = fmaxf(lm1, __shfl_xor_sync(0xffffffffu, lm1, 1));
            lm1 = fmaxf(lm1, __shfl_xor_sync(0xffffffffu, lm1, 2));
            float nm0 = fmaxf(mr[mi][0], lm0), nm1 = fmaxf(mr[mi][1], lm1);
            float p0 = 0.f, p1 = 0.f;
            #pragma unroll
            for (int ni = 0; ni < 8; ni++) {
                p0 += __expf(acc[mi][ni][0]-nm0) + __expf(acc[mi][ni][1]-nm0);
                p1 += __expf(acc[mi][ni][2]-nm1) + __expf(acc[mi][ni][3]-nm1);
            }
            p0 += __shfl_xor_sync(0xffffffffu, p0, 1);
            p0 += __shfl_xor_sync(0xffffffffu, p0, 2);
            p1 += __shfl_xor_sync(0xffffffffu, p1, 1);
            p1 += __shfl_xor_sync(0xffffffffu, p1, 2);
            zr[mi][0] = zr[mi][0]*__expf(mr[mi][0] - nm0) + p0; mr[mi][0] = nm0;
            zr[mi][1] = zr[mi][1]*__expf(mr[mi][1] - nm1) + p1; mr[mi][1] = nm1;
        }
    }
    // merge the two column-half partials per row, then write
    if (t == 0) {
        #pragma unroll
        for (int mi = 0; mi < 2; mi++) {
            int r = wm + mi*16 + g;
            sm_m[half][r]     = mr[mi][0];  sm_z[half][r]     = zr[mi][0];
            sm_m[half][r + 8] = mr[mi][1];  sm_z[half][r + 8] = zr[mi][1];
        }
    }
    __syncthreads();
    if (tid < 128) {
        float m0 = sm_m[0][tid], m1 = sm_m[1][tid];
        float m = fmaxf(m0, m1);
        float z = sm_z[0][tid]*__expf(m0 - m) + sm_z[1][tid]*__expf(m1 - m);
        g_mp[split*BN + i0 + tid] = m;
        g_zp[split*BN + i0 + tid] = z;
    }
}

// ---------------- combine splits + first-69 softmax -> cf (padded) --------
__global__ void k_cf() {
    int i = blockIdx.x;
    int j = threadIdx.x;          // 96 threads
    __shared__ float sh[2];
    if (j == 0) {
        float m = -1e30f;
        #pragma unroll
        for (int s = 0; s < 7; s++) m = fmaxf(m, g_mp[s*BN + i]);
        float z = 0.f;
        #pragma unroll
        for (int s = 0; s < 7; s++) z += g_zp[s*BN + i]*__expf(g_mp[s*BN + i] - m);
        sh[0] = m; sh[1] = 1.f/z;
    }
    __syncthreads();
    const float sc = 0.044194173824159216f;
    if (j < CFLD)
        g_cf[i*CFLD + j] = (j < TC) ? __expf(g_l69[i*TC + j]*sc - sh[0]) * sh[1] : 0.f;
}

// ---------------- GNN tc-rows partial: C69 += cf^T @ hw_x ----------------
__global__ void k_outtc() {
    __shared__ float cfs[64][72];
    __shared__ float hws[64][64];
    int t = threadIdx.x, tx = t & 63, ty = t >> 6;
    int n0 = blockIdx.x*64;
    int b0 = blockIdx.y*256;
    float acc[18];
    #pragma unroll
    for (int k = 0; k < 18; k++) acc[k] = 0.f;
    for (int bc = 0; bc < 256; bc += 64) {
        int bb = b0 + bc;
        for (int i = t; i < 64*TC; i += 256) {
            int r = i/TC, k = i%TC;
            cfs[r][k] = g_cf[(size_t)(bb+r)*CFLD + k];
        }
        for (int i = t; i < 64*64; i += 256) {
            int r = i >> 6, n = i & 63;
            hws[r][n] = g_hw[(size_t)(TC+bb+r)*DD + n0 + n];
        }
        __syncthreads();
        for (int r = 0; r < 64; r++) {
            float hv = hws[r][tx];
            #pragma unroll
            for (int k = 0; k < 18; k++) {
                int m = ty + 4*k;
                if (m < TC) acc[k] += cfs[r][m]*hv;
            }
        }
        __syncthreads();
    }
    #pragma unroll
    for (int k = 0; k < 18; k++) {
        int m = ty + 4*k;
        if (m < TC) atomicAdd(&g_C69[m*DD + n0 + tx], acc[k]);
    }
}

// ---------------- finalize tc rows ----------------
__global__ void k_fintc(int dst, const float* __restrict__ gb) {
    float* H = (dst == 0) ? g_hB : g_hA;
    int m = blockIdx.x;      // 69
    int n = threadIdx.x;     // 512
    float v = g_C69[m*DD + n];
    for (int j = 0; j < TC; j++)
        v += g_adj[m*TC+j] * g_hw[j*DD + n];
    v += gb[n];
    H[m*DD + n] = fmaxf(v, 0.f);
}

// ---------------- labels ----------------
__global__ void k_labels(const int* __restrict__ lb, float* out, int off, int out_size) {
    int i = blockIdx.x*256 + threadIdx.x;
    if (i < BN && off + i < out_size) out[off + i] = (float)lb[i];
}

// ======================== host ========================
extern "C" void kernel_launch(void* const* d_in, const int* in_sizes, int n_in,
                              void* d_out, int out_size) {
    const float* x    = (const float*)d_in[0];
    const int*   lb   = (const int*)d_in[1];
    const int*   to   = (const int*)d_in[2];
    const float* trep = (const float*)d_in[3];
    const float* cpro = (const float*)d_in[4];
    const float* tw   = (const float*)d_in[5];
    const float* tb   = (const float*)d_in[6];
    const float* cw   = (const float*)d_in[7];
    const float* cb   = (const float*)d_in[8];
    const float* wq   = (const float*)d_in[9];
    const float* wk   = (const float*)d_in[10];
    const float* gw   = (const float*)d_in[11];
    const float* gb   = (const float*)d_in[12];
    const float* bw   = (const float*)d_in[13];
    const float* bb   = (const float*)d_in[14];
    const float* tcw  = (const float*)d_in[15];
    float* out = (float*)d_out;

    int y_off = (out_size > BN*NC) ? 1 : 0;
    int lbl_off = y_off + BN*NC;

    // 1. xm + src x-rows
    k_xm<<<16384, 128>>>(x);
    // 2. segment means -> t1/c1
    k_zero_seg<<<(NC*DD + 255)/256, 256>>>();
    k_count<<<16, 256>>>(to, lb);
    k_segsum<<<dim3(8, 64), 256>>>(to, lb);
    k_t1c1<<<(TC*DD + 255)/256, 256>>>(trep, cpro);
    // 3. graphs
    k_d2cross<<<65, 128>>>();
    k_tg<<<16, 32>>>(tw, tb);
    k_cg<<<dim3(65, 65), 32>>>(cw, cb);
    if (y_off) k_ae<<<1, 65>>>(out);
    // 4. projections: q = xm@wq, kall = src@wk
    k_gemm3<<<dim3(4, 32), 256>>>(0, wq, 0, BN, DD, DD, DD, DD, DD, nullptr, 0, nullptr, nullptr, nullptr);
    k_gemm3<<<dim3(4, 33), 256>>>(1, wk, 1, NS, DD, DD, DD, DD, DD, nullptr, 0, nullptr, nullptr, nullptr);
    // 5. attention stats + first-69 logits + cross_feat
    k_attn3<<<dim3(32, 7), 256>>>();
    k_l69<<<32, 256>>>();
    k_cf<<<4096, 96>>>();
    // 6. GNN layer 0: hA -> hB
    k_gemm3<<<dim3(4, 33), 256>>>(1, gw, 2, NS, DD, DD, DD, DD, DD, nullptr, 0, nullptr, nullptr, nullptr);
    k_gemm3<<<dim3(4, 32), 256>>>(3, nullptr, 3, BN, DD, CFLD, CFLD, DD, DD, gb, 1, nullptr, nullptr, nullptr);
    k_zero_c69<<<(TC*DD + 255)/256, 256>>>();
    k_outtc<<<dim3(8, 16), 256>>>();
    k_fintc<<<69, 512>>>(0, gb);
    // 7. GNN layer 1: hB -> hA
    k_gemm3<<<dim3(4, 33), 256>>>(2, gw + DD*DD, 2, NS, DD, DD, DD, DD, DD, nullptr, 0, nullptr, nullptr, nullptr);
    k_gemm3<<<dim3(4, 32), 256>>>(3, nullptr, 4, BN, DD, CFLD, CFLD, DD, DD, gb + DD, 1, nullptr, nullptr, nullptr);
    k_zero_c69<<<(TC*DD + 255)/256, 256>>>();
    k_outtc<<<dim3(8, 16), 256>>>();
    k_fintc<<<69, 512>>>(1, gb + DD);
    // 8. outputs: y = (hA_x @ bw + bb) * tcw[to], labels
    k_gemm3<<<dim3(1, 32), 256>>>(4, bw, 0, BN, NC, DD, DD, NC, NC, bb, 0, tcw, to, out + y_off);
    k_labels<<<16, 256>>>(lb, out, lbl_off, out_size);
}

// round 6
// speedup vs baseline: 4.1782x; 1.2907x over previous
#include <cuda_runtime.h>
#include <math.h>
#include <stdint.h>

#define BN 4096
#define DD 512
#define NT 4
#define NC 65
#define TC 69          // NT + NC
#define NS 4165        // TC + BN
#define CFLD 72        // padded cf row stride

// ---------------- scratch (device globals; no allocations) ----------------
__device__ float g_xm[BN*DD];
__device__ float g_q[BN*DD];
__device__ float g_kall[NS*DD];
__device__ float g_hA[NS*DD];
__device__ float g_hB[NS*DD];
__device__ float g_hw[NS*DD];
__device__ float g_tsum[NT*DD];
__device__ float g_csum[NC*DD];
__device__ int   g_cntT[NT];
__device__ int   g_cntC[NC];
__device__ float g_adj[TC*TC];
__device__ float g_cross[NT*NC];
__device__ float g_cf[BN*CFLD];
__device__ float g_l69[BN*TC];
__device__ float g_mp[8*BN];
__device__ float g_zp[8*BN];
__device__ float g_C69[TC*DD];
__device__ float g_bwPad[DD*CFLD];

// ---------------- tf32 / mma / cp.async helpers ----------------
__device__ __forceinline__ float tf32r(float x) {
    uint32_t u;
    asm("cvt.rna.tf32.f32 %0, %1;" : "=r"(u) : "f"(x));
    return __uint_as_float(u);
}
__device__ __forceinline__ void mma8(float* c, uint32_t a0, uint32_t a1,
                                     uint32_t a2, uint32_t a3,
                                     uint32_t b0, uint32_t b1) {
    asm("mma.sync.aligned.m16n8k8.row.col.f32.tf32.tf32.f32 "
        "{%0,%1,%2,%3},{%4,%5,%6,%7},{%8,%9},{%0,%1,%2,%3};"
        : "+f"(c[0]), "+f"(c[1]), "+f"(c[2]), "+f"(c[3])
        : "r"(a0), "r"(a1), "r"(a2), "r"(a3), "r"(b0), "r"(b1));
}
__device__ __forceinline__ uint32_t fb(float x) { return __float_as_uint(x); }
__device__ __forceinline__ uint32_t ftf(float x) {  // cvt+bits
    uint32_t u;
    asm("cvt.rna.tf32.f32 %0, %1;" : "=r"(u) : "f"(x));
    return u;
}
__device__ __forceinline__ void cpa16(uint32_t dst, const float* src, int srcBytes) {
    asm volatile("cp.async.cg.shared.global [%0], [%1], 16, %2;"
                 :: "r"(dst), "l"(src), "r"(srcBytes));
}
#define CPA_COMMIT() asm volatile("cp.async.commit_group;" ::: "memory")
#define CPA_WAIT0()  asm volatile("cp.async.wait_group 0;" ::: "memory")

// ---------------- selectors ----------------
__device__ __forceinline__ const float* selA3(int s) {
    switch (s) {
        case 0: return g_xm;  case 1: return g_hA;  case 2: return g_hB;
        case 3: return g_cf;  case 4: return g_hA + TC*DD;
    }
    return g_xm;
}
__device__ __forceinline__ const float* selB3(int s, const float* Bp) {
    switch (s) { case 1: return g_hw; case 2: return g_bwPad; }
    return Bp;
}
__device__ __forceinline__ float* selC3(int s) {
    switch (s) {
        case 0: return g_q;  case 1: return g_kall;  case 2: return g_hw;
        case 3: return g_hB + TC*DD;  case 4: return g_hA + TC*DD;
    }
    return g_q;
}

// ---------------- xm = mean over 7x7; also write src rows 69.. -------------
__global__ void k_xm(const float* __restrict__ x) {
    __shared__ float buf[4][32*49];
    int w = threadIdx.x >> 5, lane = threadIdx.x & 31;
    int base = (blockIdx.x*4 + w) * 32;
    const float* src = x + (size_t)base*49;
    float* b = buf[w];
    #pragma unroll
    for (int t = 0; t < 49; t++) b[lane + 32*t] = src[lane + 32*t];
    __syncwarp();
    float s = 0.f;
    #pragma unroll
    for (int t = 0; t < 49; t++) s += b[lane*49 + t];
    s *= (1.f/49.f);
    int seg = base + lane;
    g_xm[seg] = s;
    g_hA[TC*DD + seg] = s;
}

// ---------------- zero / counts / segsum / t1c1 / padbw ----------------
__global__ void k_zero_seg() {
    int i = blockIdx.x*256 + threadIdx.x;
    if (i < NT*DD) g_tsum[i] = 0.f;
    if (i < NC*DD) g_csum[i] = 0.f;
    if (i < NT) g_cntT[i] = 0;
    if (i < NC) g_cntC[i] = 0;
}
__global__ void k_zero_c69() {
    int i = blockIdx.x*256 + threadIdx.x;
    if (i < TC*DD) g_C69[i] = 0.f;
}
__global__ void k_padbw(const float* __restrict__ bw) {
    int i = blockIdx.x*256 + threadIdx.x;
    if (i < DD*CFLD) {
        int r = i / CFLD, c = i - r*CFLD;
        g_bwPad[i] = (c < NC) ? bw[r*NC + c] : 0.f;
    }
}
__global__ void k_count(const int* __restrict__ to, const int* __restrict__ lb) {
    int i = blockIdx.x*256 + threadIdx.x;
    if (i < BN) { atomicAdd(&g_cntT[to[i]], 1); atomicAdd(&g_cntC[lb[i]], 1); }
}
__global__ void k_segsum(const int* __restrict__ to, const int* __restrict__ lb) {
    __shared__ float sT[NT][64];
    __shared__ float sC[NC][64];
    int t = threadIdx.x;
    int cr = t & 63, rr = t >> 6;
    int r0 = blockIdx.y * 64, c0 = blockIdx.x * 64;
    for (int i = t; i < NT*64; i += 256) ((float*)sT)[i] = 0.f;
    for (int i = t; i < NC*64; i += 256) ((float*)sC)[i] = 0.f;
    __syncthreads();
    for (int r = r0 + rr; r < r0 + 64; r += 4) {
        int tt = to[r], cc = lb[r];
        float v = g_xm[r*DD + c0 + cr];
        atomicAdd(&sT[tt][cr], v);
        atomicAdd(&sC[cc][cr], v);
    }
    __syncthreads();
    for (int i = t; i < NT*64; i += 256)
        atomicAdd(&g_tsum[(i>>6)*DD + c0 + (i&63)], ((float*)sT)[i]);
    for (int i = t; i < NC*64; i += 256)
        atomicAdd(&g_csum[(i>>6)*DD + c0 + (i&63)], ((float*)sC)[i]);
}
__global__ void k_t1c1(const float* __restrict__ trep, const float* __restrict__ cpro) {
    int i = blockIdx.x*256 + threadIdx.x;
    if (i >= TC*DD) return;
    int seg = i / DD, d = i % DD;
    float v;
    if (seg < NT) {
        float cnt = fmaxf((float)g_cntT[seg], 1.f);
        v = 0.9f*trep[i] + 0.1f*g_tsum[i]/cnt;
    } else {
        int c = seg - NT;
        float cnt = fmaxf((float)g_cntC[c], 1.f);
        v = 0.9f*cpro[c*DD+d] + 0.1f*g_csum[c*DD+d]/cnt;
    }
    g_hA[i] = v;
}

// ---------------- graph kernels ----------------
__global__ void k_d2cross() {
    int c = blockIdx.x;
    int w = threadIdx.x >> 5, lane = threadIdx.x & 31;
    __shared__ float sd2[NT];
    const float* t1 = g_hA;
    const float* c1 = g_hA + NT*DD;
    float s = 0.f;
    for (int d = lane; d < DD; d += 32) {
        float df = t1[w*DD+d] - c1[c*DD+d];
        s += df*df;
    }
    #pragma unroll
    for (int o = 16; o; o >>= 1) s += __shfl_xor_sync(0xffffffffu, s, o);
    if (lane == 0) sd2[w] = s;
    __syncthreads();
    if (threadIdx.x == 0) {
        float l[NT], mx = -1e30f;
        for (int t = 0; t < NT; t++) { l[t] = -sd2[t]*(1.f/16.f); mx = fmaxf(mx, l[t]); }
        float Z = 0.f;
        for (int t = 0; t < NT; t++) { l[t] = expf(l[t]-mx); Z += l[t]; }
        for (int t = 0; t < NT; t++) {
            float p = l[t]/Z;
            g_cross[t*NC + c] = p;
            g_adj[t*TC + NT + c] = p;
            g_adj[(NT+c)*TC + t] = p;
        }
    }
}
__global__ void k_tg(const float* __restrict__ tw, const float* __restrict__ tb) {
    int i = blockIdx.x >> 2, j = blockIdx.x & 3;
    int lane = threadIdx.x;
    const float* t1 = g_hA;
    float s = 0.f;
    for (int d = lane; d < DD; d += 32)
        s += fabsf(t1[i*DD+d]-t1[j*DD+d]) * tw[d];
    #pragma unroll
    for (int o = 16; o; o >>= 1) s += __shfl_xor_sync(0xffffffffu, s, o);
    if (lane == 0) {
        float v = 1.f/(1.f+expf(-(s + tb[0])));
        if (i == j) v = 0.f;
        g_adj[i*TC+j] = v;
    }
}
__global__ void k_cg(const float* __restrict__ cw, const float* __restrict__ cb) {
    int i = blockIdx.x, j = blockIdx.y;
    int lane = threadIdx.x;
    const float* c1 = g_hA + NT*DD;
    float s = 0.f;
    for (int d = lane; d < DD; d += 32)
        s += fabsf(c1[i*DD+d]-c1[j*DD+d]) * cw[d];
    #pragma unroll
    for (int o = 16; o; o >>= 1) s += __shfl_xor_sync(0xffffffffu, s, o);
    if (lane == 0) {
        float v = 1.f/(1.f+expf(-(s + cb[0])));
        if (i == j) v = 0.f;
        g_adj[(NT+i)*TC + NT+j] = v;
    }
}
__global__ void k_ae(float* out) {
    __shared__ float s[NC];
    int c = threadIdx.x;
    float a = 0.f;
    for (int t = 0; t < NT; t++) { float p = g_cross[t*NC+c]; a += p*logf(p); }
    s[c] = a;
    __syncthreads();
    if (c == 0) { float r = 0.f; for (int i = 0; i < NC; i++) r += s[i]; out[0] = r/(float)NC; }
}

// ---------------- tf32 GEMM (cp.async double-buffered) ---------------------
// C = A(MxK,row) @ B(KxN,row). Block 128x128, 8 warps (4m x 2n), warp 32x64.
// Dynamic smem: As[2][128][36] + Bs[2][32][136].
#define GEMM_SMEM ((2*128*36 + 2*32*136)*4)
#define AS(p,r,c) smp[(p)*4608 + (r)*36 + (c)]
#define BS(p,r,c) smp[9216 + (p)*4352 + (r)*136 + (c)]
__global__ void __launch_bounds__(256) k_gemm3(
        int aSel, int bSel, const float* __restrict__ Bp, int cSel,
        int M, int N, int K, int lda, int ldb, int ldc,
        const float* __restrict__ bias, int relu,
        const float* __restrict__ tcw, const int* __restrict__ to,
        float* yout) {
    extern __shared__ float smp[];
    const float* A = selA3(aSel);
    const float* B = selB3(bSel, Bp);
    float* C = yout ? yout : selC3(cSel);
    int tid = threadIdx.x;
    int w = tid >> 5, lane = tid & 31, g = lane >> 2, t = lane & 3;
    int wm = (w & 3) * 32, wn = (w >> 2) * 64;
    int m0 = blockIdx.y*128, n0 = blockIdx.x*128;
    uint32_t sb = (uint32_t)__cvta_generic_to_shared(smp);

    auto fillA = [&](int p, int k0) {
        #pragma unroll
        for (int r = 0; r < 4; r++) {
            int idx = tid + 256*r;
            int row = idx >> 3, fc = idx & 7;
            int gm = m0 + row, gk = k0 + fc*4;
            int sz = 16;
            if (gm >= M) sz = 0;
            int rem = (K - gk)*4;
            if (rem < sz) sz = rem < 0 ? 0 : rem;
            const float* src = sz > 0 ? &A[(size_t)gm*lda + gk] : A;
            cpa16(sb + (uint32_t)(p*4608 + row*36 + fc*4)*4u, src, sz);
        }
    };
    auto fillB = [&](int p, int k0) {
        #pragma unroll
        for (int r = 0; r < 4; r++) {
            int idx = tid + 256*r;
            int row = idx >> 5, c4 = (idx & 31)*4;
            int gk = k0 + row, gn = n0 + c4;
            int sz = 16;
            if (gk >= K) sz = 0;
            int rem = (N - gn)*4;
            if (rem < sz) sz = rem < 0 ? 0 : rem;
            const float* src = sz > 0 ? &B[(size_t)gk*ldb + gn] : B;
            cpa16(sb + (uint32_t)(9216 + p*4352 + row*136 + c4)*4u, src, sz);
        }
    };

    float acc[2][8][4] = {};
    int nk = (K + 31) >> 5;
    fillA(0, 0); fillB(0, 0); CPA_COMMIT();
    for (int kc = 0; kc < nk; kc++) {
        CPA_WAIT0();
        __syncthreads();
        if (kc + 1 < nk) { fillA((kc+1)&1, (kc+1)*32); fillB((kc+1)&1, (kc+1)*32); CPA_COMMIT(); }
        int p = kc & 1;
        #pragma unroll
        for (int kk = 0; kk < 32; kk += 8) {
            uint32_t a[2][4];
            #pragma unroll
            for (int mi = 0; mi < 2; mi++) {
                a[mi][0] = ftf(AS(p, wm+mi*16+g  , kk+t));
                a[mi][1] = ftf(AS(p, wm+mi*16+g+8, kk+t));
                a[mi][2] = ftf(AS(p, wm+mi*16+g  , kk+t+4));
                a[mi][3] = ftf(AS(p, wm+mi*16+g+8, kk+t+4));
            }
            uint32_t b[8][2];
            #pragma unroll
            for (int ni = 0; ni < 8; ni++) {
                b[ni][0] = ftf(BS(p, kk+t  , wn+ni*8+g));
                b[ni][1] = ftf(BS(p, kk+t+4, wn+ni*8+g));
            }
            #pragma unroll
            for (int mi = 0; mi < 2; mi++)
                #pragma unroll
                for (int ni = 0; ni < 8; ni++)
                    mma8(acc[mi][ni], a[mi][0], a[mi][1], a[mi][2], a[mi][3],
                         b[ni][0], b[ni][1]);
        }
        __syncthreads();
    }
    #pragma unroll
    for (int mi = 0; mi < 2; mi++) {
        int r0 = m0 + wm + mi*16 + g, r1 = r0 + 8;
        #pragma unroll
        for (int ni = 0; ni < 8; ni++) {
            int n = n0 + wn + ni*8 + 2*t;
            float bv0 = 0.f, bv1 = 0.f;
            if (bias) { if (n < N) bv0 = bias[n]; if (n+1 < N) bv1 = bias[n+1]; }
            float v00 = acc[mi][ni][0] + bv0, v01 = acc[mi][ni][1] + bv1;
            float v10 = acc[mi][ni][2] + bv0, v11 = acc[mi][ni][3] + bv1;
            if (relu) {
                v00 = fmaxf(v00, 0.f); v01 = fmaxf(v01, 0.f);
                v10 = fmaxf(v10, 0.f); v11 = fmaxf(v11, 0.f);
            }
            if (yout) {
                if (r0 < M) {
                    if (n < N)   C[(size_t)r0*ldc + n]   = tcw[to[r0]*NC + n]   * v00;
                    if (n+1 < N) C[(size_t)r0*ldc + n+1] = tcw[to[r0]*NC + n+1] * v01;
                }
                if (r1 < M) {
                    if (n < N)   C[(size_t)r1*ldc + n]   = tcw[to[r1]*NC + n]   * v10;
                    if (n+1 < N) C[(size_t)r1*ldc + n+1] = tcw[to[r1]*NC + n+1] * v11;
                }
            } else {
                if (r0 < M) {
                    if (n < N)   C[(size_t)r0*ldc + n]   = v00;
                    if (n+1 < N) C[(size_t)r0*ldc + n+1] = v01;
                }
                if (r1 < M) {
                    if (n < N)   C[(size_t)r1*ldc + n]   = v10;
                    if (n+1 < N) C[(size_t)r1*ldc + n+1] = v11;
                }
            }
        }
    }
}

// ---------------- attention (cp.async double-buffered, streaming softmax) --
// grid (32 row-blocks, 7 splits). Block 128 q x 128 keys, warp 32x64.
// split 0 / jt 0 additionally stores the first-69 (scaled) logits to g_l69.
#define NJT 33
#define JPT 5
#define ATTN_SMEM ((2*128*36*2)*4)
#define QS(p,r,c) smp[(p)*4608 + (r)*36 + (c)]
#define KS(p,r,c) smp[9216 + (p)*4608 + (r)*36 + (c)]
__global__ void __launch_bounds__(256) k_attn3() {
    extern __shared__ float smp[];
    __shared__ float sm_m[2][128];
    __shared__ float sm_z[2][128];
    int tid = threadIdx.x;
    int w = tid >> 5, lane = tid & 31, g = lane >> 2, t = lane & 3;
    int wm = (w & 3) * 32, wn = (w >> 2) * 64;
    int half = w >> 2;
    int i0 = blockIdx.x*128;
    int split = blockIdx.y;
    const float sc = 0.044194173824159216f;   // 1/sqrt(512)
    uint32_t sb = (uint32_t)__cvta_generic_to_shared(smp);

    auto fillQ = [&](int p, int k0) {
        #pragma unroll
        for (int r = 0; r < 4; r++) {
            int idx = tid + 256*r;
            int row = idx >> 3, fc = idx & 7;
            cpa16(sb + (uint32_t)(p*4608 + row*36 + fc*4)*4u,
                  &g_q[(size_t)(i0+row)*DD + k0 + fc*4], 16);
        }
    };
    auto fillK = [&](int p, int j0v, int k0) {
        #pragma unroll
        for (int r = 0; r < 4; r++) {
            int idx = tid + 256*r;
            int row = idx >> 3, fc = idx & 7;
            int gj = j0v + row;
            int sz = gj < NS ? 16 : 0;
            const float* src = sz ? &g_kall[(size_t)gj*DD + k0 + fc*4] : g_kall;
            cpa16(sb + (uint32_t)(9216 + p*4608 + row*36 + fc*4)*4u, src, sz);
        }
    };

    float mr[2][2] = {{-1e30f,-1e30f},{-1e30f,-1e30f}};
    float zr[2][2] = {{0.f,0.f},{0.f,0.f}};
    int jt0 = split*JPT;
    int jt1 = jt0 + JPT; if (jt1 > NJT) jt1 = NJT;
    int cg = 0;
    fillQ(0, 0); fillK(0, jt0*128, 0); CPA_COMMIT();
    for (int jt = jt0; jt < jt1; jt++) {
        int j0 = jt*128;
        float acc[2][8][4] = {};
        for (int c = 0; c < 16; c++, cg++) {
            CPA_WAIT0();
            __syncthreads();
            int p = cg & 1;
            if (c < 15) {
                fillQ(p^1, (c+1)*32); fillK(p^1, j0, (c+1)*32); CPA_COMMIT();
            } else if (jt + 1 < jt1) {
                fillQ(p^1, 0); fillK(p^1, (jt+1)*128, 0); CPA_COMMIT();
            }
            #pragma unroll
            for (int kk = 0; kk < 32; kk += 8) {
                uint32_t a[2][4];
                #pragma unroll
                for (int mi = 0; mi < 2; mi++) {
                    a[mi][0] = ftf(QS(p, wm+mi*16+g  , kk+t));
                    a[mi][1] = ftf(QS(p, wm+mi*16+g+8, kk+t));
                    a[mi][2] = ftf(QS(p, wm+mi*16+g  , kk+t+4));
                    a[mi][3] = ftf(QS(p, wm+mi*16+g+8, kk+t+4));
                }
                uint32_t b[8][2];
                #pragma unroll
                for (int ni = 0; ni < 8; ni++) {
                    b[ni][0] = ftf(KS(p, wn+ni*8+g, kk+t));
                    b[ni][1] = ftf(KS(p, wn+ni*8+g, kk+t+4));
                }
                #pragma unroll
                for (int mi = 0; mi < 2; mi++)
                    #pragma unroll
                    for (int ni = 0; ni < 8; ni++)
                        mma8(acc[mi][ni], a[mi][0], a[mi][1], a[mi][2], a[mi][3],
                             b[ni][0], b[ni][1]);
            }
            __syncthreads();
        }
        // epilogue: scale, mask, (optional l69 store), online softmax update
        int doL = (split == 0 && jt == 0);
        #pragma unroll
        for (int mi = 0; mi < 2; mi++) {
            int r0g = i0 + wm + mi*16 + g, r1g = r0g + 8;
            float lm0 = -1e30f, lm1 = -1e30f;
            #pragma unroll
            for (int ni = 0; ni < 8; ni++) {
                int base = j0 + wn + ni*8 + 2*t;
                float v0 = (base   < NS) ? acc[mi][ni][0]*sc : -1e30f;
                float v1 = (base+1 < NS) ? acc[mi][ni][1]*sc : -1e30f;
                float v2 = (base   < NS) ? acc[mi][ni][2]*sc : -1e30f;
                float v3 = (base+1 < NS) ? acc[mi][ni][3]*sc : -1e30f;
                acc[mi][ni][0] = v0; acc[mi][ni][1] = v1;
                acc[mi][ni][2] = v2; acc[mi][ni][3] = v3;
                if (doL) {
                    int c0 = wn + ni*8 + 2*t;
                    if (c0 < TC) {
                        g_l69[(size_t)r0g*TC + c0] = v0;
                        g_l69[(size_t)r1g*TC + c0] = v2;
                    }
                    if (c0 + 1 < TC) {
                        g_l69[(size_t)r0g*TC + c0+1] = v1;
                        g_l69[(size_t)r1g*TC + c0+1] = v3;
                    }
                }
                lm0 = fmaxf(lm0, fmaxf(v0, v1));
                lm1 = fmaxf(lm1, fmaxf(v2, v3));
            }
            lm0 = fmaxf(lm0, __shfl_xor_sync(0xffffffffu, lm0, 1));
            lm0 = fmaxf(lm0, __shfl_xor_sync(0xffffffffu, lm0, 2));
            lm1 = fmaxf(lm1, __shfl_xor_sync(0xffffffffu, lm1, 1));
            lm1 = fmaxf(lm1, __shfl_xor_sync(0xffffffffu, lm1, 2));
            float nm0 = fmaxf(mr[mi][0], lm0), nm1 = fmaxf(mr[mi][1], lm1);
            float p0 = 0.f, p1 = 0.f;
            #pragma unroll
            for (int ni = 0; ni < 8; ni++) {
                p0 += __expf(acc[mi][ni][0]-nm0) + __expf(acc[mi][ni][1]-nm0);
                p1 += __expf(acc[mi][ni][2]-nm1) + __expf(acc[mi][ni][3]-nm1);
            }
            p0 += __shfl_xor_sync(0xffffffffu, p0, 1);
            p0 += __shfl_xor_sync(0xffffffffu, p0, 2);
            p1 += __shfl_xor_sync(0xffffffffu, p1, 1);
            p1 += __shfl_xor_sync(0xffffffffu, p1, 2);
            zr[mi][0] = zr[mi][0]*__expf(mr[mi][0] - nm0) + p0; mr[mi][0] = nm0;
            zr[mi][1] = zr[mi][1]*__expf(mr[mi][1] - nm1) + p1; mr[mi][1] = nm1;
        }
    }
    // merge the two column-half partials per row, then write
    if (t == 0) {
        #pragma unroll
        for (int mi = 0; mi < 2; mi++) {
            int r = wm + mi*16 + g;
            sm_m[half][r]     = mr[mi][0];  sm_z[half][r]     = zr[mi][0];
            sm_m[half][r + 8] = mr[mi][1];  sm_z[half][r + 8] = zr[mi][1];
        }
    }
    __syncthreads();
    if (tid < 128) {
        float m0 = sm_m[0][tid], m1 = sm_m[1][tid];
        float m = fmaxf(m0, m1);
        float z = sm_z[0][tid]*__expf(m0 - m) + sm_z[1][tid]*__expf(m1 - m);
        g_mp[split*BN + i0 + tid] = m;
        g_zp[split*BN + i0 + tid] = z;
    }
}

// ---------------- combine splits + first-69 softmax -> cf (padded) --------
__global__ void k_cf() {
    int i = blockIdx.x;
    int j = threadIdx.x;          // 96 threads
    __shared__ float sh[2];
    if (j == 0) {
        float m = -1e30f;
        #pragma unroll
        for (int s = 0; s < 7; s++) m = fmaxf(m, g_mp[s*BN + i]);
        float z = 0.f;
        #pragma unroll
        for (int s = 0; s < 7; s++) z += g_zp[s*BN + i]*__expf(g_mp[s*BN + i] - m);
        sh[0] = m; sh[1] = 1.f/z;
    }
    __syncthreads();
    if (j < CFLD)
        g_cf[i*CFLD + j] = (j < TC) ? __expf(g_l69[i*TC + j] - sh[0]) * sh[1] : 0.f;
}

// ---------------- GNN tc-rows partial: C69 += cf^T @ hw_x ----------------
__global__ void k_outtc() {
    __shared__ float cfs[64][72];
    __shared__ float hws[64][64];
    int t = threadIdx.x, tx = t & 63, ty = t >> 6;
    int n0 = blockIdx.x*64;
    int b0 = blockIdx.y*256;
    float acc[18];
    #pragma unroll
    for (int k = 0; k < 18; k++) acc[k] = 0.f;
    for (int bc = 0; bc < 256; bc += 64) {
        int bb = b0 + bc;
        for (int i = t; i < 64*TC; i += 256) {
            int r = i/TC, k = i%TC;
            cfs[r][k] = g_cf[(size_t)(bb+r)*CFLD + k];
        }
        for (int i = t; i < 64*64; i += 256) {
            int r = i >> 6, n = i & 63;
            hws[r][n] = g_hw[(size_t)(TC+bb+r)*DD + n0 + n];
        }
        __syncthreads();
        for (int r = 0; r < 64; r++) {
            float hv = hws[r][tx];
            #pragma unroll
            for (int k = 0; k < 18; k++) {
                int m = ty + 4*k;
                if (m < TC) acc[k] += cfs[r][m]*hv;
            }
        }
        __syncthreads();
    }
    #pragma unroll
    for (int k = 0; k < 18; k++) {
        int m = ty + 4*k;
        if (m < TC) atomicAdd(&g_C69[m*DD + n0 + tx], acc[k]);
    }
}

// ---------------- finalize tc rows ----------------
__global__ void k_fintc(int dst, const float* __restrict__ gb) {
    float* H = (dst == 0) ? g_hB : g_hA;
    int m = blockIdx.x;      // 69
    int n = threadIdx.x;     // 512
    float v = g_C69[m*DD + n];
    for (int j = 0; j < TC; j++)
        v += g_adj[m*TC+j] * g_hw[j*DD + n];
    v += gb[n];
    H[m*DD + n] = fmaxf(v, 0.f);
}

// ---------------- labels ----------------
__global__ void k_labels(const int* __restrict__ lb, float* out, int off, int out_size) {
    int i = blockIdx.x*256 + threadIdx.x;
    if (i < BN && off + i < out_size) out[off + i] = (float)lb[i];
}

// ======================== host ========================
extern "C" void kernel_launch(void* const* d_in, const int* in_sizes, int n_in,
                              void* d_out, int out_size) {
    const float* x    = (const float*)d_in[0];
    const int*   lb   = (const int*)d_in[1];
    const int*   to   = (const int*)d_in[2];
    const float* trep = (const float*)d_in[3];
    const float* cpro = (const float*)d_in[4];
    const float* tw   = (const float*)d_in[5];
    const float* tb   = (const float*)d_in[6];
    const float* cw   = (const float*)d_in[7];
    const float* cb   = (const float*)d_in[8];
    const float* wq   = (const float*)d_in[9];
    const float* wk   = (const float*)d_in[10];
    const float* gw   = (const float*)d_in[11];
    const float* gb   = (const float*)d_in[12];
    const float* bw   = (const float*)d_in[13];
    const float* bb   = (const float*)d_in[14];
    const float* tcw  = (const float*)d_in[15];
    float* out = (float*)d_out;

    cudaFuncSetAttribute(k_gemm3, cudaFuncAttributeMaxDynamicSharedMemorySize, GEMM_SMEM);
    cudaFuncSetAttribute(k_attn3, cudaFuncAttributeMaxDynamicSharedMemorySize, ATTN_SMEM);

    int y_off = (out_size > BN*NC) ? 1 : 0;
    int lbl_off = y_off + BN*NC;

    // 1. xm + src x-rows, pad base_w
    k_xm<<<16384, 128>>>(x);
    k_padbw<<<(DD*CFLD + 255)/256, 256>>>(bw);
    // 2. segment means -> t1/c1
    k_zero_seg<<<(NC*DD + 255)/256, 256>>>();
    k_count<<<16, 256>>>(to, lb);
    k_segsum<<<dim3(8, 64), 256>>>(to, lb);
    k_t1c1<<<(TC*DD + 255)/256, 256>>>(trep, cpro);
    // 3. graphs
    k_d2cross<<<65, 128>>>();
    k_tg<<<16, 32>>>(tw, tb);
    k_cg<<<dim3(65, 65), 32>>>(cw, cb);
    if (y_off) k_ae<<<1, 65>>>(out);
    // 4. projections: q = xm@wq, kall = src@wk
    k_gemm3<<<dim3(4, 32), 256, GEMM_SMEM>>>(0, 0, wq, 0, BN, DD, DD, DD, DD, DD, nullptr, 0, nullptr, nullptr, nullptr);
    k_gemm3<<<dim3(4, 33), 256, GEMM_SMEM>>>(1, 0, wk, 1, NS, DD, DD, DD, DD, DD, nullptr, 0, nullptr, nullptr, nullptr);
    // 5. attention stats (+ first-69 logits) + cross_feat
    k_attn3<<<dim3(32, 7), 256, ATTN_SMEM>>>();
    k_cf<<<4096, 96>>>();
    // 6. GNN layer 0: hA -> hB
    k_gemm3<<<dim3(4, 33), 256, GEMM_SMEM>>>(1, 0, gw, 2, NS, DD, DD, DD, DD, DD, nullptr, 0, nullptr, nullptr, nullptr);
    k_gemm3<<<dim3(4, 32), 256, GEMM_SMEM>>>(3, 1, nullptr, 3, BN, DD, CFLD, CFLD, DD, DD, gb, 1, nullptr, nullptr, nullptr);
    k_zero_c69<<<(TC*DD + 255)/256, 256>>>();
    k_outtc<<<dim3(8, 16), 256>>>();
    k_fintc<<<69, 512>>>(0, gb);
    // 7. GNN layer 1: hB -> hA
    k_gemm3<<<dim3(4, 33), 256, GEMM_SMEM>>>(2, 0, gw + DD*DD, 2, NS, DD, DD, DD, DD, DD, nullptr, 0, nullptr, nullptr, nullptr);
    k_gemm3<<<dim3(4, 32), 256, GEMM_SMEM>>>(3, 1, nullptr, 4, BN, DD, CFLD, CFLD, DD, DD, gb + DD, 1, nullptr, nullptr, nullptr);
    k_zero_c69<<<(TC*DD + 255)/256, 256>>>();
    k_outtc<<<dim3(8, 16), 256>>>();
    k_fintc<<<69, 512>>>(1, gb + DD);
    // 8. outputs: y = (hA_x @ bwPad + bb) * tcw[to], labels
    k_gemm3<<<dim3(1, 32), 256, GEMM_SMEM>>>(4, 2, nullptr, 0, BN, NC, DD, DD, CFLD, NC, bb, 0, tcw, to, out + y_off);
    k_labels<<<16, 256>>>(lb, out, lbl_off, out_size);
}

// round 7
// speedup vs baseline: 4.9979x; 1.1962x over previous
#include <cuda_runtime.h>
#include <math.h>
#include <stdint.h>

#define BN 4096
#define DD 512
#define NT 4
#define NC 65
#define TC 69          // NT + NC
#define NS 4165        // TC + BN
#define CFLD 72        // padded cf row stride
#define NSPL 9         // attention splits
#define NJT 33
#define JPT 4

// ---------------- scratch (device globals; no allocations) ----------------
__device__ float g_xm[BN*DD];
__device__ float g_q[BN*DD];
__device__ float g_kall[NS*DD];
__device__ float g_hA[NS*DD];
__device__ float g_hB[NS*DD];
__device__ float g_hw[NS*DD];
__device__ float g_tsum[NT*DD];
__device__ float g_csum[NC*DD];
__device__ int   g_cntT[NT];
__device__ int   g_cntC[NC];
__device__ float g_adj[TC*TC];
__device__ float g_cross[NT*NC];
__device__ float g_cf[BN*CFLD];
__device__ float g_l69[BN*TC];
__device__ float g_mp[16*BN];
__device__ float g_zp[16*BN];
__device__ float g_C69[TC*DD];
__device__ float g_bwPad[DD*CFLD];

// ---------------- tf32 / mma / cp.async helpers ----------------
__device__ __forceinline__ void mma8(float* c, uint32_t a0, uint32_t a1,
                                     uint32_t a2, uint32_t a3,
                                     uint32_t b0, uint32_t b1) {
    asm("mma.sync.aligned.m16n8k8.row.col.f32.tf32.tf32.f32 "
        "{%0,%1,%2,%3},{%4,%5,%6,%7},{%8,%9},{%0,%1,%2,%3};"
        : "+f"(c[0]), "+f"(c[1]), "+f"(c[2]), "+f"(c[3])
        : "r"(a0), "r"(a1), "r"(a2), "r"(a3), "r"(b0), "r"(b1));
}
__device__ __forceinline__ uint32_t ftf(float x) {
    uint32_t u;
    asm("cvt.rna.tf32.f32 %0, %1;" : "=r"(u) : "f"(x));
    return u;
}
__device__ __forceinline__ void cpa16(uint32_t dst, const float* src, int srcBytes) {
    asm volatile("cp.async.cg.shared.global [%0], [%1], 16, %2;"
                 :: "r"(dst), "l"(src), "r"(srcBytes));
}
#define CPA_COMMIT() asm volatile("cp.async.commit_group;" ::: "memory")
#define CPA_WAIT0()  asm volatile("cp.async.wait_group 0;" ::: "memory")

// ---------------- selectors ----------------
__device__ __forceinline__ const float* selA3(int s) {
    switch (s) {
        case 0: return g_xm;  case 1: return g_hA;  case 2: return g_hB;
        case 3: return g_cf;  case 4: return g_hA + TC*DD;
    }
    return g_xm;
}
__device__ __forceinline__ const float* selB3(int s, const float* Bp) {
    switch (s) { case 1: return g_hw; case 2: return g_bwPad; }
    return Bp;
}
__device__ __forceinline__ float* selC3(int s) {
    switch (s) {
        case 0: return g_q;  case 1: return g_kall;  case 2: return g_hw;
        case 3: return g_hB + TC*DD;  case 4: return g_hA + TC*DD;
    }
    return g_q;
}

// ---------------- xm = mean over 7x7; also write src rows 69.. -------------
__global__ void k_xm(const float* __restrict__ x) {
    __shared__ float buf[4][32*49];
    int w = threadIdx.x >> 5, lane = threadIdx.x & 31;
    int base = (blockIdx.x*4 + w) * 32;
    const float* src = x + (size_t)base*49;
    float* b = buf[w];
    #pragma unroll
    for (int t = 0; t < 49; t++) b[lane + 32*t] = src[lane + 32*t];
    __syncwarp();
    float s = 0.f;
    #pragma unroll
    for (int t = 0; t < 49; t++) s += b[lane*49 + t];
    s *= (1.f/49.f);
    int seg = base + lane;
    g_xm[seg] = s;
    g_hA[TC*DD + seg] = s;
}

// ---------------- prep: zero seg sums/counts/C69, pad base_w ----------------
__global__ void k_prep(const float* __restrict__ bw) {
    int i = blockIdx.x*256 + threadIdx.x;
    if (i < NT*DD) g_tsum[i] = 0.f;
    if (i < NC*DD) g_csum[i] = 0.f;
    if (i < NT) g_cntT[i] = 0;
    if (i < NC) g_cntC[i] = 0;
    if (i < TC*DD) g_C69[i] = 0.f;
    if (i < DD*CFLD) {
        int r = i / CFLD, c = i - r*CFLD;
        g_bwPad[i] = (c < NC) ? bw[r*NC + c] : 0.f;
    }
}
__global__ void k_count(const int* __restrict__ to, const int* __restrict__ lb) {
    int i = blockIdx.x*256 + threadIdx.x;
    if (i < BN) { atomicAdd(&g_cntT[to[i]], 1); atomicAdd(&g_cntC[lb[i]], 1); }
}
__global__ void k_segsum(const int* __restrict__ to, const int* __restrict__ lb) {
    __shared__ float sT[NT][64];
    __shared__ float sC[NC][64];
    int t = threadIdx.x;
    int cr = t & 63, rr = t >> 6;
    int r0 = blockIdx.y * 64, c0 = blockIdx.x * 64;
    for (int i = t; i < NT*64; i += 256) ((float*)sT)[i] = 0.f;
    for (int i = t; i < NC*64; i += 256) ((float*)sC)[i] = 0.f;
    __syncthreads();
    for (int r = r0 + rr; r < r0 + 64; r += 4) {
        int tt = to[r], cc = lb[r];
        float v = g_xm[r*DD + c0 + cr];
        atomicAdd(&sT[tt][cr], v);
        atomicAdd(&sC[cc][cr], v);
    }
    __syncthreads();
    for (int i = t; i < NT*64; i += 256)
        atomicAdd(&g_tsum[(i>>6)*DD + c0 + (i&63)], ((float*)sT)[i]);
    for (int i = t; i < NC*64; i += 256)
        atomicAdd(&g_csum[(i>>6)*DD + c0 + (i&63)], ((float*)sC)[i]);
}
__global__ void k_t1c1(const float* __restrict__ trep, const float* __restrict__ cpro) {
    int i = blockIdx.x*256 + threadIdx.x;
    if (i >= TC*DD) return;
    int seg = i / DD, d = i % DD;
    float v;
    if (seg < NT) {
        float cnt = fmaxf((float)g_cntT[seg], 1.f);
        v = 0.9f*trep[i] + 0.1f*g_tsum[i]/cnt;
    } else {
        int c = seg - NT;
        float cnt = fmaxf((float)g_cntC[c], 1.f);
        v = 0.9f*cpro[c*DD+d] + 0.1f*g_csum[c*DD+d]/cnt;
    }
    g_hA[i] = v;
}

// ---------------- graph kernels ----------------
__global__ void k_d2cross() {
    int c = blockIdx.x;
    int w = threadIdx.x >> 5, lane = threadIdx.x & 31;
    __shared__ float sd2[NT];
    const float* t1 = g_hA;
    const float* c1 = g_hA + NT*DD;
    float s = 0.f;
    for (int d = lane; d < DD; d += 32) {
        float df = t1[w*DD+d] - c1[c*DD+d];
        s += df*df;
    }
    #pragma unroll
    for (int o = 16; o; o >>= 1) s += __shfl_xor_sync(0xffffffffu, s, o);
    if (lane == 0) sd2[w] = s;
    __syncthreads();
    if (threadIdx.x == 0) {
        float l[NT], mx = -1e30f;
        for (int t = 0; t < NT; t++) { l[t] = -sd2[t]*(1.f/16.f); mx = fmaxf(mx, l[t]); }
        float Z = 0.f;
        for (int t = 0; t < NT; t++) { l[t] = expf(l[t]-mx); Z += l[t]; }
        for (int t = 0; t < NT; t++) {
            float p = l[t]/Z;
            g_cross[t*NC + c] = p;
            g_adj[t*TC + NT + c] = p;
            g_adj[(NT+c)*TC + t] = p;
        }
    }
}
__global__ void k_tg(const float* __restrict__ tw, const float* __restrict__ tb) {
    int i = blockIdx.x >> 2, j = blockIdx.x & 3;
    int lane = threadIdx.x;
    const float* t1 = g_hA;
    float s = 0.f;
    for (int d = lane; d < DD; d += 32)
        s += fabsf(t1[i*DD+d]-t1[j*DD+d]) * tw[d];
    #pragma unroll
    for (int o = 16; o; o >>= 1) s += __shfl_xor_sync(0xffffffffu, s, o);
    if (lane == 0) {
        float v = 1.f/(1.f+expf(-(s + tb[0])));
        if (i == j) v = 0.f;
        g_adj[i*TC+j] = v;
    }
}
__global__ void k_cg(const float* __restrict__ cw, const float* __restrict__ cb) {
    int i = blockIdx.x, j = blockIdx.y;
    int lane = threadIdx.x;
    const float* c1 = g_hA + NT*DD;
    float s = 0.f;
    for (int d = lane; d < DD; d += 32)
        s += fabsf(c1[i*DD+d]-c1[j*DD+d]) * cw[d];
    #pragma unroll
    for (int o = 16; o; o >>= 1) s += __shfl_xor_sync(0xffffffffu, s, o);
    if (lane == 0) {
        float v = 1.f/(1.f+expf(-(s + cb[0])));
        if (i == j) v = 0.f;
        g_adj[(NT+i)*TC + NT+j] = v;
    }
}
__global__ void k_ae(float* out) {
    __shared__ float s[NC];
    int c = threadIdx.x;
    float a = 0.f;
    for (int t = 0; t < NT; t++) { float p = g_cross[t*NC+c]; a += p*logf(p); }
    s[c] = a;
    __syncthreads();
    if (c == 0) { float r = 0.f; for (int i = 0; i < NC; i++) r += s[i]; out[0] = r/(float)NC; }
}

// ---------------- tf32 GEMM (cp.async double-buffered) ---------------------
// C = A(MxK,row) @ B(KxN,row). Block 128x128, 8 warps (4m x 2n), warp 32x64.
// ySplit>0: blocks with blockIdx.y >= ySplit use the (aSel2,Bp2,cSel2,M2) config.
#define GEMM_SMEM ((2*128*36 + 2*32*136)*4)
#define AS(p,r,c) smp[(p)*4608 + (r)*36 + (c)]
#define BS(p,r,c) smp[9216 + (p)*4352 + (r)*136 + (c)]
__global__ void __launch_bounds__(256, 2) k_gemm3(
        int aSel, int bSel, const float* __restrict__ Bp, int cSel,
        int M, int N, int K, int lda, int ldb, int ldc,
        const float* __restrict__ bias, int relu,
        const float* __restrict__ tcw, const int* __restrict__ to,
        float* yout,
        int ySplit, int aSel2, const float* __restrict__ Bp2, int cSel2, int M2) {
    extern __shared__ float smp[];
    int by = blockIdx.y;
    if (ySplit > 0 && by >= ySplit) {
        aSel = aSel2; Bp = Bp2; cSel = cSel2; M = M2; by -= ySplit;
    }
    const float* A = selA3(aSel);
    const float* B = selB3(bSel, Bp);
    float* C = yout ? yout : selC3(cSel);
    int tid = threadIdx.x;
    int w = tid >> 5, lane = tid & 31, g = lane >> 2, t = lane & 3;
    int wm = (w & 3) * 32, wn = (w >> 2) * 64;
    int m0 = by*128, n0 = blockIdx.x*128;
    uint32_t sb = (uint32_t)__cvta_generic_to_shared(smp);

    auto fillA = [&](int p, int k0) {
        #pragma unroll
        for (int r = 0; r < 4; r++) {
            int idx = tid + 256*r;
            int row = idx >> 3, fc = idx & 7;
            int gm = m0 + row, gk = k0 + fc*4;
            int sz = 16;
            if (gm >= M) sz = 0;
            int rem = (K - gk)*4;
            if (rem < sz) sz = rem < 0 ? 0 : rem;
            const float* src = sz > 0 ? &A[(size_t)gm*lda + gk] : A;
            cpa16(sb + (uint32_t)(p*4608 + row*36 + fc*4)*4u, src, sz);
        }
    };
    auto fillB = [&](int p, int k0) {
        #pragma unroll
        for (int r = 0; r < 4; r++) {
            int idx = tid + 256*r;
            int row = idx >> 5, c4 = (idx & 31)*4;
            int gk = k0 + row, gn = n0 + c4;
            int sz = 16;
            if (gk >= K) sz = 0;
            int rem = (N - gn)*4;
            if (rem < sz) sz = rem < 0 ? 0 : rem;
            const float* src = sz > 0 ? &B[(size_t)gk*ldb + gn] : B;
            cpa16(sb + (uint32_t)(9216 + p*4352 + row*136 + c4)*4u, src, sz);
        }
    };

    float acc[2][8][4] = {};
    int nk = (K + 31) >> 5;
    fillA(0, 0); fillB(0, 0); CPA_COMMIT();
    for (int kc = 0; kc < nk; kc++) {
        CPA_WAIT0();
        __syncthreads();
        if (kc + 1 < nk) { fillA((kc+1)&1, (kc+1)*32); fillB((kc+1)&1, (kc+1)*32); CPA_COMMIT(); }
        int p = kc & 1;
        #pragma unroll
        for (int kk = 0; kk < 32; kk += 8) {
            uint32_t a[2][4];
            #pragma unroll
            for (int mi = 0; mi < 2; mi++) {
                a[mi][0] = ftf(AS(p, wm+mi*16+g  , kk+t));
                a[mi][1] = ftf(AS(p, wm+mi*16+g+8, kk+t));
                a[mi][2] = ftf(AS(p, wm+mi*16+g  , kk+t+4));
                a[mi][3] = ftf(AS(p, wm+mi*16+g+8, kk+t+4));
            }
            uint32_t b[8][2];
            #pragma unroll
            for (int ni = 0; ni < 8; ni++) {
                b[ni][0] = ftf(BS(p, kk+t  , wn+ni*8+g));
                b[ni][1] = ftf(BS(p, kk+t+4, wn+ni*8+g));
            }
            #pragma unroll
            for (int mi = 0; mi < 2; mi++)
                #pragma unroll
                for (int ni = 0; ni < 8; ni++)
                    mma8(acc[mi][ni], a[mi][0], a[mi][1], a[mi][2], a[mi][3],
                         b[ni][0], b[ni][1]);
        }
        __syncthreads();
    }
    #pragma unroll
    for (int mi = 0; mi < 2; mi++) {
        int r0 = m0 + wm + mi*16 + g, r1 = r0 + 8;
        #pragma unroll
        for (int ni = 0; ni < 8; ni++) {
            int n = n0 + wn + ni*8 + 2*t;
            float bv0 = 0.f, bv1 = 0.f;
            if (bias) { if (n < N) bv0 = bias[n]; if (n+1 < N) bv1 = bias[n+1]; }
            float v00 = acc[mi][ni][0] + bv0, v01 = acc[mi][ni][1] + bv1;
            float v10 = acc[mi][ni][2] + bv0, v11 = acc[mi][ni][3] + bv1;
            if (relu) {
                v00 = fmaxf(v00, 0.f); v01 = fmaxf(v01, 0.f);
                v10 = fmaxf(v10, 0.f); v11 = fmaxf(v11, 0.f);
            }
            if (yout) {
                if (r0 < M) {
                    if (n < N)   C[(size_t)r0*ldc + n]   = tcw[to[r0]*NC + n]   * v00;
                    if (n+1 < N) C[(size_t)r0*ldc + n+1] = tcw[to[r0]*NC + n+1] * v01;
                }
                if (r1 < M) {
                    if (n < N)   C[(size_t)r1*ldc + n]   = tcw[to[r1]*NC + n]   * v10;
                    if (n+1 < N) C[(size_t)r1*ldc + n+1] = tcw[to[r1]*NC + n+1] * v11;
                }
            } else {
                if (r0 < M) {
                    if (n < N)   C[(size_t)r0*ldc + n]   = v00;
                    if (n+1 < N) C[(size_t)r0*ldc + n+1] = v01;
                }
                if (r1 < M) {
                    if (n < N)   C[(size_t)r1*ldc + n]   = v10;
                    if (n+1 < N) C[(size_t)r1*ldc + n+1] = v11;
                }
            }
        }
    }
}

// ---------------- attention (cp.async double-buffered, streaming softmax) --
// grid (32 row-blocks, NSPL splits). Block 128 q x 128 keys, warp 32x64.
// split 0 / jt 0 additionally stores the first-69 (scaled) logits to g_l69.
#define ATTN_SMEM ((2*128*36*2)*4)
#define QS(p,r,c) smp[(p)*4608 + (r)*36 + (c)]
#define KS(p,r,c) smp[9216 + (p)*4608 + (r)*36 + (c)]
__global__ void __launch_bounds__(256, 2) k_attn3() {
    extern __shared__ float smp[];
    __shared__ float sm_m[2][128];
    __shared__ float sm_z[2][128];
    int tid = threadIdx.x;
    int w = tid >> 5, lane = tid & 31, g = lane >> 2, t = lane & 3;
    int wm = (w & 3) * 32, wn = (w >> 2) * 64;
    int half = w >> 2;
    int i0 = blockIdx.x*128;
    int split = blockIdx.y;
    const float sc = 0.044194173824159216f;   // 1/sqrt(512)
    uint32_t sb = (uint32_t)__cvta_generic_to_shared(smp);

    auto fillQ = [&](int p, int k0) {
        #pragma unroll
        for (int r = 0; r < 4; r++) {
            int idx = tid + 256*r;
            int row = idx >> 3, fc = idx & 7;
            cpa16(sb + (uint32_t)(p*4608 + row*36 + fc*4)*4u,
                  &g_q[(size_t)(i0+row)*DD + k0 + fc*4], 16);
        }
    };
    auto fillK = [&](int p, int j0v, int k0) {
        #pragma unroll
        for (int r = 0; r < 4; r++) {
            int idx = tid + 256*r;
            int row = idx >> 3, fc = idx & 7;
            int gj = j0v + row;
            int sz = gj < NS ? 16 : 0;
            const float* src = sz ? &g_kall[(size_t)gj*DD + k0 + fc*4] : g_kall;
            cpa16(sb + (uint32_t)(9216 + p*4608 + row*36 + fc*4)*4u, src, sz);
        }
    };

    float mr[2][2] = {{-1e30f,-1e30f},{-1e30f,-1e30f}};
    float zr[2][2] = {{0.f,0.f},{0.f,0.f}};
    int jt0 = split*JPT;
    int jt1 = jt0 + JPT; if (jt1 > NJT) jt1 = NJT;
    int cg = 0;
    fillQ(0, 0); fillK(0, jt0*128, 0); CPA_COMMIT();
    for (int jt = jt0; jt < jt1; jt++) {
        int j0 = jt*128;
        float acc[2][8][4] = {};
        for (int c = 0; c < 16; c++, cg++) {
            CPA_WAIT0();
            __syncthreads();
            int p = cg & 1;
            if (c < 15) {
                fillQ(p^1, (c+1)*32); fillK(p^1, j0, (c+1)*32); CPA_COMMIT();
            } else if (jt + 1 < jt1) {
                fillQ(p^1, 0); fillK(p^1, (jt+1)*128, 0); CPA_COMMIT();
            }
            #pragma unroll
            for (int kk = 0; kk < 32; kk += 8) {
                uint32_t a[2][4];
                #pragma unroll
                for (int mi = 0; mi < 2; mi++) {
                    a[mi][0] = ftf(QS(p, wm+mi*16+g  , kk+t));
                    a[mi][1] = ftf(QS(p, wm+mi*16+g+8, kk+t));
                    a[mi][2] = ftf(QS(p, wm+mi*16+g  , kk+t+4));
                    a[mi][3] = ftf(QS(p, wm+mi*16+g+8, kk+t+4));
                }
                uint32_t b[8][2];
                #pragma unroll
                for (int ni = 0; ni < 8; ni++) {
                    b[ni][0] = ftf(KS(p, wn+ni*8+g, kk+t));
                    b[ni][1] = ftf(KS(p, wn+ni*8+g, kk+t+4));
                }
                #pragma unroll
                for (int mi = 0; mi < 2; mi++)
                    #pragma unroll
                    for (int ni = 0; ni < 8; ni++)
                        mma8(acc[mi][ni], a[mi][0], a[mi][1], a[mi][2], a[mi][3],
                             b[ni][0], b[ni][1]);
            }
            __syncthreads();
        }
        // epilogue: scale, mask, (optional l69 store), online softmax update
        int doL = (split == 0 && jt == 0);
        #pragma unroll
        for (int mi = 0; mi < 2; mi++) {
            int r0g = i0 + wm + mi*16 + g, r1g = r0g + 8;
            float lm0 = -1e30f, lm1 = -1e30f;
            #pragma unroll
            for (int ni = 0; ni < 8; ni++) {
                int base = j0 + wn + ni*8 + 2*t;
                float v0 = (base   < NS) ? acc[mi][ni][0]*sc : -1e30f;
                float v1 = (base+1 < NS) ? acc[mi][ni][1]*sc : -1e30f;
                float v2 = (base   < NS) ? acc[mi][ni][2]*sc : -1e30f;
                float v3 = (base+1 < NS) ? acc[mi][ni][3]*sc : -1e30f;
                acc[mi][ni][0] = v0; acc[mi][ni][1] = v1;
                acc[mi][ni][2] = v2; acc[mi][ni][3] = v3;
                if (doL) {
                    int c0 = wn + ni*8 + 2*t;
                    if (c0 < TC) {
                        g_l69[(size_t)r0g*TC + c0] = v0;
                        g_l69[(size_t)r1g*TC + c0] = v2;
                    }
                    if (c0 + 1 < TC) {
                        g_l69[(size_t)r0g*TC + c0+1] = v1;
                        g_l69[(size_t)r1g*TC + c0+1] = v3;
                    }
                }
                lm0 = fmaxf(lm0, fmaxf(v0, v1));
                lm1 = fmaxf(lm1, fmaxf(v2, v3));
            }
            lm0 = fmaxf(lm0, __shfl_xor_sync(0xffffffffu, lm0, 1));
            lm0 = fmaxf(lm0, __shfl_xor_sync(0xffffffffu, lm0, 2));
            lm1 = fmaxf(lm1, __shfl_xor_sync(0xffffffffu, lm1, 1));
            lm1 = fmaxf(lm1, __shfl_xor_sync(0xffffffffu, lm1, 2));
            float nm0 = fmaxf(mr[mi][0], lm0), nm1 = fmaxf(mr[mi][1], lm1);
            float p0 = 0.f, p1 = 0.f;
            #pragma unroll
            for (int ni = 0; ni < 8; ni++) {
                p0 += __expf(acc[mi][ni][0]-nm0) + __expf(acc[mi][ni][1]-nm0);
                p1 += __expf(acc[mi][ni][2]-nm1) + __expf(acc[mi][ni][3]-nm1);
            }
            p0 += __shfl_xor_sync(0xffffffffu, p0, 1);
            p0 += __shfl_xor_sync(0xffffffffu, p0, 2);
            p1 += __shfl_xor_sync(0xffffffffu, p1, 1);
            p1 += __shfl_xor_sync(0xffffffffu, p1, 2);
            zr[mi][0] = zr[mi][0]*__expf(mr[mi][0] - nm0) + p0; mr[mi][0] = nm0;
            zr[mi][1] = zr[mi][1]*__expf(mr[mi][1] - nm1) + p1; mr[mi][1] = nm1;
        }
    }
    // merge the two column-half partials per row, then write
    if (t == 0) {
        #pragma unroll
        for (int mi = 0; mi < 2; mi++) {
            int r = wm + mi*16 + g;
            sm_m[half][r]     = mr[mi][0];  sm_z[half][r]     = zr[mi][0];
            sm_m[half][r + 8] = mr[mi][1];  sm_z[half][r + 8] = zr[mi][1];
        }
    }
    __syncthreads();
    if (tid < 128) {
        float m0 = sm_m[0][tid], m1 = sm_m[1][tid];
        float m = fmaxf(m0, m1);
        float z = sm_z[0][tid]*__expf(m0 - m) + sm_z[1][tid]*__expf(m1 - m);
        g_mp[split*BN + i0 + tid] = m;
        g_zp[split*BN + i0 + tid] = z;
    }
}

// ---------------- combine splits + first-69 softmax -> cf (padded) --------
__global__ void k_cf() {
    int i = blockIdx.x;
    int j = threadIdx.x;          // 96 threads
    __shared__ float sh[2];
    if (j == 0) {
        float m = -1e30f;
        #pragma unroll
        for (int s = 0; s < NSPL; s++) m = fmaxf(m, g_mp[s*BN + i]);
        float z = 0.f;
        #pragma unroll
        for (int s = 0; s < NSPL; s++) z += g_zp[s*BN + i]*__expf(g_mp[s*BN + i] - m);
        sh[0] = m; sh[1] = 1.f/z;
    }
    __syncthreads();
    if (j < CFLD)
        g_cf[i*CFLD + j] = (j < TC) ? __expf(g_l69[i*TC + j] - sh[0]) * sh[1] : 0.f;
}

// ---------------- GNN tc-rows partial: C69 += cf^T @ hw_x ----------------
__global__ void k_outtc() {
    __shared__ float cfs[64][72];
    __shared__ float hws[64][64];
    int t = threadIdx.x, tx = t & 63, ty = t >> 6;
    int n0 = blockIdx.x*64;
    int b0 = blockIdx.y*256;
    float acc[18];
    #pragma unroll
    for (int k = 0; k < 18; k++) acc[k] = 0.f;
    for (int bc = 0; bc < 256; bc += 64) {
        int bb = b0 + bc;
        for (int i = t; i < 64*TC; i += 256) {
            int r = i/TC, k = i%TC;
            cfs[r][k] = g_cf[(size_t)(bb+r)*CFLD + k];
        }
        for (int i = t; i < 64*64; i += 256) {
            int r = i >> 6, n = i & 63;
            hws[r][n] = g_hw[(size_t)(TC+bb+r)*DD + n0 + n];
        }
        __syncthreads();
        for (int r = 0; r < 64; r++) {
            float hv = hws[r][tx];
            #pragma unroll
            for (int k = 0; k < 18; k++) {
                int m = ty + 4*k;
                if (m < TC) acc[k] += cfs[r][m]*hv;
            }
        }
        __syncthreads();
    }
    #pragma unroll
    for (int k = 0; k < 18; k++) {
        int m = ty + 4*k;
        if (m < TC) atomicAdd(&g_C69[m*DD + n0 + tx], acc[k]);
    }
}

// ---------------- finalize tc rows (layer 0 only) ----------------
__global__ void k_fintc(const float* __restrict__ gb) {
    int m = blockIdx.x;      // 69
    int n = threadIdx.x;     // 512
    float v = g_C69[m*DD + n];
    for (int j = 0; j < TC; j++)
        v += g_adj[m*TC+j] * g_hw[j*DD + n];
    v += gb[n];
    g_hB[m*DD + n] = fmaxf(v, 0.f);
}

// ---------------- labels ----------------
__global__ void k_labels(const int* __restrict__ lb, float* out, int off, int out_size) {
    int i = blockIdx.x*256 + threadIdx.x;
    if (i < BN && off + i < out_size) out[off + i] = (float)lb[i];
}

// ======================== host ========================
extern "C" void kernel_launch(void* const* d_in, const int* in_sizes, int n_in,
                              void* d_out, int out_size) {
    const float* x    = (const float*)d_in[0];
    const int*   lb   = (const int*)d_in[1];
    const int*   to   = (const int*)d_in[2];
    const float* trep = (const float*)d_in[3];
    const float* cpro = (const float*)d_in[4];
    const float* tw   = (const float*)d_in[5];
    const float* tb   = (const float*)d_in[6];
    const float* cw   = (const float*)d_in[7];
    const float* cb   = (const float*)d_in[8];
    const float* wq   = (const float*)d_in[9];
    const float* wk   = (const float*)d_in[10];
    const float* gw   = (const float*)d_in[11];
    const float* gb   = (const float*)d_in[12];
    const float* bw   = (const float*)d_in[13];
    const float* bb   = (const float*)d_in[14];
    const float* tcw  = (const float*)d_in[15];
    float* out = (float*)d_out;

    cudaFuncSetAttribute(k_gemm3, cudaFuncAttributeMaxDynamicSharedMemorySize, GEMM_SMEM);
    cudaFuncSetAttribute(k_attn3, cudaFuncAttributeMaxDynamicSharedMemorySize, ATTN_SMEM);

    int y_off = (out_size > BN*NC) ? 1 : 0;
    int lbl_off = y_off + BN*NC;

    // 1. xm + src x-rows; prep (zero sums/counts/C69, pad base_w)
    k_xm<<<16384, 128>>>(x);
    k_prep<<<(DD*CFLD + 255)/256, 256>>>(bw);
    // 2. segment means -> t1/c1
    k_count<<<16, 256>>>(to, lb);
    k_segsum<<<dim3(8, 64), 256>>>(to, lb);
    k_t1c1<<<(TC*DD + 255)/256, 256>>>(trep, cpro);
    // 3. graphs
    k_d2cross<<<65, 128>>>();
    k_tg<<<16, 32>>>(tw, tb);
    k_cg<<<dim3(65, 65), 32>>>(cw, cb);
    if (y_off) k_ae<<<1, 65>>>(out);
    // 4. fused projections: y<32 -> q = xm@wq, y>=32 -> kall = hA@wk
    k_gemm3<<<dim3(4, 65), 256, GEMM_SMEM>>>(0, 0, wq, 0, BN, DD, DD, DD, DD, DD,
                                             nullptr, 0, nullptr, nullptr, nullptr,
                                             32, 1, wk, 1, NS);
    // 5. attention stats (+ first-69 logits) + cross_feat
    k_attn3<<<dim3(32, NSPL), 256, ATTN_SMEM>>>();
    k_cf<<<4096, 96>>>();
    // 6. GNN layer 0: hA -> hB  (hw = hA@gw1 full; x-rows + tc-rows)
    k_gemm3<<<dim3(4, 33), 256, GEMM_SMEM>>>(1, 0, gw, 2, NS, DD, DD, DD, DD, DD,
                                             nullptr, 0, nullptr, nullptr, nullptr,
                                             0, 0, nullptr, 0, 0);
    k_gemm3<<<dim3(4, 32), 256, GEMM_SMEM>>>(3, 1, nullptr, 3, BN, DD, CFLD, CFLD, DD, DD,
                                             gb, 1, nullptr, nullptr, nullptr,
                                             0, 0, nullptr, 0, 0);
    k_outtc<<<dim3(8, 16), 256>>>();
    k_fintc<<<69, 512>>>(gb);
    // 7. GNN layer 1: hB -> hA x-rows only (hw rows 0..127 suffice; tc-rows dead)
    k_gemm3<<<dim3(4, 1), 256, GEMM_SMEM>>>(2, 0, gw + DD*DD, 2, 128, DD, DD, DD, DD, DD,
                                            nullptr, 0, nullptr, nullptr, nullptr,
                                            0, 0, nullptr, 0, 0);
    k_gemm3<<<dim3(4, 32), 256, GEMM_SMEM>>>(3, 1, nullptr, 4, BN, DD, CFLD, CFLD, DD, DD,
                                             gb + DD, 1, nullptr, nullptr, nullptr,
                                             0, 0, nullptr, 0, 0);
    // 8. outputs: y = (hA_x @ bwPad + bb) * tcw[to], labels
    k_gemm3<<<dim3(1, 32), 256, GEMM_SMEM>>>(4, 2, nullptr, 0, BN, NC, DD, DD, CFLD, NC,
                                             bb, 0, tcw, to, out + y_off,
                                             0, 0, nullptr, 0, 0);
    k_labels<<<16, 256>>>(lb, out, lbl_off, out_size);
}

// round 8
// speedup vs baseline: 5.0399x; 1.0084x over previous
#include <cuda_runtime.h>
#include <math.h>
#include <stdint.h>

#define BN 4096
#define DD 512
#define NT 4
#define NC 65
#define TC 69          // NT + NC
#define NS 4165        // TC + BN
#define CFLD 72        // padded cf row stride
#define NSPL 9         // attention splits
#define NJT 33
#define JPT 4

// ---------------- scratch (device globals; no allocations) ----------------
__device__ float g_xm[BN*DD];
__device__ float g_q[BN*DD];
__device__ float g_kall[NS*DD];
__device__ float g_hA[NS*DD];
__device__ float g_hB[NS*DD];
__device__ float g_hw[NS*DD];
__device__ float g_tsum[NT*DD];
__device__ float g_csum[NC*DD];
__device__ int   g_cntT[NT];
__device__ int   g_cntC[NC];
__device__ float g_adj[TC*TC];
__device__ float g_cross[NT*NC];
__device__ float g_cf[BN*CFLD];
__device__ float g_l69[BN*TC];
__device__ float g_mp[16*BN];
__device__ float g_zp[16*BN];
__device__ float g_C69[TC*DD];
__device__ float g_bwPad[DD*CFLD];

// ---------------- tf32 / mma / cp.async helpers ----------------
__device__ __forceinline__ void mma8(float* c, uint32_t a0, uint32_t a1,
                                     uint32_t a2, uint32_t a3,
                                     uint32_t b0, uint32_t b1) {
    asm("mma.sync.aligned.m16n8k8.row.col.f32.tf32.tf32.f32 "
        "{%0,%1,%2,%3},{%4,%5,%6,%7},{%8,%9},{%0,%1,%2,%3};"
        : "+f"(c[0]), "+f"(c[1]), "+f"(c[2]), "+f"(c[3])
        : "r"(a0), "r"(a1), "r"(a2), "r"(a3), "r"(b0), "r"(b1));
}
__device__ __forceinline__ uint32_t ftf(float x) {
    uint32_t u;
    asm("cvt.rna.tf32.f32 %0, %1;" : "=r"(u) : "f"(x));
    return u;
}
__device__ __forceinline__ void cpa16(uint32_t dst, const float* src, int srcBytes) {
    asm volatile("cp.async.cg.shared.global [%0], [%1], 16, %2;"
                 :: "r"(dst), "l"(src), "r"(srcBytes));
}
#define CPA_COMMIT() asm volatile("cp.async.commit_group;" ::: "memory")
#define CPA_WAIT0()  asm volatile("cp.async.wait_group 0;" ::: "memory")

// ---------------- selectors ----------------
__device__ __forceinline__ const float* selA3(int s) {
    switch (s) {
        case 0: return g_xm;  case 1: return g_hA;  case 2: return g_hB;
        case 3: return g_cf;  case 4: return g_hA + TC*DD;
    }
    return g_xm;
}
__device__ __forceinline__ const float* selB3(int s, const float* Bp) {
    switch (s) { case 1: return g_hw; case 2: return g_bwPad; }
    return Bp;
}
__device__ __forceinline__ float* selC3(int s) {
    switch (s) {
        case 0: return g_q;  case 1: return g_kall;  case 2: return g_hw;
        case 3: return g_hB + TC*DD;  case 4: return g_hA + TC*DD;
    }
    return g_q;
}

// ---------------- xm = mean over 7x7; also write src rows 69.. -------------
__global__ void k_xm(const float* __restrict__ x) {
    __shared__ float buf[4][32*49];
    int w = threadIdx.x >> 5, lane = threadIdx.x & 31;
    int base = (blockIdx.x*4 + w) * 32;
    const float* src = x + (size_t)base*49;
    float* b = buf[w];
    #pragma unroll
    for (int t = 0; t < 49; t++) b[lane + 32*t] = src[lane + 32*t];
    __syncwarp();
    float s = 0.f;
    #pragma unroll
    for (int t = 0; t < 49; t++) s += b[lane*49 + t];
    s *= (1.f/49.f);
    int seg = base + lane;
    g_xm[seg] = s;
    g_hA[TC*DD + seg] = s;
}

// ---------------- prep: zero seg sums/counts/C69, pad base_w ----------------
__global__ void k_prep(const float* __restrict__ bw) {
    int i = blockIdx.x*256 + threadIdx.x;
    if (i < NT*DD) g_tsum[i] = 0.f;
    if (i < NC*DD) g_csum[i] = 0.f;
    if (i < NT) g_cntT[i] = 0;
    if (i < NC) g_cntC[i] = 0;
    if (i < TC*DD) g_C69[i] = 0.f;
    if (i < DD*CFLD) {
        int r = i / CFLD, c = i - r*CFLD;
        g_bwPad[i] = (c < NC) ? bw[r*NC + c] : 0.f;
    }
}
__global__ void k_count(const int* __restrict__ to, const int* __restrict__ lb) {
    int i = blockIdx.x*256 + threadIdx.x;
    if (i < BN) { atomicAdd(&g_cntT[to[i]], 1); atomicAdd(&g_cntC[lb[i]], 1); }
}
__global__ void k_segsum(const int* __restrict__ to, const int* __restrict__ lb) {
    __shared__ float sT[NT][64];
    __shared__ float sC[NC][64];
    int t = threadIdx.x;
    int cr = t & 63, rr = t >> 6;
    int r0 = blockIdx.y * 64, c0 = blockIdx.x * 64;
    for (int i = t; i < NT*64; i += 256) ((float*)sT)[i] = 0.f;
    for (int i = t; i < NC*64; i += 256) ((float*)sC)[i] = 0.f;
    __syncthreads();
    for (int r = r0 + rr; r < r0 + 64; r += 4) {
        int tt = to[r], cc = lb[r];
        float v = g_xm[r*DD + c0 + cr];
        atomicAdd(&sT[tt][cr], v);
        atomicAdd(&sC[cc][cr], v);
    }
    __syncthreads();
    for (int i = t; i < NT*64; i += 256)
        atomicAdd(&g_tsum[(i>>6)*DD + c0 + (i&63)], ((float*)sT)[i]);
    for (int i = t; i < NC*64; i += 256)
        atomicAdd(&g_csum[(i>>6)*DD + c0 + (i&63)], ((float*)sC)[i]);
}
__global__ void k_t1c1(const float* __restrict__ trep, const float* __restrict__ cpro) {
    int i = blockIdx.x*256 + threadIdx.x;
    if (i >= TC*DD) return;
    int seg = i / DD, d = i % DD;
    float v;
    if (seg < NT) {
        float cnt = fmaxf((float)g_cntT[seg], 1.f);
        v = 0.9f*trep[i] + 0.1f*g_tsum[i]/cnt;
    } else {
        int c = seg - NT;
        float cnt = fmaxf((float)g_cntC[c], 1.f);
        v = 0.9f*cpro[c*DD+d] + 0.1f*g_csum[c*DD+d]/cnt;
    }
    g_hA[i] = v;
}

// ---------------- graph kernels ----------------
__global__ void k_d2cross() {
    int c = blockIdx.x;
    int w = threadIdx.x >> 5, lane = threadIdx.x & 31;
    __shared__ float sd2[NT];
    const float* t1 = g_hA;
    const float* c1 = g_hA + NT*DD;
    float s = 0.f;
    for (int d = lane; d < DD; d += 32) {
        float df = t1[w*DD+d] - c1[c*DD+d];
        s += df*df;
    }
    #pragma unroll
    for (int o = 16; o; o >>= 1) s += __shfl_xor_sync(0xffffffffu, s, o);
    if (lane == 0) sd2[w] = s;
    __syncthreads();
    if (threadIdx.x == 0) {
        float l[NT], mx = -1e30f;
        for (int t = 0; t < NT; t++) { l[t] = -sd2[t]*(1.f/16.f); mx = fmaxf(mx, l[t]); }
        float Z = 0.f;
        for (int t = 0; t < NT; t++) { l[t] = expf(l[t]-mx); Z += l[t]; }
        for (int t = 0; t < NT; t++) {
            float p = l[t]/Z;
            g_cross[t*NC + c] = p;
            g_adj[t*TC + NT + c] = p;
            g_adj[(NT+c)*TC + t] = p;
        }
    }
}
__global__ void k_tg(const float* __restrict__ tw, const float* __restrict__ tb) {
    int i = blockIdx.x >> 2, j = blockIdx.x & 3;
    int lane = threadIdx.x;
    const float* t1 = g_hA;
    float s = 0.f;
    for (int d = lane; d < DD; d += 32)
        s += fabsf(t1[i*DD+d]-t1[j*DD+d]) * tw[d];
    #pragma unroll
    for (int o = 16; o; o >>= 1) s += __shfl_xor_sync(0xffffffffu, s, o);
    if (lane == 0) {
        float v = 1.f/(1.f+expf(-(s + tb[0])));
        if (i == j) v = 0.f;
        g_adj[i*TC+j] = v;
    }
}
__global__ void k_cg(const float* __restrict__ cw, const float* __restrict__ cb) {
    int i = blockIdx.x;
    int w = threadIdx.x >> 5, lane = threadIdx.x & 31;
    int j = blockIdx.y*4 + w;
    if (j >= NC) return;
    const float* c1 = g_hA + NT*DD;
    float s = 0.f;
    for (int d = lane; d < DD; d += 32)
        s += fabsf(c1[i*DD+d]-c1[j*DD+d]) * cw[d];
    #pragma unroll
    for (int o = 16; o; o >>= 1) s += __shfl_xor_sync(0xffffffffu, s, o);
    if (lane == 0) {
        float v = 1.f/(1.f+expf(-(s + cb[0])));
        if (i == j) v = 0.f;
        g_adj[(NT+i)*TC + NT+j] = v;
    }
}
__global__ void k_ae(float* out) {
    __shared__ float s[NC];
    int c = threadIdx.x;
    float a = 0.f;
    for (int t = 0; t < NT; t++) { float p = g_cross[t*NC+c]; a += p*logf(p); }
    s[c] = a;
    __syncthreads();
    if (c == 0) { float r = 0.f; for (int i = 0; i < NC; i++) r += s[i]; out[0] = r/(float)NC; }
}

// ---------------- tf32 GEMM (cp.async double-buffered, 1 barrier/chunk) ----
// C = A(MxK,row) @ B(KxN,row). Block 128x128, 8 warps (4m x 2n), warp 32x64.
// Up to 3 configs per launch via ySplit/ySplit2 (blockIdx.y segmented).
#define GEMM_SMEM ((2*128*36 + 2*32*136)*4)
#define AS(p,r,c) smp[(p)*4608 + (r)*36 + (c)]
#define BS(p,r,c) smp[9216 + (p)*4352 + (r)*136 + (c)]
__global__ void __launch_bounds__(256, 2) k_gemm3(
        int aSel, int bSel, const float* __restrict__ Bp, int cSel,
        int M, int N, int K, int lda, int ldb, int ldc,
        const float* __restrict__ bias, int relu,
        const float* __restrict__ tcw, const int* __restrict__ to,
        float* yout,
        int ySplit, int aSel2, const float* __restrict__ Bp2, int cSel2, int M2,
        int ySplit2, int aSel3, const float* __restrict__ Bp3, int cSel3, int M3) {
    extern __shared__ float smp[];
    int by = blockIdx.y;
    if (ySplit2 > 0 && by >= ySplit2) {
        aSel = aSel3; Bp = Bp3; cSel = cSel3; M = M3; by -= ySplit2;
    } else if (ySplit > 0 && by >= ySplit) {
        aSel = aSel2; Bp = Bp2; cSel = cSel2; M = M2; by -= ySplit;
    }
    const float* A = selA3(aSel);
    const float* B = selB3(bSel, Bp);
    float* C = yout ? yout : selC3(cSel);
    int tid = threadIdx.x;
    int w = tid >> 5, lane = tid & 31, g = lane >> 2, t = lane & 3;
    int wm = (w & 3) * 32, wn = (w >> 2) * 64;
    int m0 = by*128, n0 = blockIdx.x*128;
    uint32_t sb = (uint32_t)__cvta_generic_to_shared(smp);

    auto fillA = [&](int p, int k0) {
        #pragma unroll
        for (int r = 0; r < 4; r++) {
            int idx = tid + 256*r;
            int row = idx >> 3, fc = idx & 7;
            int gm = m0 + row, gk = k0 + fc*4;
            int sz = 16;
            if (gm >= M) sz = 0;
            int rem = (K - gk)*4;
            if (rem < sz) sz = rem < 0 ? 0 : rem;
            const float* src = sz > 0 ? &A[(size_t)gm*lda + gk] : A;
            cpa16(sb + (uint32_t)(p*4608 + row*36 + fc*4)*4u, src, sz);
        }
    };
    auto fillB = [&](int p, int k0) {
        #pragma unroll
        for (int r = 0; r < 4; r++) {
            int idx = tid + 256*r;
            int row = idx >> 5, c4 = (idx & 31)*4;
            int gk = k0 + row, gn = n0 + c4;
            int sz = 16;
            if (gk >= K) sz = 0;
            int rem = (N - gn)*4;
            if (rem < sz) sz = rem < 0 ? 0 : rem;
            const float* src = sz > 0 ? &B[(size_t)gk*ldb + gn] : B;
            cpa16(sb + (uint32_t)(9216 + p*4352 + row*136 + c4)*4u, src, sz);
        }
    };

    float acc[2][8][4] = {};
    int nk = (K + 31) >> 5;
    fillA(0, 0); fillB(0, 0); CPA_COMMIT();
    for (int kc = 0; kc < nk; kc++) {
        CPA_WAIT0();
        __syncthreads();   // all compute(kc-1) done (program order) + data visible
        if (kc + 1 < nk) { fillA((kc+1)&1, (kc+1)*32); fillB((kc+1)&1, (kc+1)*32); CPA_COMMIT(); }
        int p = kc & 1;
        #pragma unroll
        for (int kk = 0; kk < 32; kk += 8) {
            uint32_t a[2][4];
            #pragma unroll
            for (int mi = 0; mi < 2; mi++) {
                a[mi][0] = ftf(AS(p, wm+mi*16+g  , kk+t));
                a[mi][1] = ftf(AS(p, wm+mi*16+g+8, kk+t));
                a[mi][2] = ftf(AS(p, wm+mi*16+g  , kk+t+4));
                a[mi][3] = ftf(AS(p, wm+mi*16+g+8, kk+t+4));
            }
            uint32_t b[8][2];
            #pragma unroll
            for (int ni = 0; ni < 8; ni++) {
                b[ni][0] = ftf(BS(p, kk+t  , wn+ni*8+g));
                b[ni][1] = ftf(BS(p, kk+t+4, wn+ni*8+g));
            }
            #pragma unroll
            for (int mi = 0; mi < 2; mi++)
                #pragma unroll
                for (int ni = 0; ni < 8; ni++)
                    mma8(acc[mi][ni], a[mi][0], a[mi][1], a[mi][2], a[mi][3],
                         b[ni][0], b[ni][1]);
        }
    }
    #pragma unroll
    for (int mi = 0; mi < 2; mi++) {
        int r0 = m0 + wm + mi*16 + g, r1 = r0 + 8;
        #pragma unroll
        for (int ni = 0; ni < 8; ni++) {
            int n = n0 + wn + ni*8 + 2*t;
            float bv0 = 0.f, bv1 = 0.f;
            if (bias) { if (n < N) bv0 = bias[n]; if (n+1 < N) bv1 = bias[n+1]; }
            float v00 = acc[mi][ni][0] + bv0, v01 = acc[mi][ni][1] + bv1;
            float v10 = acc[mi][ni][2] + bv0, v11 = acc[mi][ni][3] + bv1;
            if (relu) {
                v00 = fmaxf(v00, 0.f); v01 = fmaxf(v01, 0.f);
                v10 = fmaxf(v10, 0.f); v11 = fmaxf(v11, 0.f);
            }
            if (yout) {
                if (r0 < M) {
                    if (n < N)   C[(size_t)r0*ldc + n]   = tcw[to[r0]*NC + n]   * v00;
                    if (n+1 < N) C[(size_t)r0*ldc + n+1] = tcw[to[r0]*NC + n+1] * v01;
                }
                if (r1 < M) {
                    if (n < N)   C[(size_t)r1*ldc + n]   = tcw[to[r1]*NC + n]   * v10;
                    if (n+1 < N) C[(size_t)r1*ldc + n+1] = tcw[to[r1]*NC + n+1] * v11;
                }
            } else {
                if (r0 < M) {
                    if (n < N)   C[(size_t)r0*ldc + n]   = v00;
                    if (n+1 < N) C[(size_t)r0*ldc + n+1] = v01;
                }
                if (r1 < M) {
                    if (n < N)   C[(size_t)r1*ldc + n]   = v10;
                    if (n+1 < N) C[(size_t)r1*ldc + n+1] = v11;
                }
            }
        }
    }
}

// ---------------- attention (cp.async, 1 barrier/chunk, streaming softmax) --
// grid (32 row-blocks, NSPL splits). Block 128 q x 128 keys, warp 32x64.
// split 0 / jt 0 additionally stores the first-69 (scaled) logits to g_l69.
#define ATTN_SMEM ((2*128*36*2)*4)
#define QS(p,r,c) smp[(p)*4608 + (r)*36 + (c)]
#define KS(p,r,c) smp[9216 + (p)*4608 + (r)*36 + (c)]
__global__ void __launch_bounds__(256, 2) k_attn3() {
    extern __shared__ float smp[];
    __shared__ float sm_m[2][128];
    __shared__ float sm_z[2][128];
    int tid = threadIdx.x;
    int w = tid >> 5, lane = tid & 31, g = lane >> 2, t = lane & 3;
    int wm = (w & 3) * 32, wn = (w >> 2) * 64;
    int half = w >> 2;
    int i0 = blockIdx.x*128;
    int split = blockIdx.y;
    const float sc = 0.044194173824159216f;   // 1/sqrt(512)
    uint32_t sb = (uint32_t)__cvta_generic_to_shared(smp);

    auto fillQ = [&](int p, int k0) {
        #pragma unroll
        for (int r = 0; r < 4; r++) {
            int idx = tid + 256*r;
            int row = idx >> 3, fc = idx & 7;
            cpa16(sb + (uint32_t)(p*4608 + row*36 + fc*4)*4u,
                  &g_q[(size_t)(i0+row)*DD + k0 + fc*4], 16);
        }
    };
    auto fillK = [&](int p, int j0v, int k0) {
        #pragma unroll
        for (int r = 0; r < 4; r++) {
            int idx = tid + 256*r;
            int row = idx >> 3, fc = idx & 7;
            int gj = j0v + row;
            int sz = gj < NS ? 16 : 0;
            const float* src = sz ? &g_kall[(size_t)gj*DD + k0 + fc*4] : g_kall;
            cpa16(sb + (uint32_t)(9216 + p*4608 + row*36 + fc*4)*4u, src, sz);
        }
    };

    float mr[2][2] = {{-1e30f,-1e30f},{-1e30f,-1e30f}};
    float zr[2][2] = {{0.f,0.f},{0.f,0.f}};
    int jt0 = split*JPT;
    int jt1 = jt0 + JPT; if (jt1 > NJT) jt1 = NJT;
    int cg = 0;
    fillQ(0, 0); fillK(0, jt0*128, 0); CPA_COMMIT();
    for (int jt = jt0; jt < jt1; jt++) {
        int j0 = jt*128;
        float acc[2][8][4] = {};
        for (int c = 0; c < 16; c++, cg++) {
            CPA_WAIT0();
            __syncthreads();   // single barrier per chunk
            int p = cg & 1;
            if (c < 15) {
                fillQ(p^1, (c+1)*32); fillK(p^1, j0, (c+1)*32); CPA_COMMIT();
            } else if (jt + 1 < jt1) {
                fillQ(p^1, 0); fillK(p^1, (jt+1)*128, 0); CPA_COMMIT();
            }
            #pragma unroll
            for (int kk = 0; kk < 32; kk += 8) {
                uint32_t a[2][4];
                #pragma unroll
                for (int mi = 0; mi < 2; mi++) {
                    a[mi][0] = ftf(QS(p, wm+mi*16+g  , kk+t));
                    a[mi][1] = ftf(QS(p, wm+mi*16+g+8, kk+t));
                    a[mi][2] = ftf(QS(p, wm+mi*16+g  , kk+t+4));
                    a[mi][3] = ftf(QS(p, wm+mi*16+g+8, kk+t+4));
                }
                uint32_t b[8][2];
                #pragma unroll
                for (int ni = 0; ni < 8; ni++) {
                    b[ni][0] = ftf(KS(p, wn+ni*8+g, kk+t));
                    b[ni][1] = ftf(KS(p, wn+ni*8+g, kk+t+4));
                }
                #pragma unroll
                for (int mi = 0; mi < 2; mi++)
                    #pragma unroll
                    for (int ni = 0; ni < 8; ni++)
                        mma8(acc[mi][ni], a[mi][0], a[mi][1], a[mi][2], a[mi][3],
                             b[ni][0], b[ni][1]);
            }
        }
        // epilogue: scale, mask, (optional l69 store), online softmax update
        int doL = (split == 0 && jt == 0);
        #pragma unroll
        for (int mi = 0; mi < 2; mi++) {
            int r0g = i0 + wm + mi*16 + g, r1g = r0g + 8;
            float lm0 = -1e30f, lm1 = -1e30f;
            #pragma unroll
            for (int ni = 0; ni < 8; ni++) {
                int base = j0 + wn + ni*8 + 2*t;
                float v0 = (base   < NS) ? acc[mi][ni][0]*sc : -1e30f;
                float v1 = (base+1 < NS) ? acc[mi][ni][1]*sc : -1e30f;
                float v2 = (base   < NS) ? acc[mi][ni][2]*sc : -1e30f;
                float v3 = (base+1 < NS) ? acc[mi][ni][3]*sc : -1e30f;
                acc[mi][ni][0] = v0; acc[mi][ni][1] = v1;
                acc[mi][ni][2] = v2; acc[mi][ni][3] = v3;
                if (doL) {
                    int c0 = wn + ni*8 + 2*t;
                    if (c0 < TC) {
                        g_l69[(size_t)r0g*TC + c0] = v0;
                        g_l69[(size_t)r1g*TC + c0] = v2;
                    }
                    if (c0 + 1 < TC) {
                        g_l69[(size_t)r0g*TC + c0+1] = v1;
                        g_l69[(size_t)r1g*TC + c0+1] = v3;
                    }
                }
                lm0 = fmaxf(lm0, fmaxf(v0, v1));
                lm1 = fmaxf(lm1, fmaxf(v2, v3));
            }
            lm0 = fmaxf(lm0, __shfl_xor_sync(0xffffffffu, lm0, 1));
            lm0 = fmaxf(lm0, __shfl_xor_sync(0xffffffffu, lm0, 2));
            lm1 = fmaxf(lm1, __shfl_xor_sync(0xffffffffu, lm1, 1));
            lm1 = fmaxf(lm1, __shfl_xor_sync(0xffffffffu, lm1, 2));
            float nm0 = fmaxf(mr[mi][0], lm0), nm1 = fmaxf(mr[mi][1], lm1);
            float p0 = 0.f, p1 = 0.f;
            #pragma unroll
            for (int ni = 0; ni < 8; ni++) {
                p0 += __expf(acc[mi][ni][0]-nm0) + __expf(acc[mi][ni][1]-nm0);
                p1 += __expf(acc[mi][ni][2]-nm1) + __expf(acc[mi][ni][3]-nm1);
            }
            p0 += __shfl_xor_sync(0xffffffffu, p0, 1);
            p0 += __shfl_xor_sync(0xffffffffu, p0, 2);
            p1 += __shfl_xor_sync(0xffffffffu, p1, 1);
            p1 += __shfl_xor_sync(0xffffffffu, p1, 2);
            zr[mi][0] = zr[mi][0]*__expf(mr[mi][0] - nm0) + p0; mr[mi][0] = nm0;
            zr[mi][1] = zr[mi][1]*__expf(mr[mi][1] - nm1) + p1; mr[mi][1] = nm1;
        }
    }
    // merge the two column-half partials per row, then write
    if (t == 0) {
        #pragma unroll
        for (int mi = 0; mi < 2; mi++) {
            int r = wm + mi*16 + g;
            sm_m[half][r]     = mr[mi][0];  sm_z[half][r]     = zr[mi][0];
            sm_m[half][r + 8] = mr[mi][1];  sm_z[half][r + 8] = zr[mi][1];
        }
    }
    __syncthreads();
    if (tid < 128) {
        float m0 = sm_m[0][tid], m1 = sm_m[1][tid];
        float m = fmaxf(m0, m1);
        float z = sm_z[0][tid]*__expf(m0 - m) + sm_z[1][tid]*__expf(m1 - m);
        g_mp[split*BN + i0 + tid] = m;
        g_zp[split*BN + i0 + tid] = z;
    }
}

// ---------------- combine splits + first-69 softmax -> cf (padded) --------
__global__ void k_cf() {
    int i = blockIdx.x;
    int j = threadIdx.x;          // 96 threads
    __shared__ float sh[2];
    if (j == 0) {
        float m = -1e30f;
        #pragma unroll
        for (int s = 0; s < NSPL; s++) m = fmaxf(m, g_mp[s*BN + i]);
        float z = 0.f;
        #pragma unroll
        for (int s = 0; s < NSPL; s++) z += g_zp[s*BN + i]*__expf(g_mp[s*BN + i] - m);
        sh[0] = m; sh[1] = 1.f/z;
    }
    __syncthreads();
    if (j < CFLD)
        g_cf[i*CFLD + j] = (j < TC) ? __expf(g_l69[i*TC + j] - sh[0]) * sh[1] : 0.f;
}

// ---------------- GNN tc-rows partial: C69 += cf^T @ hw_x ----------------
__global__ void k_outtc() {
    __shared__ float cfs[64][72];
    __shared__ float hws[64][64];
    int t = threadIdx.x, tx = t & 63, ty = t >> 6;
    int n0 = blockIdx.x*64;
    int b0 = blockIdx.y*256;
    float acc[18];
    #pragma unroll
    for (int k = 0; k < 18; k++) acc[k] = 0.f;
    for (int bc = 0; bc < 256; bc += 64) {
        int bb = b0 + bc;
        for (int i = t; i < 64*TC; i += 256) {
            int r = i/TC, k = i%TC;
            cfs[r][k] = g_cf[(size_t)(bb+r)*CFLD + k];
        }
        for (int i = t; i < 64*64; i += 256) {
            int r = i >> 6, n = i & 63;
            hws[r][n] = g_hw[(size_t)(TC+bb+r)*DD + n0 + n];
        }
        __syncthreads();
        for (int r = 0; r < 64; r++) {
            float hv = hws[r][tx];
            #pragma unroll
            for (int k = 0; k < 18; k++) {
                int m = ty + 4*k;
                if (m < TC) acc[k] += cfs[r][m]*hv;
            }
        }
        __syncthreads();
    }
    #pragma unroll
    for (int k = 0; k < 18; k++) {
        int m = ty + 4*k;
        if (m < TC) atomicAdd(&g_C69[m*DD + n0 + tx], acc[k]);
    }
}

// ---------------- finalize tc rows (layer 0 only) ----------------
__global__ void k_fintc(const float* __restrict__ gb) {
    int m = blockIdx.x;      // 69
    int n = threadIdx.x;     // 512
    float v = g_C69[m*DD + n];
    for (int j = 0; j < TC; j++)
        v += g_adj[m*TC+j] * g_hw[j*DD + n];
    v += gb[n];
    g_hB[m*DD + n] = fmaxf(v, 0.f);
}

// ---------------- labels ----------------
__global__ void k_labels(const int* __restrict__ lb, float* out, int off, int out_size) {
    int i = blockIdx.x*256 + threadIdx.x;
    if (i < BN && off + i < out_size) out[off + i] = (float)lb[i];
}

// ======================== host ========================
extern "C" void kernel_launch(void* const* d_in, const int* in_sizes, int n_in,
                              void* d_out, int out_size) {
    const float* x    = (const float*)d_in[0];
    const int*   lb   = (const int*)d_in[1];
    const int*   to   = (const int*)d_in[2];
    const float* trep = (const float*)d_in[3];
    const float* cpro = (const float*)d_in[4];
    const float* tw   = (const float*)d_in[5];
    const float* tb   = (const float*)d_in[6];
    const float* cw   = (const float*)d_in[7];
    const float* cb   = (const float*)d_in[8];
    const float* wq   = (const float*)d_in[9];
    const float* wk   = (const float*)d_in[10];
    const float* gw   = (const float*)d_in[11];
    const float* gb   = (const float*)d_in[12];
    const float* bw   = (const float*)d_in[13];
    const float* bb   = (const float*)d_in[14];
    const float* tcw  = (const float*)d_in[15];
    float* out = (float*)d_out;

    cudaFuncSetAttribute(k_gemm3, cudaFuncAttributeMaxDynamicSharedMemorySize, GEMM_SMEM);
    cudaFuncSetAttribute(k_attn3, cudaFuncAttributeMaxDynamicSharedMemorySize, ATTN_SMEM);

    int y_off = (out_size > BN*NC) ? 1 : 0;
    int lbl_off = y_off + BN*NC;

    // 1. xm + src x-rows; prep (zero sums/counts/C69, pad base_w)
    k_xm<<<16384, 128>>>(x);
    k_prep<<<(DD*CFLD + 255)/256, 256>>>(bw);
    // 2. segment means -> t1/c1
    k_count<<<16, 256>>>(to, lb);
    k_segsum<<<dim3(8, 64), 256>>>(to, lb);
    k_t1c1<<<(TC*DD + 255)/256, 256>>>(trep, cpro);
    // 3. graphs
    k_d2cross<<<65, 128>>>();
    k_tg<<<16, 32>>>(tw, tb);
    k_cg<<<dim3(65, 17), 128>>>(cw, cb);
    if (y_off) k_ae<<<1, 65>>>(out);
    // 4. fused: y<32 q=xm@wq | 32..64 kall=hA@wk | 65..97 hw=hA@gw1
    k_gemm3<<<dim3(4, 98), 256, GEMM_SMEM>>>(0, 0, wq, 0, BN, DD, DD, DD, DD, DD,
                                             nullptr, 0, nullptr, nullptr, nullptr,
                                             32, 1, wk, 1, NS,
                                             65, 1, gw, 2, NS);
    // 5. attention stats (+ first-69 logits) + cross_feat
    k_attn3<<<dim3(32, NSPL), 256, ATTN_SMEM>>>();
    k_cf<<<4096, 96>>>();
    // 6. GNN layer 0 outputs: x-rows = relu(cf@hw_tc + gb0); tc-rows via outtc/fintc
    k_gemm3<<<dim3(4, 32), 256, GEMM_SMEM>>>(3, 1, nullptr, 3, BN, DD, CFLD, CFLD, DD, DD,
                                             gb, 1, nullptr, nullptr, nullptr,
                                             0, 0, nullptr, 0, 0, 0, 0, nullptr, 0, 0);
    k_outtc<<<dim3(8, 16), 256>>>();
    k_fintc<<<69, 512>>>(gb);
    // 7. GNN layer 1: hw rows 0..127 only (tc-row outputs are dead)
    k_gemm3<<<dim3(4, 1), 256, GEMM_SMEM>>>(2, 0, gw + DD*DD, 2, 128, DD, DD, DD, DD, DD,
                                            nullptr, 0, nullptr, nullptr, nullptr,
                                            0, 0, nullptr, 0, 0, 0, 0, nullptr, 0, 0);
    k_gemm3<<<dim3(4, 32), 256, GEMM_SMEM>>>(3, 1, nullptr, 4, BN, DD, CFLD, CFLD, DD, DD,
                                             gb + DD, 1, nullptr, nullptr, nullptr,
                                             0, 0, nullptr, 0, 0, 0, 0, nullptr, 0, 0);
    // 8. outputs: y = (hA_x @ bwPad + bb) * tcw[to], labels
    k_gemm3<<<dim3(1, 32), 256, GEMM_SMEM>>>(4, 2, nullptr, 0, BN, NC, DD, DD, CFLD, NC,
                                             bb, 0, tcw, to, out + y_off,
                                             0, 0, nullptr, 0, 0, 0, 0, nullptr, 0, 0);
    k_labels<<<16, 256>>>(lb, out, lbl_off, out_size);
}

// round 9
// speedup vs baseline: 5.1294x; 1.0178x over previous
#include <cuda_runtime.h>
#include <math.h>
#include <stdint.h>

#define BN 4096
#define DD 512
#define NT 4
#define NC 65
#define TC 69          // NT + NC
#define NS 4165        // TC + BN
#define CFLD 72        // padded cf row stride
#define NSPL 9         // attention splits
#define NJT 33
#define JPT 4

// ---------------- scratch (device globals; no allocations) ----------------
__device__ float g_xm[BN*DD];
__device__ float g_q[BN*DD];
__device__ float g_kall[NS*DD];
__device__ float g_hA[NS*DD];
__device__ float g_hB[NS*DD];
__device__ float g_hw[NS*DD];
__device__ float g_tsum[NT*DD];
__device__ float g_csum[NC*DD];
__device__ int   g_cntT[NT];
__device__ int   g_cntC[NC];
__device__ float g_adj[TC*TC];
__device__ float g_cross[NT*NC];
__device__ float g_cf[BN*CFLD];
__device__ float g_l69[BN*TC];
__device__ float g_mp[16*BN];
__device__ float g_zp[16*BN];
__device__ float g_C69[TC*DD];
__device__ float g_bwPad[DD*CFLD];

// ---------------- static stream/event resources (created pre-checkpoint) ---
static cudaStream_t g_s1;
static cudaEvent_t g_e1, g_e2, g_e3;
static struct StreamInit {
    StreamInit() {
        cudaStreamCreateWithFlags(&g_s1, cudaStreamNonBlocking);
        cudaEventCreateWithFlags(&g_e1, cudaEventDisableTiming);
        cudaEventCreateWithFlags(&g_e2, cudaEventDisableTiming);
        cudaEventCreateWithFlags(&g_e3, cudaEventDisableTiming);
    }
} g_si;

// ---------------- tf32 / mma / cp.async helpers ----------------
__device__ __forceinline__ void mma8(float* c, uint32_t a0, uint32_t a1,
                                     uint32_t a2, uint32_t a3,
                                     uint32_t b0, uint32_t b1) {
    asm("mma.sync.aligned.m16n8k8.row.col.f32.tf32.tf32.f32 "
        "{%0,%1,%2,%3},{%4,%5,%6,%7},{%8,%9},{%0,%1,%2,%3};"
        : "+f"(c[0]), "+f"(c[1]), "+f"(c[2]), "+f"(c[3])
        : "r"(a0), "r"(a1), "r"(a2), "r"(a3), "r"(b0), "r"(b1));
}
__device__ __forceinline__ uint32_t ftf(float x) {
    uint32_t u;
    asm("cvt.rna.tf32.f32 %0, %1;" : "=r"(u) : "f"(x));
    return u;
}
__device__ __forceinline__ void cpa16(uint32_t dst, const float* src, int srcBytes) {
    asm volatile("cp.async.cg.shared.global [%0], [%1], 16, %2;"
                 :: "r"(dst), "l"(src), "r"(srcBytes));
}
#define CPA_COMMIT() asm volatile("cp.async.commit_group;" ::: "memory")
#define CPA_WAIT0()  asm volatile("cp.async.wait_group 0;" ::: "memory")

// ---------------- selectors ----------------
__device__ __forceinline__ const float* selA3(int s) {
    switch (s) {
        case 0: return g_xm;  case 1: return g_hA;  case 2: return g_hB;
        case 3: return g_cf;  case 4: return g_hA + TC*DD;
    }
    return g_xm;
}
__device__ __forceinline__ const float* selB3(int s, const float* Bp) {
    switch (s) { case 1: return g_hw; case 2: return g_bwPad; }
    return Bp;
}
__device__ __forceinline__ float* selC3(int s) {
    switch (s) {
        case 0: return g_q;  case 1: return g_kall;  case 2: return g_hw;
        case 3: return g_hB + TC*DD;  case 4: return g_hA + TC*DD;
    }
    return g_q;
}

// ---------------- xm = mean over 7x7; also write src rows 69.. -------------
__global__ void k_xm(const float* __restrict__ x) {
    __shared__ float buf[4][32*49];
    int w = threadIdx.x >> 5, lane = threadIdx.x & 31;
    int base = (blockIdx.x*4 + w) * 32;
    const float* src = x + (size_t)base*49;
    float* b = buf[w];
    #pragma unroll
    for (int t = 0; t < 49; t++) b[lane + 32*t] = src[lane + 32*t];
    __syncwarp();
    float s = 0.f;
    #pragma unroll
    for (int t = 0; t < 49; t++) s += b[lane*49 + t];
    s *= (1.f/49.f);
    int seg = base + lane;
    g_xm[seg] = s;
    g_hA[TC*DD + seg] = s;
}

// ---------------- prep: zero seg sums/counts/C69, pad base_w ----------------
__global__ void k_prep(const float* __restrict__ bw) {
    int i = blockIdx.x*256 + threadIdx.x;
    if (i < NT*DD) g_tsum[i] = 0.f;
    if (i < NC*DD) g_csum[i] = 0.f;
    if (i < NT) g_cntT[i] = 0;
    if (i < NC) g_cntC[i] = 0;
    if (i < TC*DD) g_C69[i] = 0.f;
    if (i < DD*CFLD) {
        int r = i / CFLD, c = i - r*CFLD;
        g_bwPad[i] = (c < NC) ? bw[r*NC + c] : 0.f;
    }
}
__global__ void k_count(const int* __restrict__ to, const int* __restrict__ lb) {
    int i = blockIdx.x*256 + threadIdx.x;
    if (i < BN) { atomicAdd(&g_cntT[to[i]], 1); atomicAdd(&g_cntC[lb[i]], 1); }
}
__global__ void k_segsum(const int* __restrict__ to, const int* __restrict__ lb) {
    __shared__ float sT[NT][64];
    __shared__ float sC[NC][64];
    int t = threadIdx.x;
    int cr = t & 63, rr = t >> 6;
    int r0 = blockIdx.y * 64, c0 = blockIdx.x * 64;
    for (int i = t; i < NT*64; i += 256) ((float*)sT)[i] = 0.f;
    for (int i = t; i < NC*64; i += 256) ((float*)sC)[i] = 0.f;
    __syncthreads();
    for (int r = r0 + rr; r < r0 + 64; r += 4) {
        int tt = to[r], cc = lb[r];
        float v = g_xm[r*DD + c0 + cr];
        atomicAdd(&sT[tt][cr], v);
        atomicAdd(&sC[cc][cr], v);
    }
    __syncthreads();
    for (int i = t; i < NT*64; i += 256)
        atomicAdd(&g_tsum[(i>>6)*DD + c0 + (i&63)], ((float*)sT)[i]);
    for (int i = t; i < NC*64; i += 256)
        atomicAdd(&g_csum[(i>>6)*DD + c0 + (i&63)], ((float*)sC)[i]);
}
__global__ void k_t1c1(const float* __restrict__ trep, const float* __restrict__ cpro) {
    int i = blockIdx.x*256 + threadIdx.x;
    if (i >= TC*DD) return;
    int seg = i / DD, d = i % DD;
    float v;
    if (seg < NT) {
        float cnt = fmaxf((float)g_cntT[seg], 1.f);
        v = 0.9f*trep[i] + 0.1f*g_tsum[i]/cnt;
    } else {
        int c = seg - NT;
        float cnt = fmaxf((float)g_cntC[c], 1.f);
        v = 0.9f*cpro[c*DD+d] + 0.1f*g_csum[c*DD+d]/cnt;
    }
    g_hA[i] = v;
}

// ---------------- graph kernels ----------------
__global__ void k_d2cross() {
    int c = blockIdx.x;
    int w = threadIdx.x >> 5, lane = threadIdx.x & 31;
    __shared__ float sd2[NT];
    const float* t1 = g_hA;
    const float* c1 = g_hA + NT*DD;
    float s = 0.f;
    for (int d = lane; d < DD; d += 32) {
        float df = t1[w*DD+d] - c1[c*DD+d];
        s += df*df;
    }
    #pragma unroll
    for (int o = 16; o; o >>= 1) s += __shfl_xor_sync(0xffffffffu, s, o);
    if (lane == 0) sd2[w] = s;
    __syncthreads();
    if (threadIdx.x == 0) {
        float l[NT], mx = -1e30f;
        for (int t = 0; t < NT; t++) { l[t] = -sd2[t]*(1.f/16.f); mx = fmaxf(mx, l[t]); }
        float Z = 0.f;
        for (int t = 0; t < NT; t++) { l[t] = expf(l[t]-mx); Z += l[t]; }
        for (int t = 0; t < NT; t++) {
            float p = l[t]/Z;
            g_cross[t*NC + c] = p;
            g_adj[t*TC + NT + c] = p;
            g_adj[(NT+c)*TC + t] = p;
        }
    }
}
__global__ void k_tg(const float* __restrict__ tw, const float* __restrict__ tb) {
    int i = blockIdx.x >> 2, j = blockIdx.x & 3;
    int lane = threadIdx.x;
    const float* t1 = g_hA;
    float s = 0.f;
    for (int d = lane; d < DD; d += 32)
        s += fabsf(t1[i*DD+d]-t1[j*DD+d]) * tw[d];
    #pragma unroll
    for (int o = 16; o; o >>= 1) s += __shfl_xor_sync(0xffffffffu, s, o);
    if (lane == 0) {
        float v = 1.f/(1.f+expf(-(s + tb[0])));
        if (i == j) v = 0.f;
        g_adj[i*TC+j] = v;
    }
}
__global__ void k_cg(const float* __restrict__ cw, const float* __restrict__ cb) {
    int i = blockIdx.x;
    int w = threadIdx.x >> 5, lane = threadIdx.x & 31;
    int j = blockIdx.y*4 + w;
    if (j >= NC) return;
    const float* c1 = g_hA + NT*DD;
    float s = 0.f;
    for (int d = lane; d < DD; d += 32)
        s += fabsf(c1[i*DD+d]-c1[j*DD+d]) * cw[d];
    #pragma unroll
    for (int o = 16; o; o >>= 1) s += __shfl_xor_sync(0xffffffffu, s, o);
    if (lane == 0) {
        float v = 1.f/(1.f+expf(-(s + cb[0])));
        if (i == j) v = 0.f;
        g_adj[(NT+i)*TC + NT+j] = v;
    }
}
__global__ void k_ae(float* out) {
    __shared__ float s[NC];
    int c = threadIdx.x;
    float a = 0.f;
    for (int t = 0; t < NT; t++) { float p = g_cross[t*NC+c]; a += p*logf(p); }
    s[c] = a;
    __syncthreads();
    if (c == 0) { float r = 0.f; for (int i = 0; i < NC; i++) r += s[i]; out[0] = r/(float)NC; }
}

// ---------------- tf32 GEMM (cp.async double-buffered, 1 barrier/chunk) ----
// C = A(MxK,row) @ B(KxN,row). Block 128x128, 8 warps (4m x 2n), warp 32x64.
// Up to 2 extra configs via ySplit/ySplit2. cSel 0/1 (q/kall) stores tf32-rounded.
#define GEMM_SMEM ((2*128*36 + 2*32*136)*4)
#define AS(p,r,c) smp[(p)*4608 + (r)*36 + (c)]
#define BS(p,r,c) smp[9216 + (p)*4352 + (r)*136 + (c)]
__global__ void __launch_bounds__(256, 2) k_gemm3(
        int aSel, int bSel, const float* __restrict__ Bp, int cSel,
        int M, int N, int K, int lda, int ldb, int ldc,
        const float* __restrict__ bias, int relu,
        const float* __restrict__ tcw, const int* __restrict__ to,
        float* yout,
        int ySplit, int aSel2, const float* __restrict__ Bp2, int cSel2, int M2,
        int ySplit2, int aSel3, const float* __restrict__ Bp3, int cSel3, int M3) {
    extern __shared__ float smp[];
    int by = blockIdx.y;
    if (ySplit2 > 0 && by >= ySplit2) {
        aSel = aSel3; Bp = Bp3; cSel = cSel3; M = M3; by -= ySplit2;
    } else if (ySplit > 0 && by >= ySplit) {
        aSel = aSel2; Bp = Bp2; cSel = cSel2; M = M2; by -= ySplit;
    }
    const float* A = selA3(aSel);
    const float* B = selB3(bSel, Bp);
    float* C = yout ? yout : selC3(cSel);
    int tfout = (!yout && cSel <= 1);
    int tid = threadIdx.x;
    int w = tid >> 5, lane = tid & 31, g = lane >> 2, t = lane & 3;
    int wm = (w & 3) * 32, wn = (w >> 2) * 64;
    int m0 = by*128, n0 = blockIdx.x*128;
    uint32_t sb = (uint32_t)__cvta_generic_to_shared(smp);

    auto fillA = [&](int p, int k0) {
        #pragma unroll
        for (int r = 0; r < 4; r++) {
            int idx = tid + 256*r;
            int row = idx >> 3, fc = idx & 7;
            int gm = m0 + row, gk = k0 + fc*4;
            int sz = 16;
            if (gm >= M) sz = 0;
            int rem = (K - gk)*4;
            if (rem < sz) sz = rem < 0 ? 0 : rem;
            const float* src = sz > 0 ? &A[(size_t)gm*lda + gk] : A;
            cpa16(sb + (uint32_t)(p*4608 + row*36 + fc*4)*4u, src, sz);
        }
    };
    auto fillB = [&](int p, int k0) {
        #pragma unroll
        for (int r = 0; r < 4; r++) {
            int idx = tid + 256*r;
            int row = idx >> 5, c4 = (idx & 31)*4;
            int gk = k0 + row, gn = n0 + c4;
            int sz = 16;
            if (gk >= K) sz = 0;
            int rem = (N - gn)*4;
            if (rem < sz) sz = rem < 0 ? 0 : rem;
            const float* src = sz > 0 ? &B[(size_t)gk*ldb + gn] : B;
            cpa16(sb + (uint32_t)(9216 + p*4352 + row*136 + c4)*4u, src, sz);
        }
    };

    float acc[2][8][4] = {};
    int nk = (K + 31) >> 5;
    fillA(0, 0); fillB(0, 0); CPA_COMMIT();
    for (int kc = 0; kc < nk; kc++) {
        CPA_WAIT0();
        __syncthreads();
        if (kc + 1 < nk) { fillA((kc+1)&1, (kc+1)*32); fillB((kc+1)&1, (kc+1)*32); CPA_COMMIT(); }
        int p = kc & 1;
        #pragma unroll
        for (int kk = 0; kk < 32; kk += 8) {
            uint32_t a[2][4];
            #pragma unroll
            for (int mi = 0; mi < 2; mi++) {
                a[mi][0] = ftf(AS(p, wm+mi*16+g  , kk+t));
                a[mi][1] = ftf(AS(p, wm+mi*16+g+8, kk+t));
                a[mi][2] = ftf(AS(p, wm+mi*16+g  , kk+t+4));
                a[mi][3] = ftf(AS(p, wm+mi*16+g+8, kk+t+4));
            }
            uint32_t b[8][2];
            #pragma unroll
            for (int ni = 0; ni < 8; ni++) {
                b[ni][0] = ftf(BS(p, kk+t  , wn+ni*8+g));
                b[ni][1] = ftf(BS(p, kk+t+4, wn+ni*8+g));
            }
            #pragma unroll
            for (int mi = 0; mi < 2; mi++)
                #pragma unroll
                for (int ni = 0; ni < 8; ni++)
                    mma8(acc[mi][ni], a[mi][0], a[mi][1], a[mi][2], a[mi][3],
                         b[ni][0], b[ni][1]);
        }
    }
    #pragma unroll
    for (int mi = 0; mi < 2; mi++) {
        int r0 = m0 + wm + mi*16 + g, r1 = r0 + 8;
        #pragma unroll
        for (int ni = 0; ni < 8; ni++) {
            int n = n0 + wn + ni*8 + 2*t;
            float bv0 = 0.f, bv1 = 0.f;
            if (bias) { if (n < N) bv0 = bias[n]; if (n+1 < N) bv1 = bias[n+1]; }
            float v00 = acc[mi][ni][0] + bv0, v01 = acc[mi][ni][1] + bv1;
            float v10 = acc[mi][ni][2] + bv0, v11 = acc[mi][ni][3] + bv1;
            if (relu) {
                v00 = fmaxf(v00, 0.f); v01 = fmaxf(v01, 0.f);
                v10 = fmaxf(v10, 0.f); v11 = fmaxf(v11, 0.f);
            }
            if (tfout) {
                v00 = __uint_as_float(ftf(v00)); v01 = __uint_as_float(ftf(v01));
                v10 = __uint_as_float(ftf(v10)); v11 = __uint_as_float(ftf(v11));
            }
            if (yout) {
                if (r0 < M) {
                    if (n < N)   C[(size_t)r0*ldc + n]   = tcw[to[r0]*NC + n]   * v00;
                    if (n+1 < N) C[(size_t)r0*ldc + n+1] = tcw[to[r0]*NC + n+1] * v01;
                }
                if (r1 < M) {
                    if (n < N)   C[(size_t)r1*ldc + n]   = tcw[to[r1]*NC + n]   * v10;
                    if (n+1 < N) C[(size_t)r1*ldc + n+1] = tcw[to[r1]*NC + n+1] * v11;
                }
            } else {
                if (r0 < M) {
                    if (n < N)   C[(size_t)r0*ldc + n]   = v00;
                    if (n+1 < N) C[(size_t)r0*ldc + n+1] = v01;
                }
                if (r1 < M) {
                    if (n < N)   C[(size_t)r1*ldc + n]   = v10;
                    if (n+1 < N) C[(size_t)r1*ldc + n+1] = v11;
                }
            }
        }
    }
}

// ---------------- attention (cp.async, streaming softmax) ------------------
// q/kall are PRE-ROUNDED to tf32 -> fragment loads are raw bit loads (no cvt).
#define ATTN_SMEM ((2*128*36*2)*4)
#define QS(p,r,c) smp[(p)*4608 + (r)*36 + (c)]
#define KS(p,r,c) smp[9216 + (p)*4608 + (r)*36 + (c)]
__global__ void __launch_bounds__(256, 2) k_attn3() {
    extern __shared__ float smp[];
    __shared__ float sm_m[2][128];
    __shared__ float sm_z[2][128];
    int tid = threadIdx.x;
    int w = tid >> 5, lane = tid & 31, g = lane >> 2, t = lane & 3;
    int wm = (w & 3) * 32, wn = (w >> 2) * 64;
    int half = w >> 2;
    int i0 = blockIdx.x*128;
    int split = blockIdx.y;
    const float sc = 0.044194173824159216f;   // 1/sqrt(512)
    uint32_t sb = (uint32_t)__cvta_generic_to_shared(smp);

    auto fillQ = [&](int p, int k0) {
        #pragma unroll
        for (int r = 0; r < 4; r++) {
            int idx = tid + 256*r;
            int row = idx >> 3, fc = idx & 7;
            cpa16(sb + (uint32_t)(p*4608 + row*36 + fc*4)*4u,
                  &g_q[(size_t)(i0+row)*DD + k0 + fc*4], 16);
        }
    };
    auto fillK = [&](int p, int j0v, int k0) {
        #pragma unroll
        for (int r = 0; r < 4; r++) {
            int idx = tid + 256*r;
            int row = idx >> 3, fc = idx & 7;
            int gj = j0v + row;
            int sz = gj < NS ? 16 : 0;
            const float* src = sz ? &g_kall[(size_t)gj*DD + k0 + fc*4] : g_kall;
            cpa16(sb + (uint32_t)(9216 + p*4608 + row*36 + fc*4)*4u, src, sz);
        }
    };

    float mr[2][2] = {{-1e30f,-1e30f},{-1e30f,-1e30f}};
    float zr[2][2] = {{0.f,0.f},{0.f,0.f}};
    int jt0 = split*JPT;
    int jt1 = jt0 + JPT; if (jt1 > NJT) jt1 = NJT;
    int cg = 0;
    fillQ(0, 0); fillK(0, jt0*128, 0); CPA_COMMIT();
    for (int jt = jt0; jt < jt1; jt++) {
        int j0 = jt*128;
        float acc[2][8][4] = {};
        for (int c = 0; c < 16; c++, cg++) {
            CPA_WAIT0();
            __syncthreads();
            int p = cg & 1;
            if (c < 15) {
                fillQ(p^1, (c+1)*32); fillK(p^1, j0, (c+1)*32); CPA_COMMIT();
            } else if (jt + 1 < jt1) {
                fillQ(p^1, 0); fillK(p^1, (jt+1)*128, 0); CPA_COMMIT();
            }
            #pragma unroll
            for (int kk = 0; kk < 32; kk += 8) {
                uint32_t a[2][4];
                #pragma unroll
                for (int mi = 0; mi < 2; mi++) {
                    a[mi][0] = __float_as_uint(QS(p, wm+mi*16+g  , kk+t));
                    a[mi][1] = __float_as_uint(QS(p, wm+mi*16+g+8, kk+t));
                    a[mi][2] = __float_as_uint(QS(p, wm+mi*16+g  , kk+t+4));
                    a[mi][3] = __float_as_uint(QS(p, wm+mi*16+g+8, kk+t+4));
                }
                uint32_t b[8][2];
                #pragma unroll
                for (int ni = 0; ni < 8; ni++) {
                    b[ni][0] = __float_as_uint(KS(p, wn+ni*8+g, kk+t));
                    b[ni][1] = __float_as_uint(KS(p, wn+ni*8+g, kk+t+4));
                }
                #pragma unroll
                for (int mi = 0; mi < 2; mi++)
                    #pragma unroll
                    for (int ni = 0; ni < 8; ni++)
                        mma8(acc[mi][ni], a[mi][0], a[mi][1], a[mi][2], a[mi][3],
                             b[ni][0], b[ni][1]);
            }
        }
        int doL = (split == 0 && jt == 0);
        #pragma unroll
        for (int mi = 0; mi < 2; mi++) {
            int r0g = i0 + wm + mi*16 + g, r1g = r0g + 8;
            float lm0 = -1e30f, lm1 = -1e30f;
            #pragma unroll
            for (int ni = 0; ni < 8; ni++) {
                int base = j0 + wn + ni*8 + 2*t;
                float v0 = (base   < NS) ? acc[mi][ni][0]*sc : -1e30f;
                float v1 = (base+1 < NS) ? acc[mi][ni][1]*sc : -1e30f;
                float v2 = (base   < NS) ? acc[mi][ni][2]*sc : -1e30f;
                float v3 = (base+1 < NS) ? acc[mi][ni][3]*sc : -1e30f;
                acc[mi][ni][0] = v0; acc[mi][ni][1] = v1;
                acc[mi][ni][2] = v2; acc[mi][ni][3] = v3;
                if (doL) {
                    int c0 = wn + ni*8 + 2*t;
                    if (c0 < TC) {
                        g_l69[(size_t)r0g*TC + c0] = v0;
                        g_l69[(size_t)r1g*TC + c0] = v2;
                    }
                    if (c0 + 1 < TC) {
                        g_l69[(size_t)r0g*TC + c0+1] = v1;
                        g_l69[(size_t)r1g*TC + c0+1] = v3;
                    }
                }
                lm0 = fmaxf(lm0, fmaxf(v0, v1));
                lm1 = fmaxf(lm1, fmaxf(v2, v3));
            }
            lm0 = fmaxf(lm0, __shfl_xor_sync(0xffffffffu, lm0, 1));
            lm0 = fmaxf(lm0, __shfl_xor_sync(0xffffffffu, lm0, 2));
            lm1 = fmaxf(lm1, __shfl_xor_sync(0xffffffffu, lm1, 1));
            lm1 = fmaxf(lm1, __shfl_xor_sync(0xffffffffu, lm1, 2));
            float nm0 = fmaxf(mr[mi][0], lm0), nm1 = fmaxf(mr[mi][1], lm1);
            float p0 = 0.f, p1 = 0.f;
            #pragma unroll
            for (int ni = 0; ni < 8; ni++) {
                p0 += __expf(acc[mi][ni][0]-nm0) + __expf(acc[mi][ni][1]-nm0);
                p1 += __expf(acc[mi][ni][2]-nm1) + __expf(acc[mi][ni][3]-nm1);
            }
            p0 += __shfl_xor_sync(0xffffffffu, p0, 1);
            p0 += __shfl_xor_sync(0xffffffffu, p0, 2);
            p1 += __shfl_xor_sync(0xffffffffu, p1, 1);
            p1 += __shfl_xor_sync(0xffffffffu, p1, 2);
            zr[mi][0] = zr[mi][0]*__expf(mr[mi][0] - nm0) + p0; mr[mi][0] = nm0;
            zr[mi][1] = zr[mi][1]*__expf(mr[mi][1] - nm1) + p1; mr[mi][1] = nm1;
        }
    }
    if (t == 0) {
        #pragma unroll
        for (int mi = 0; mi < 2; mi++) {
            int r = wm + mi*16 + g;
            sm_m[half][r]     = mr[mi][0];  sm_z[half][r]     = zr[mi][0];
            sm_m[half][r + 8] = mr[mi][1];  sm_z[half][r + 8] = zr[mi][1];
        }
    }
    __syncthreads();
    if (tid < 128) {
        float m0 = sm_m[0][tid], m1 = sm_m[1][tid];
        float m = fmaxf(m0, m1);
        float z = sm_z[0][tid]*__expf(m0 - m) + sm_z[1][tid]*__expf(m1 - m);
        g_mp[split*BN + i0 + tid] = m;
        g_zp[split*BN + i0 + tid] = z;
    }
}

// ---------------- combine splits + first-69 softmax -> cf (padded) --------
__global__ void k_cf() {
    int i = blockIdx.x;
    int j = threadIdx.x;
    __shared__ float sh[2];
    if (j == 0) {
        float m = -1e30f;
        #pragma unroll
        for (int s = 0; s < NSPL; s++) m = fmaxf(m, g_mp[s*BN + i]);
        float z = 0.f;
        #pragma unroll
        for (int s = 0; s < NSPL; s++) z += g_zp[s*BN + i]*__expf(g_mp[s*BN + i] - m);
        sh[0] = m; sh[1] = 1.f/z;
    }
    __syncthreads();
    if (j < CFLD)
        g_cf[i*CFLD + j] = (j < TC) ? __expf(g_l69[i*TC + j] - sh[0]) * sh[1] : 0.f;
}

// ---------------- GNN tc-rows partial: C69 += cf^T @ hw_x ----------------
__global__ void k_outtc() {
    __shared__ float cfs[64][72];
    __shared__ float hws[64][64];
    int t = threadIdx.x, tx = t & 63, ty = t >> 6;
    int n0 = blockIdx.x*64;
    int b0 = blockIdx.y*256;
    float acc[18];
    #pragma unroll
    for (int k = 0; k < 18; k++) acc[k] = 0.f;
    for (int bc = 0; bc < 256; bc += 64) {
        int bb = b0 + bc;
        for (int i = t; i < 64*TC; i += 256) {
            int r = i/TC, k = i%TC;
            cfs[r][k] = g_cf[(size_t)(bb+r)*CFLD + k];
        }
        for (int i = t; i < 64*64; i += 256) {
            int r = i >> 6, n = i & 63;
            hws[r][n] = g_hw[(size_t)(TC+bb+r)*DD + n0 + n];
        }
        __syncthreads();
        for (int r = 0; r < 64; r++) {
            float hv = hws[r][tx];
            #pragma unroll
            for (int k = 0; k < 18; k++) {
                int m = ty + 4*k;
                if (m < TC) acc[k] += cfs[r][m]*hv;
            }
        }
        __syncthreads();
    }
    #pragma unroll
    for (int k = 0; k < 18; k++) {
        int m = ty + 4*k;
        if (m < TC) atomicAdd(&g_C69[m*DD + n0 + tx], acc[k]);
    }
}

// ---------------- finalize tc rows (layer 0 only) ----------------
__global__ void k_fintc(const float* __restrict__ gb) {
    int m = blockIdx.x;      // 69
    int n = threadIdx.x;     // 512
    float v = g_C69[m*DD + n];
    for (int j = 0; j < TC; j++)
        v += g_adj[m*TC+j] * g_hw[j*DD + n];
    v += gb[n];
    g_hB[m*DD + n] = fmaxf(v, 0.f);
}

// ---------------- labels ----------------
__global__ void k_labels(const int* __restrict__ lb, float* out, int off, int out_size) {
    int i = blockIdx.x*256 + threadIdx.x;
    if (i < BN && off + i < out_size) out[off + i] = (float)lb[i];
}

// ======================== host ========================
extern "C" void kernel_launch(void* const* d_in, const int* in_sizes, int n_in,
                              void* d_out, int out_size) {
    const float* x    = (const float*)d_in[0];
    const int*   lb   = (const int*)d_in[1];
    const int*   to   = (const int*)d_in[2];
    const float* trep = (const float*)d_in[3];
    const float* cpro = (const float*)d_in[4];
    const float* tw   = (const float*)d_in[5];
    const float* tb   = (const float*)d_in[6];
    const float* cw   = (const float*)d_in[7];
    const float* cb   = (const float*)d_in[8];
    const float* wq   = (const float*)d_in[9];
    const float* wk   = (const float*)d_in[10];
    const float* gw   = (const float*)d_in[11];
    const float* gb   = (const float*)d_in[12];
    const float* bw   = (const float*)d_in[13];
    const float* bb   = (const float*)d_in[14];
    const float* tcw  = (const float*)d_in[15];
    float* out = (float*)d_out;

    cudaFuncSetAttribute(k_gemm3, cudaFuncAttributeMaxDynamicSharedMemorySize, GEMM_SMEM);
    cudaFuncSetAttribute(k_attn3, cudaFuncAttributeMaxDynamicSharedMemorySize, ATTN_SMEM);

    int y_off = (out_size > BN*NC) ? 1 : 0;
    int lbl_off = y_off + BN*NC;

    // 1-3. xm; prep; count
    k_xm<<<16384, 128>>>(x);
    k_prep<<<(DD*CFLD + 255)/256, 256>>>(bw);
    k_count<<<16, 256>>>(to, lb);
    // 4. q = xm@wq (profiling beacon at slot 4; only needs xm)
    k_gemm3<<<dim3(4, 32), 256, GEMM_SMEM>>>(0, 0, wq, 0, BN, DD, DD, DD, DD, DD,
                                             nullptr, 0, nullptr, nullptr, nullptr,
                                             0, 0, nullptr, 0, 0, 0, 0, nullptr, 0, 0);
    // 5-6. segment means -> t1/c1
    k_segsum<<<dim3(8, 64), 256>>>(to, lb);
    k_t1c1<<<(TC*DD + 255)/256, 256>>>(trep, cpro);
    // fork: graph kernels on side stream (need only hA rows 0..68)
    cudaEventRecord(g_e1, 0);
    cudaStreamWaitEvent(g_s1, g_e1, 0);
    k_d2cross<<<65, 128, 0, g_s1>>>();
    k_tg<<<16, 32, 0, g_s1>>>(tw, tb);
    k_cg<<<dim3(65, 17), 128, 0, g_s1>>>(cw, cb);
    if (y_off) k_ae<<<1, 65, 0, g_s1>>>(out);
    // main: fused kall = hA@wk | hw = hA@gw1
    k_gemm3<<<dim3(4, 66), 256, GEMM_SMEM>>>(1, 0, wk, 1, NS, DD, DD, DD, DD, DD,
                                             nullptr, 0, nullptr, nullptr, nullptr,
                                             33, 1, gw, 2, NS, 0, 0, nullptr, 0, 0);
    // main: attention + cf
    k_attn3<<<dim3(32, NSPL), 256, ATTN_SMEM>>>();
    k_cf<<<4096, 96>>>();
    // fork2: outtc + fintc on side stream (needs cf, hw, adj)
    cudaEventRecord(g_e2, 0);
    cudaStreamWaitEvent(g_s1, g_e2, 0);
    k_outtc<<<dim3(8, 16), 256, 0, g_s1>>>();
    k_fintc<<<69, 512, 0, g_s1>>>(gb);
    cudaEventRecord(g_e3, g_s1);
    // main: L0 x-rows = relu(cf@hw_tc + gb0)  (overlaps outtc/fintc)
    k_gemm3<<<dim3(4, 32), 256, GEMM_SMEM>>>(3, 1, nullptr, 3, BN, DD, CFLD, CFLD, DD, DD,
                                             gb, 1, nullptr, nullptr, nullptr,
                                             0, 0, nullptr, 0, 0, 0, 0, nullptr, 0, 0);
    // join
    cudaStreamWaitEvent(0, g_e3, 0);
    // L1: hw2 rows 0..127 (needs hB rows 0..127), then x-rows
    k_gemm3<<<dim3(4, 1), 256, GEMM_SMEM>>>(2, 0, gw + DD*DD, 2, 128, DD, DD, DD, DD, DD,
                                            nullptr, 0, nullptr, nullptr, nullptr,
                                            0, 0, nullptr, 0, 0, 0, 0, nullptr, 0, 0);
    k_gemm3<<<dim3(4, 32), 256, GEMM_SMEM>>>(3, 1, nullptr, 4, BN, DD, CFLD, CFLD, DD, DD,
                                             gb + DD, 1, nullptr, nullptr, nullptr,
                                             0, 0, nullptr, 0, 0, 0, 0, nullptr, 0, 0);
    // outputs
    k_gemm3<<<dim3(1, 32), 256, GEMM_SMEM>>>(4, 2, nullptr, 0, BN, NC, DD, DD, CFLD, NC,
                                             bb, 0, tcw, to, out + y_off,
                                             0, 0, nullptr, 0, 0, 0, 0, nullptr, 0, 0);
    k_labels<<<16, 256>>>(lb, out, lbl_off, out_size);
}

// round 10
// speedup vs baseline: 5.8483x; 1.1402x over previous
#include <cuda_runtime.h>
#include <math.h>
#include <stdint.h>

#define BN 4096
#define DD 512
#define NT 4
#define NC 65
#define TC 69          // NT + NC
#define NS 4165        // TC + BN
#define CFLD 72        // padded cf row stride
#define NSPL 9         // attention splits
#define NJT 33
#define JPT 4

// ---------------- scratch (device globals; no allocations) ----------------
__device__ float g_xm[BN*DD];
__device__ float g_q[BN*DD];
__device__ float g_kall[NS*DD];
__device__ float g_hA[NS*DD];
__device__ float g_hB[NS*DD];
__device__ float g_hw[NS*DD];
__device__ float g_tsum[NT*DD];
__device__ float g_csum[NC*DD];
__device__ int   g_cntT[NT];
__device__ int   g_cntC[NC];
__device__ float g_adj[TC*TC];
__device__ float g_cross[NT*NC];
__device__ float g_cf[BN*CFLD];
__device__ float g_l69[BN*TC];
__device__ float g_mp[16*BN];
__device__ float g_zp[16*BN];
__device__ float g_C69[TC*DD];
__device__ float g_bwPad[DD*CFLD];
__device__ float g_wR[4*DD*DD];   // tf32-rounded: 0=wq 1=wk 2=gw1 3=gw2

// ---------------- static stream/event resources ----------------
static cudaStream_t g_s1;
static cudaEvent_t g_e1, g_e2, g_e3;
static struct StreamInit {
    StreamInit() {
        cudaStreamCreateWithFlags(&g_s1, cudaStreamNonBlocking);
        cudaEventCreateWithFlags(&g_e1, cudaEventDisableTiming);
        cudaEventCreateWithFlags(&g_e2, cudaEventDisableTiming);
        cudaEventCreateWithFlags(&g_e3, cudaEventDisableTiming);
    }
} g_si;

// ---------------- tf32 / mma / cp.async helpers ----------------
__device__ __forceinline__ void mma8(float* c, uint32_t a0, uint32_t a1,
                                     uint32_t a2, uint32_t a3,
                                     uint32_t b0, uint32_t b1) {
    asm("mma.sync.aligned.m16n8k8.row.col.f32.tf32.tf32.f32 "
        "{%0,%1,%2,%3},{%4,%5,%6,%7},{%8,%9},{%0,%1,%2,%3};"
        : "+f"(c[0]), "+f"(c[1]), "+f"(c[2]), "+f"(c[3])
        : "r"(a0), "r"(a1), "r"(a2), "r"(a3), "r"(b0), "r"(b1));
}
__device__ __forceinline__ float rtf(float x) {
    uint32_t u;
    asm("cvt.rna.tf32.f32 %0, %1;" : "=r"(u) : "f"(x));
    return __uint_as_float(u);
}
__device__ __forceinline__ void cpa16(uint32_t dst, const float* src, int srcBytes) {
    asm volatile("cp.async.cg.shared.global [%0], [%1], 16, %2;"
                 :: "r"(dst), "l"(src), "r"(srcBytes));
}
#define CPA_COMMIT() asm volatile("cp.async.commit_group;" ::: "memory")
#define CPA_WAIT0()  asm volatile("cp.async.wait_group 0;" ::: "memory")

// ---------------- selectors ----------------
__device__ __forceinline__ const float* selA3(int s) {
    switch (s) {
        case 0: return g_xm;  case 1: return g_hA;  case 2: return g_hB;
        case 3: return g_cf;  case 4: return g_hA + TC*DD;
    }
    return g_xm;
}
__device__ __forceinline__ const float* selB3(int s, const float* Bp) {
    switch (s) { case 1: return g_hw; case 2: return g_bwPad; }
    return Bp;
}
__device__ __forceinline__ float* selC3(int s) {
    switch (s) {
        case 0: return g_q;  case 1: return g_kall;  case 2: return g_hw;
        case 3: return g_hB + TC*DD;  case 4: return g_hA + TC*DD;
    }
    return g_q;
}

// ---------------- xm = mean over 7x7 (tf32-rounded); src rows 69.. ---------
__global__ void k_xm(const float* __restrict__ x) {
    __shared__ float buf[4][32*49];
    int w = threadIdx.x >> 5, lane = threadIdx.x & 31;
    int base = (blockIdx.x*4 + w) * 32;
    const float* src = x + (size_t)base*49;
    float* b = buf[w];
    #pragma unroll
    for (int t = 0; t < 49; t++) b[lane + 32*t] = src[lane + 32*t];
    __syncwarp();
    float s = 0.f;
    #pragma unroll
    for (int t = 0; t < 49; t++) s += b[lane*49 + t];
    s = rtf(s * (1.f/49.f));
    int seg = base + lane;
    g_xm[seg] = s;
    g_hA[TC*DD + seg] = s;
}

// ---------------- prep: zeros, pad+round base_w, round all weights ---------
__global__ void k_prep(const float* __restrict__ wq, const float* __restrict__ wk,
                       const float* __restrict__ gw, const float* __restrict__ bw) {
    int i = blockIdx.x*256 + threadIdx.x;
    if (i < DD*DD) {
        g_wR[i]           = rtf(wq[i]);
        g_wR[DD*DD + i]   = rtf(wk[i]);
        g_wR[2*DD*DD + i] = rtf(gw[i]);
        g_wR[3*DD*DD + i] = rtf(gw[DD*DD + i]);
    }
    if (i < NT*DD) g_tsum[i] = 0.f;
    if (i < NC*DD) g_csum[i] = 0.f;
    if (i < NT) g_cntT[i] = 0;
    if (i < NC) g_cntC[i] = 0;
    if (i < TC*DD) g_C69[i] = 0.f;
    if (i < DD*CFLD) {
        int r = i / CFLD, c = i - r*CFLD;
        g_bwPad[i] = (c < NC) ? rtf(bw[r*NC + c]) : 0.f;
    }
}
__global__ void k_count(const int* __restrict__ to, const int* __restrict__ lb) {
    int i = blockIdx.x*256 + threadIdx.x;
    if (i < BN) { atomicAdd(&g_cntT[to[i]], 1); atomicAdd(&g_cntC[lb[i]], 1); }
}
__global__ void k_segsum(const int* __restrict__ to, const int* __restrict__ lb) {
    __shared__ float sT[NT][64];
    __shared__ float sC[NC][64];
    int t = threadIdx.x;
    int cr = t & 63, rr = t >> 6;
    int r0 = blockIdx.y * 64, c0 = blockIdx.x * 64;
    for (int i = t; i < NT*64; i += 256) ((float*)sT)[i] = 0.f;
    for (int i = t; i < NC*64; i += 256) ((float*)sC)[i] = 0.f;
    __syncthreads();
    for (int r = r0 + rr; r < r0 + 64; r += 4) {
        int tt = to[r], cc = lb[r];
        float v = g_xm[r*DD + c0 + cr];
        atomicAdd(&sT[tt][cr], v);
        atomicAdd(&sC[cc][cr], v);
    }
    __syncthreads();
    for (int i = t; i < NT*64; i += 256)
        atomicAdd(&g_tsum[(i>>6)*DD + c0 + (i&63)], ((float*)sT)[i]);
    for (int i = t; i < NC*64; i += 256)
        atomicAdd(&g_csum[(i>>6)*DD + c0 + (i&63)], ((float*)sC)[i]);
}
__global__ void k_t1c1(const float* __restrict__ trep, const float* __restrict__ cpro) {
    int i = blockIdx.x*256 + threadIdx.x;
    if (i >= TC*DD) return;
    int seg = i / DD, d = i % DD;
    float v;
    if (seg < NT) {
        float cnt = fmaxf((float)g_cntT[seg], 1.f);
        v = 0.9f*trep[i] + 0.1f*g_tsum[i]/cnt;
    } else {
        int c = seg - NT;
        float cnt = fmaxf((float)g_cntC[c], 1.f);
        v = 0.9f*cpro[c*DD+d] + 0.1f*g_csum[c*DD+d]/cnt;
    }
    g_hA[i] = rtf(v);
}

// ---------------- graph kernels ----------------
__global__ void k_d2cross() {
    int c = blockIdx.x;
    int w = threadIdx.x >> 5, lane = threadIdx.x & 31;
    __shared__ float sd2[NT];
    const float* t1 = g_hA;
    const float* c1 = g_hA + NT*DD;
    float s = 0.f;
    for (int d = lane; d < DD; d += 32) {
        float df = t1[w*DD+d] - c1[c*DD+d];
        s += df*df;
    }
    #pragma unroll
    for (int o = 16; o; o >>= 1) s += __shfl_xor_sync(0xffffffffu, s, o);
    if (lane == 0) sd2[w] = s;
    __syncthreads();
    if (threadIdx.x == 0) {
        float l[NT], mx = -1e30f;
        for (int t = 0; t < NT; t++) { l[t] = -sd2[t]*(1.f/16.f); mx = fmaxf(mx, l[t]); }
        float Z = 0.f;
        for (int t = 0; t < NT; t++) { l[t] = expf(l[t]-mx); Z += l[t]; }
        for (int t = 0; t < NT; t++) {
            float p = l[t]/Z;
            g_cross[t*NC + c] = p;
            g_adj[t*TC + NT + c] = p;
            g_adj[(NT+c)*TC + t] = p;
        }
    }
}
__global__ void k_tg(const float* __restrict__ tw, const float* __restrict__ tb) {
    int i = blockIdx.x >> 2, j = blockIdx.x & 3;
    int lane = threadIdx.x;
    const float* t1 = g_hA;
    float s = 0.f;
    for (int d = lane; d < DD; d += 32)
        s += fabsf(t1[i*DD+d]-t1[j*DD+d]) * tw[d];
    #pragma unroll
    for (int o = 16; o; o >>= 1) s += __shfl_xor_sync(0xffffffffu, s, o);
    if (lane == 0) {
        float v = 1.f/(1.f+expf(-(s + tb[0])));
        if (i == j) v = 0.f;
        g_adj[i*TC+j] = v;
    }
}
__global__ void k_cg(const float* __restrict__ cw, const float* __restrict__ cb) {
    int i = blockIdx.x;
    int w = threadIdx.x >> 5, lane = threadIdx.x & 31;
    int j = blockIdx.y*4 + w;
    if (j >= NC) return;
    const float* c1 = g_hA + NT*DD;
    float s = 0.f;
    for (int d = lane; d < DD; d += 32)
        s += fabsf(c1[i*DD+d]-c1[j*DD+d]) * cw[d];
    #pragma unroll
    for (int o = 16; o; o >>= 1) s += __shfl_xor_sync(0xffffffffu, s, o);
    if (lane == 0) {
        float v = 1.f/(1.f+expf(-(s + cb[0])));
        if (i == j) v = 0.f;
        g_adj[(NT+i)*TC + NT+j] = v;
    }
}
__global__ void k_ae(float* out) {
    __shared__ float s[NC];
    int c = threadIdx.x;
    float a = 0.f;
    for (int t = 0; t < NT; t++) { float p = g_cross[t*NC+c]; a += p*logf(p); }
    s[c] = a;
    __syncthreads();
    if (c == 0) { float r = 0.f; for (int i = 0; i < NC; i++) r += s[i]; out[0] = r/(float)NC; }
}

// ---------------- tf32 GEMM (cp.async double-buffered, NO hot-loop CVT) ----
// All inputs pre-rounded to tf32 in gmem. Non-y outputs stored tf32-rounded.
#define GEMM_SMEM ((2*128*36 + 2*32*136)*4)
#define AS(p,r,c) smp[(p)*4608 + (r)*36 + (c)]
#define BS(p,r,c) smp[9216 + (p)*4352 + (r)*136 + (c)]
__global__ void __launch_bounds__(256, 2) k_gemm3(
        int aSel, int bSel, const float* __restrict__ Bp, int cSel,
        int M, int N, int K, int lda, int ldb, int ldc,
        const float* __restrict__ bias, int relu,
        const float* __restrict__ tcw, const int* __restrict__ to,
        float* yout,
        int ySplit, int aSel2, const float* __restrict__ Bp2, int cSel2, int M2,
        int ySplit2, int aSel3, const float* __restrict__ Bp3, int cSel3, int M3) {
    extern __shared__ float smp[];
    int by = blockIdx.y;
    if (ySplit2 > 0 && by >= ySplit2) {
        aSel = aSel3; Bp = Bp3; cSel = cSel3; M = M3; by -= ySplit2;
    } else if (ySplit > 0 && by >= ySplit) {
        aSel = aSel2; Bp = Bp2; cSel = cSel2; M = M2; by -= ySplit;
    }
    const float* A = selA3(aSel);
    const float* B = selB3(bSel, Bp);
    float* C = yout ? yout : selC3(cSel);
    int tid = threadIdx.x;
    int w = tid >> 5, lane = tid & 31, g = lane >> 2, t = lane & 3;
    int wm = (w & 3) * 32, wn = (w >> 2) * 64;
    int m0 = by*128, n0 = blockIdx.x*128;
    uint32_t sb = (uint32_t)__cvta_generic_to_shared(smp);

    auto fillA = [&](int p, int k0) {
        #pragma unroll
        for (int r = 0; r < 4; r++) {
            int idx = tid + 256*r;
            int row = idx >> 3, fc = idx & 7;
            int gm = m0 + row, gk = k0 + fc*4;
            int sz = 16;
            if (gm >= M) sz = 0;
            int rem = (K - gk)*4;
            if (rem < sz) sz = rem < 0 ? 0 : rem;
            const float* src = sz > 0 ? &A[(size_t)gm*lda + gk] : A;
            cpa16(sb + (uint32_t)(p*4608 + row*36 + fc*4)*4u, src, sz);
        }
    };
    auto fillB = [&](int p, int k0) {
        #pragma unroll
        for (int r = 0; r < 4; r++) {
            int idx = tid + 256*r;
            int row = idx >> 5, c4 = (idx & 31)*4;
            int gk = k0 + row, gn = n0 + c4;
            int sz = 16;
            if (gk >= K) sz = 0;
            int rem = (N - gn)*4;
            if (rem < sz) sz = rem < 0 ? 0 : rem;
            const float* src = sz > 0 ? &B[(size_t)gk*ldb + gn] : B;
            cpa16(sb + (uint32_t)(9216 + p*4352 + row*136 + c4)*4u, src, sz);
        }
    };

    float acc[2][8][4] = {};
    int nk = (K + 31) >> 5;
    fillA(0, 0); fillB(0, 0); CPA_COMMIT();
    for (int kc = 0; kc < nk; kc++) {
        CPA_WAIT0();
        __syncthreads();
        if (kc + 1 < nk) { fillA((kc+1)&1, (kc+1)*32); fillB((kc+1)&1, (kc+1)*32); CPA_COMMIT(); }
        int p = kc & 1;
        #pragma unroll
        for (int kk = 0; kk < 32; kk += 8) {
            uint32_t a[2][4];
            #pragma unroll
            for (int mi = 0; mi < 2; mi++) {
                a[mi][0] = __float_as_uint(AS(p, wm+mi*16+g  , kk+t));
                a[mi][1] = __float_as_uint(AS(p, wm+mi*16+g+8, kk+t));
                a[mi][2] = __float_as_uint(AS(p, wm+mi*16+g  , kk+t+4));
                a[mi][3] = __float_as_uint(AS(p, wm+mi*16+g+8, kk+t+4));
            }
            uint32_t b[8][2];
            #pragma unroll
            for (int ni = 0; ni < 8; ni++) {
                b[ni][0] = __float_as_uint(BS(p, kk+t  , wn+ni*8+g));
                b[ni][1] = __float_as_uint(BS(p, kk+t+4, wn+ni*8+g));
            }
            #pragma unroll
            for (int mi = 0; mi < 2; mi++)
                #pragma unroll
                for (int ni = 0; ni < 8; ni++)
                    mma8(acc[mi][ni], a[mi][0], a[mi][1], a[mi][2], a[mi][3],
                         b[ni][0], b[ni][1]);
        }
    }
    #pragma unroll
    for (int mi = 0; mi < 2; mi++) {
        int r0 = m0 + wm + mi*16 + g, r1 = r0 + 8;
        #pragma unroll
        for (int ni = 0; ni < 8; ni++) {
            int n = n0 + wn + ni*8 + 2*t;
            float bv0 = 0.f, bv1 = 0.f;
            if (bias) { if (n < N) bv0 = bias[n]; if (n+1 < N) bv1 = bias[n+1]; }
            float v00 = acc[mi][ni][0] + bv0, v01 = acc[mi][ni][1] + bv1;
            float v10 = acc[mi][ni][2] + bv0, v11 = acc[mi][ni][3] + bv1;
            if (relu) {
                v00 = fmaxf(v00, 0.f); v01 = fmaxf(v01, 0.f);
                v10 = fmaxf(v10, 0.f); v11 = fmaxf(v11, 0.f);
            }
            if (yout) {
                if (r0 < M) {
                    if (n < N)   C[(size_t)r0*ldc + n]   = tcw[to[r0]*NC + n]   * v00;
                    if (n+1 < N) C[(size_t)r0*ldc + n+1] = tcw[to[r0]*NC + n+1] * v01;
                }
                if (r1 < M) {
                    if (n < N)   C[(size_t)r1*ldc + n]   = tcw[to[r1]*NC + n]   * v10;
                    if (n+1 < N) C[(size_t)r1*ldc + n+1] = tcw[to[r1]*NC + n+1] * v11;
                }
            } else {
                v00 = rtf(v00); v01 = rtf(v01); v10 = rtf(v10); v11 = rtf(v11);
                if (r0 < M) {
                    if (n < N)   C[(size_t)r0*ldc + n]   = v00;
                    if (n+1 < N) C[(size_t)r0*ldc + n+1] = v01;
                }
                if (r1 < M) {
                    if (n < N)   C[(size_t)r1*ldc + n]   = v10;
                    if (n+1 < N) C[(size_t)r1*ldc + n+1] = v11;
                }
            }
        }
    }
}

// ---------------- attention (cp.async, streaming softmax, raw loads) -------
#define ATTN_SMEM ((2*128*36*2)*4)
#define QS(p,r,c) smp[(p)*4608 + (r)*36 + (c)]
#define KS(p,r,c) smp[9216 + (p)*4608 + (r)*36 + (c)]
__global__ void __launch_bounds__(256, 2) k_attn3() {
    extern __shared__ float smp[];
    __shared__ float sm_m[2][128];
    __shared__ float sm_z[2][128];
    int tid = threadIdx.x;
    int w = tid >> 5, lane = tid & 31, g = lane >> 2, t = lane & 3;
    int wm = (w & 3) * 32, wn = (w >> 2) * 64;
    int half = w >> 2;
    int i0 = blockIdx.x*128;
    int split = blockIdx.y;
    const float sc = 0.044194173824159216f;   // 1/sqrt(512)
    uint32_t sb = (uint32_t)__cvta_generic_to_shared(smp);

    auto fillQ = [&](int p, int k0) {
        #pragma unroll
        for (int r = 0; r < 4; r++) {
            int idx = tid + 256*r;
            int row = idx >> 3, fc = idx & 7;
            cpa16(sb + (uint32_t)(p*4608 + row*36 + fc*4)*4u,
                  &g_q[(size_t)(i0+row)*DD + k0 + fc*4], 16);
        }
    };
    auto fillK = [&](int p, int j0v, int k0) {
        #pragma unroll
        for (int r = 0; r < 4; r++) {
            int idx = tid + 256*r;
            int row = idx >> 3, fc = idx & 7;
            int gj = j0v + row;
            int sz = gj < NS ? 16 : 0;
            const float* src = sz ? &g_kall[(size_t)gj*DD + k0 + fc*4] : g_kall;
            cpa16(sb + (uint32_t)(9216 + p*4608 + row*36 + fc*4)*4u, src, sz);
        }
    };

    float mr[2][2] = {{-1e30f,-1e30f},{-1e30f,-1e30f}};
    float zr[2][2] = {{0.f,0.f},{0.f,0.f}};
    int jt0 = split*JPT;
    int jt1 = jt0 + JPT; if (jt1 > NJT) jt1 = NJT;
    int cg = 0;
    fillQ(0, 0); fillK(0, jt0*128, 0); CPA_COMMIT();
    for (int jt = jt0; jt < jt1; jt++) {
        int j0 = jt*128;
        float acc[2][8][4] = {};
        for (int c = 0; c < 16; c++, cg++) {
            CPA_WAIT0();
            __syncthreads();
            int p = cg & 1;
            if (c < 15) {
                fillQ(p^1, (c+1)*32); fillK(p^1, j0, (c+1)*32); CPA_COMMIT();
            } else if (jt + 1 < jt1) {
                fillQ(p^1, 0); fillK(p^1, (jt+1)*128, 0); CPA_COMMIT();
            }
            #pragma unroll
            for (int kk = 0; kk < 32; kk += 8) {
                uint32_t a[2][4];
                #pragma unroll
                for (int mi = 0; mi < 2; mi++) {
                    a[mi][0] = __float_as_uint(QS(p, wm+mi*16+g  , kk+t));
                    a[mi][1] = __float_as_uint(QS(p, wm+mi*16+g+8, kk+t));
                    a[mi][2] = __float_as_uint(QS(p, wm+mi*16+g  , kk+t+4));
                    a[mi][3] = __float_as_uint(QS(p, wm+mi*16+g+8, kk+t+4));
                }
                uint32_t b[8][2];
                #pragma unroll
                for (int ni = 0; ni < 8; ni++) {
                    b[ni][0] = __float_as_uint(KS(p, wn+ni*8+g, kk+t));
                    b[ni][1] = __float_as_uint(KS(p, wn+ni*8+g, kk+t+4));
                }
                #pragma unroll
                for (int mi = 0; mi < 2; mi++)
                    #pragma unroll
                    for (int ni = 0; ni < 8; ni++)
                        mma8(acc[mi][ni], a[mi][0], a[mi][1], a[mi][2], a[mi][3],
                             b[ni][0], b[ni][1]);
            }
        }
        int doL = (split == 0 && jt == 0);
        #pragma unroll
        for (int mi = 0; mi < 2; mi++) {
            int r0g = i0 + wm + mi*16 + g, r1g = r0g + 8;
            float lm0 = -1e30f, lm1 = -1e30f;
            #pragma unroll
            for (int ni = 0; ni < 8; ni++) {
                int base = j0 + wn + ni*8 + 2*t;
                float v0 = (base   < NS) ? acc[mi][ni][0]*sc : -1e30f;
                float v1 = (base+1 < NS) ? acc[mi][ni][1]*sc : -1e30f;
                float v2 = (base   < NS) ? acc[mi][ni][2]*sc : -1e30f;
                float v3 = (base+1 < NS) ? acc[mi][ni][3]*sc : -1e30f;
                acc[mi][ni][0] = v0; acc[mi][ni][1] = v1;
                acc[mi][ni][2] = v2; acc[mi][ni][3] = v3;
                if (doL) {
                    int c0 = wn + ni*8 + 2*t;
                    if (c0 < TC) {
                        g_l69[(size_t)r0g*TC + c0] = v0;
                        g_l69[(size_t)r1g*TC + c0] = v2;
                    }
                    if (c0 + 1 < TC) {
                        g_l69[(size_t)r0g*TC + c0+1] = v1;
                        g_l69[(size_t)r1g*TC + c0+1] = v3;
                    }
                }
                lm0 = fmaxf(lm0, fmaxf(v0, v1));
                lm1 = fmaxf(lm1, fmaxf(v2, v3));
            }
            lm0 = fmaxf(lm0, __shfl_xor_sync(0xffffffffu, lm0, 1));
            lm0 = fmaxf(lm0, __shfl_xor_sync(0xffffffffu, lm0, 2));
            lm1 = fmaxf(lm1, __shfl_xor_sync(0xffffffffu, lm1, 1));
            lm1 = fmaxf(lm1, __shfl_xor_sync(0xffffffffu, lm1, 2));
            float nm0 = fmaxf(mr[mi][0], lm0), nm1 = fmaxf(mr[mi][1], lm1);
            float p0 = 0.f, p1 = 0.f;
            #pragma unroll
            for (int ni = 0; ni < 8; ni++) {
                p0 += __expf(acc[mi][ni][0]-nm0) + __expf(acc[mi][ni][1]-nm0);
                p1 += __expf(acc[mi][ni][2]-nm1) + __expf(acc[mi][ni][3]-nm1);
            }
            p0 += __shfl_xor_sync(0xffffffffu, p0, 1);
            p0 += __shfl_xor_sync(0xffffffffu, p0, 2);
            p1 += __shfl_xor_sync(0xffffffffu, p1, 1);
            p1 += __shfl_xor_sync(0xffffffffu, p1, 2);
            zr[mi][0] = zr[mi][0]*__expf(mr[mi][0] - nm0) + p0; mr[mi][0] = nm0;
            zr[mi][1] = zr[mi][1]*__expf(mr[mi][1] - nm1) + p1; mr[mi][1] = nm1;
        }
    }
    if (t == 0) {
        #pragma unroll
        for (int mi = 0; mi < 2; mi++) {
            int r = wm + mi*16 + g;
            sm_m[half][r]     = mr[mi][0];  sm_z[half][r]     = zr[mi][0];
            sm_m[half][r + 8] = mr[mi][1];  sm_z[half][r + 8] = zr[mi][1];
        }
    }
    __syncthreads();
    if (tid < 128) {
        float m0 = sm_m[0][tid], m1 = sm_m[1][tid];
        float m = fmaxf(m0, m1);
        float z = sm_z[0][tid]*__expf(m0 - m) + sm_z[1][tid]*__expf(m1 - m);
        g_mp[split*BN + i0 + tid] = m;
        g_zp[split*BN + i0 + tid] = z;
    }
}

// ---------------- combine splits + first-69 softmax -> cf (tf32) ----------
__global__ void k_cf() {
    int i = blockIdx.x;
    int j = threadIdx.x;
    __shared__ float sh[2];
    if (j == 0) {
        float m = -1e30f;
        #pragma unroll
        for (int s = 0; s < NSPL; s++) m = fmaxf(m, g_mp[s*BN + i]);
        float z = 0.f;
        #pragma unroll
        for (int s = 0; s < NSPL; s++) z += g_zp[s*BN + i]*__expf(g_mp[s*BN + i] - m);
        sh[0] = m; sh[1] = 1.f/z;
    }
    __syncthreads();
    if (j < CFLD)
        g_cf[i*CFLD + j] = (j < TC) ? rtf(__expf(g_l69[i*TC + j] - sh[0]) * sh[1]) : 0.f;
}

// ---------------- GNN tc-rows partial: C69 += cf^T @ hw_x ----------------
__global__ void k_outtc() {
    __shared__ float cfs[64][72];
    __shared__ float hws[64][64];
    int t = threadIdx.x, tx = t & 63, ty = t >> 6;
    int n0 = blockIdx.x*64;
    int b0 = blockIdx.y*256;
    float acc[18];
    #pragma unroll
    for (int k = 0; k < 18; k++) acc[k] = 0.f;
    for (int bc = 0; bc < 256; bc += 64) {
        int bb = b0 + bc;
        for (int i = t; i < 64*TC; i += 256) {
            int r = i/TC, k = i%TC;
            cfs[r][k] = g_cf[(size_t)(bb+r)*CFLD + k];
        }
        for (int i = t; i < 64*64; i += 256) {
            int r = i >> 6, n = i & 63;
            hws[r][n] = g_hw[(size_t)(TC+bb+r)*DD + n0 + n];
        }
        __syncthreads();
        for (int r = 0; r < 64; r++) {
            float hv = hws[r][tx];
            #pragma unroll
            for (int k = 0; k < 18; k++) {
                int m = ty + 4*k;
                if (m < TC) acc[k] += cfs[r][m]*hv;
            }
        }
        __syncthreads();
    }
    #pragma unroll
    for (int k = 0; k < 18; k++) {
        int m = ty + 4*k;
        if (m < TC) atomicAdd(&g_C69[m*DD + n0 + tx], acc[k]);
    }
}

// ---------------- finalize tc rows (layer 0 only), tf32-rounded ------------
__global__ void k_fintc(const float* __restrict__ gb) {
    int m = blockIdx.x;      // 69
    int n = threadIdx.x;     // 512
    float v = g_C69[m*DD + n];
    for (int j = 0; j < TC; j++)
        v += g_adj[m*TC+j] * g_hw[j*DD + n];
    v += gb[n];
    g_hB[m*DD + n] = rtf(fmaxf(v, 0.f));
}

// ---------------- labels ----------------
__global__ void k_labels(const int* __restrict__ lb, float* out, int off, int out_size) {
    int i = blockIdx.x*256 + threadIdx.x;
    if (i < BN && off + i < out_size) out[off + i] = (float)lb[i];
}

// ======================== host ========================
extern "C" void kernel_launch(void* const* d_in, const int* in_sizes, int n_in,
                              void* d_out, int out_size) {
    const float* x    = (const float*)d_in[0];
    const int*   lb   = (const int*)d_in[1];
    const int*   to   = (const int*)d_in[2];
    const float* trep = (const float*)d_in[3];
    const float* cpro = (const float*)d_in[4];
    const float* tw   = (const float*)d_in[5];
    const float* tb   = (const float*)d_in[6];
    const float* cw   = (const float*)d_in[7];
    const float* cb   = (const float*)d_in[8];
    const float* wq   = (const float*)d_in[9];
    const float* wk   = (const float*)d_in[10];
    const float* gw   = (const float*)d_in[11];
    const float* gb   = (const float*)d_in[12];
    const float* bw   = (const float*)d_in[13];
    const float* bb   = (const float*)d_in[14];
    const float* tcw  = (const float*)d_in[15];
    float* out = (float*)d_out;

    cudaFuncSetAttribute(k_gemm3, cudaFuncAttributeMaxDynamicSharedMemorySize, GEMM_SMEM);
    cudaFuncSetAttribute(k_attn3, cudaFuncAttributeMaxDynamicSharedMemorySize, ATTN_SMEM);

    float* wRp = nullptr;
    cudaGetSymbolAddress((void**)&wRp, g_wR);
    const float* wqR  = wRp;
    const float* wkR  = wRp + DD*DD;
    const float* gw1R = wRp + 2*DD*DD;
    const float* gw2R = wRp + 3*DD*DD;

    int y_off = (out_size > BN*NC) ? 1 : 0;
    int lbl_off = y_off + BN*NC;

    // 1-3. xm; prep (zeros + rounded weights); count
    k_xm<<<16384, 128>>>(x);
    k_prep<<<(DD*DD + 255)/256, 256>>>(wq, wk, gw, bw);
    k_count<<<16, 256>>>(to, lb);
    // 4. q = xm@wqR (profiling beacon)
    k_gemm3<<<dim3(4, 32), 256, GEMM_SMEM>>>(0, 0, wqR, 0, BN, DD, DD, DD, DD, DD,
                                             nullptr, 0, nullptr, nullptr, nullptr,
                                             0, 0, nullptr, 0, 0, 0, 0, nullptr, 0, 0);
    // 5-6. segment means -> t1/c1
    k_segsum<<<dim3(8, 64), 256>>>(to, lb);
    k_t1c1<<<(TC*DD + 255)/256, 256>>>(trep, cpro);
    // fork: graph kernels on side stream
    cudaEventRecord(g_e1, 0);
    cudaStreamWaitEvent(g_s1, g_e1, 0);
    k_d2cross<<<65, 128, 0, g_s1>>>();
    k_tg<<<16, 32, 0, g_s1>>>(tw, tb);
    k_cg<<<dim3(65, 17), 128, 0, g_s1>>>(cw, cb);
    if (y_off) k_ae<<<1, 65, 0, g_s1>>>(out);
    // main: fused kall = hA@wkR | hw = hA@gw1R
    k_gemm3<<<dim3(4, 66), 256, GEMM_SMEM>>>(1, 0, wkR, 1, NS, DD, DD, DD, DD, DD,
                                             nullptr, 0, nullptr, nullptr, nullptr,
                                             33, 1, gw1R, 2, NS, 0, 0, nullptr, 0, 0);
    // main: attention + cf
    k_attn3<<<dim3(32, NSPL), 256, ATTN_SMEM>>>();
    k_cf<<<4096, 96>>>();
    // fork2: outtc + fintc on side stream
    cudaEventRecord(g_e2, 0);
    cudaStreamWaitEvent(g_s1, g_e2, 0);
    k_outtc<<<dim3(8, 16), 256, 0, g_s1>>>();
    k_fintc<<<69, 512, 0, g_s1>>>(gb);
    cudaEventRecord(g_e3, g_s1);
    // main: L0 x-rows = relu(cf@hw_tc + gb0)
    k_gemm3<<<dim3(4, 32), 256, GEMM_SMEM>>>(3, 1, nullptr, 3, BN, DD, CFLD, CFLD, DD, DD,
                                             gb, 1, nullptr, nullptr, nullptr,
                                             0, 0, nullptr, 0, 0, 0, 0, nullptr, 0, 0);
    // join
    cudaStreamWaitEvent(0, g_e3, 0);
    // L1: hw2 rows 0..127, then x-rows
    k_gemm3<<<dim3(4, 1), 256, GEMM_SMEM>>>(2, 0, gw2R, 2, 128, DD, DD, DD, DD, DD,
                                            nullptr, 0, nullptr, nullptr, nullptr,
                                            0, 0, nullptr, 0, 0, 0, 0, nullptr, 0, 0);
    k_gemm3<<<dim3(4, 32), 256, GEMM_SMEM>>>(3, 1, nullptr, 4, BN, DD, CFLD, CFLD, DD, DD,
                                             gb + DD, 1, nullptr, nullptr, nullptr,
                                             0, 0, nullptr, 0, 0, 0, 0, nullptr, 0, 0);
    // outputs
    k_gemm3<<<dim3(1, 32), 256, GEMM_SMEM>>>(4, 2, nullptr, 0, BN, NC, DD, DD, CFLD, NC,
                                             bb, 0, tcw, to, out + y_off,
                                             0, 0, nullptr, 0, 0, 0, 0, nullptr, 0, 0);
    k_labels<<<16, 256>>>(lb, out, lbl_off, out_size);
}

// round 12
// speedup vs baseline: 6.0596x; 1.0361x over previous
#include <cuda_runtime.h>
#include <math.h>
#include <stdint.h>

#define BN 4096
#define DD 512
#define NT 4
#define NC 65
#define TC 69          // NT + NC
#define NS 4165        // TC + BN
#define CFLD 72        // padded cf row stride
#define NSPL 9         // attention splits
#define NJT 33
#define JPT 4

// ---------------- scratch (device globals; no allocations) ----------------
__device__ float g_xm[BN*DD];
__device__ float g_q[BN*DD];
__device__ float g_kall[NS*DD];
__device__ float g_hA[NS*DD];
__device__ float g_hB[NS*DD];
__device__ float g_hw[NS*DD];
__device__ float g_tsum[NT*DD];
__device__ float g_csum[NC*DD];
__device__ int   g_cntT[NT];
__device__ int   g_cntC[NC];
__device__ float g_adj[TC*TC];
__device__ float g_cross[NT*NC];
__device__ float g_cf[BN*CFLD];
__device__ float g_l69[BN*TC];
__device__ float g_mp[16*BN];
__device__ float g_zp[16*BN];
__device__ float g_C69[TC*DD];
__device__ float g_bwPad[DD*CFLD];
__device__ float g_wR[4*DD*DD];   // tf32-rounded: 0=wq 1=wk 2=gw1 3=gw2

// ---------------- static stream/event resources ----------------
static cudaStream_t g_s1;
static cudaEvent_t g_eF, g_e0, g_e1, g_e2, g_e3, g_e4, g_e5;
static struct StreamInit {
    StreamInit() {
        cudaStreamCreateWithFlags(&g_s1, cudaStreamNonBlocking);
        cudaEventCreateWithFlags(&g_eF, cudaEventDisableTiming);
        cudaEventCreateWithFlags(&g_e0, cudaEventDisableTiming);
        cudaEventCreateWithFlags(&g_e1, cudaEventDisableTiming);
        cudaEventCreateWithFlags(&g_e2, cudaEventDisableTiming);
        cudaEventCreateWithFlags(&g_e3, cudaEventDisableTiming);
        cudaEventCreateWithFlags(&g_e4, cudaEventDisableTiming);
        cudaEventCreateWithFlags(&g_e5, cudaEventDisableTiming);
    }
} g_si;

// ---------------- tf32 / mma / cp.async helpers ----------------
__device__ __forceinline__ void mma8(float* c, uint32_t a0, uint32_t a1,
                                     uint32_t a2, uint32_t a3,
                                     uint32_t b0, uint32_t b1) {
    asm("mma.sync.aligned.m16n8k8.row.col.f32.tf32.tf32.f32 "
        "{%0,%1,%2,%3},{%4,%5,%6,%7},{%8,%9},{%0,%1,%2,%3};"
        : "+f"(c[0]), "+f"(c[1]), "+f"(c[2]), "+f"(c[3])
        : "r"(a0), "r"(a1), "r"(a2), "r"(a3), "r"(b0), "r"(b1));
}
__device__ __forceinline__ float rtf(float x) {
    uint32_t u;
    asm("cvt.rna.tf32.f32 %0, %1;" : "=r"(u) : "f"(x));
    return __uint_as_float(u);
}
__device__ __forceinline__ void cpa16(uint32_t dst, const float* src, int srcBytes) {
    asm volatile("cp.async.cg.shared.global [%0], [%1], 16, %2;"
                 :: "r"(dst), "l"(src), "r"(srcBytes));
}
#define CPA_COMMIT() asm volatile("cp.async.commit_group;" ::: "memory")
#define CPA_WAIT0()  asm volatile("cp.async.wait_group 0;" ::: "memory")

// ---------------- selectors ----------------
__device__ __forceinline__ const float* selA3(int s) {
    switch (s) {
        case 0: return g_xm;  case 1: return g_hA;  case 2: return g_hB;
        case 3: return g_cf;  case 4: return g_hA + TC*DD;
    }
    return g_xm;
}
__device__ __forceinline__ const float* selB3(int s, const float* Bp) {
    switch (s) { case 1: return g_hw; case 2: return g_bwPad; }
    return Bp;
}
__device__ __forceinline__ float* selC3(int s) {
    switch (s) {
        case 0: return g_q;  case 1: return g_kall;  case 2: return g_hw;
        case 3: return g_hB + TC*DD;  case 4: return g_hA + TC*DD;
    }
    return g_q;
}

// ---------------- xm = mean over 7x7 (tf32-rounded); src rows 69.. ---------
__global__ void k_xm(const float* __restrict__ x) {
    __shared__ float buf[4][32*49];
    int w = threadIdx.x >> 5, lane = threadIdx.x & 31;
    int base = (blockIdx.x*4 + w) * 32;
    const float* src = x + (size_t)base*49;
    float* b = buf[w];
    #pragma unroll
    for (int t = 0; t < 49; t++) b[lane + 32*t] = src[lane + 32*t];
    __syncwarp();
    float s = 0.f;
    #pragma unroll
    for (int t = 0; t < 49; t++) s += b[lane*49 + t];
    s = rtf(s * (1.f/49.f));
    int seg = base + lane;
    g_xm[seg] = s;
    g_hA[TC*DD + seg] = s;
}

// ---------------- prep: zeros, pad+round base_w, round all weights ---------
__global__ void k_prep(const float* __restrict__ wq, const float* __restrict__ wk,
                       const float* __restrict__ gw, const float* __restrict__ bw) {
    int i = blockIdx.x*256 + threadIdx.x;
    if (i < DD*DD) {
        g_wR[i]           = rtf(wq[i]);
        g_wR[DD*DD + i]   = rtf(wk[i]);
        g_wR[2*DD*DD + i] = rtf(gw[i]);
        g_wR[3*DD*DD + i] = rtf(gw[DD*DD + i]);
    }
    if (i < NT*DD) g_tsum[i] = 0.f;
    if (i < NC*DD) g_csum[i] = 0.f;
    if (i < NT) g_cntT[i] = 0;
    if (i < NC) g_cntC[i] = 0;
    if (i < TC*DD) g_C69[i] = 0.f;
    if (i < DD*CFLD) {
        int r = i / CFLD, c = i - r*CFLD;
        g_bwPad[i] = (c < NC) ? rtf(bw[r*NC + c]) : 0.f;
    }
}
__global__ void k_count(const int* __restrict__ to, const int* __restrict__ lb) {
    int i = blockIdx.x*256 + threadIdx.x;
    if (i < BN) { atomicAdd(&g_cntT[to[i]], 1); atomicAdd(&g_cntC[lb[i]], 1); }
}
__global__ void k_segsum(const int* __restrict__ to, const int* __restrict__ lb) {
    __shared__ float sT[NT][64];
    __shared__ float sC[NC][64];
    int t = threadIdx.x;
    int cr = t & 63, rr = t >> 6;
    int r0 = blockIdx.y * 64, c0 = blockIdx.x * 64;
    for (int i = t; i < NT*64; i += 256) ((float*)sT)[i] = 0.f;
    for (int i = t; i < NC*64; i += 256) ((float*)sC)[i] = 0.f;
    __syncthreads();
    for (int r = r0 + rr; r < r0 + 64; r += 4) {
        int tt = to[r], cc = lb[r];
        float v = g_xm[r*DD + c0 + cr];
        atomicAdd(&sT[tt][cr], v);
        atomicAdd(&sC[cc][cr], v);
    }
    __syncthreads();
    for (int i = t; i < NT*64; i += 256)
        atomicAdd(&g_tsum[(i>>6)*DD + c0 + (i&63)], ((float*)sT)[i]);
    for (int i = t; i < NC*64; i += 256)
        atomicAdd(&g_csum[(i>>6)*DD + c0 + (i&63)], ((float*)sC)[i]);
}
__global__ void k_t1c1(const float* __restrict__ trep, const float* __restrict__ cpro) {
    int i = blockIdx.x*256 + threadIdx.x;
    if (i >= TC*DD) return;
    int seg = i / DD, d = i % DD;
    float v;
    if (seg < NT) {
        float cnt = fmaxf((float)g_cntT[seg], 1.f);
        v = 0.9f*trep[i] + 0.1f*g_tsum[i]/cnt;
    } else {
        int c = seg - NT;
        float cnt = fmaxf((float)g_cntC[c], 1.f);
        v = 0.9f*cpro[c*DD+d] + 0.1f*g_csum[c*DD+d]/cnt;
    }
    g_hA[i] = rtf(v);
}

// ---------------- graph kernels ----------------
__global__ void k_d2cross() {
    int c = blockIdx.x;
    int w = threadIdx.x >> 5, lane = threadIdx.x & 31;
    __shared__ float sd2[NT];
    const float* t1 = g_hA;
    const float* c1 = g_hA + NT*DD;
    float s = 0.f;
    for (int d = lane; d < DD; d += 32) {
        float df = t1[w*DD+d] - c1[c*DD+d];
        s += df*df;
    }
    #pragma unroll
    for (int o = 16; o; o >>= 1) s += __shfl_xor_sync(0xffffffffu, s, o);
    if (lane == 0) sd2[w] = s;
    __syncthreads();
    if (threadIdx.x == 0) {
        float l[NT], mx = -1e30f;
        for (int t = 0; t < NT; t++) { l[t] = -sd2[t]*(1.f/16.f); mx = fmaxf(mx, l[t]); }
        float Z = 0.f;
        for (int t = 0; t < NT; t++) { l[t] = expf(l[t]-mx); Z += l[t]; }
        for (int t = 0; t < NT; t++) {
            float p = l[t]/Z;
            g_cross[t*NC + c] = p;
            g_adj[t*TC + NT + c] = p;
            g_adj[(NT+c)*TC + t] = p;
        }
    }
}
__global__ void k_tg(const float* __restrict__ tw, const float* __restrict__ tb) {
    int i = blockIdx.x >> 2, j = blockIdx.x & 3;
    int lane = threadIdx.x;
    const float* t1 = g_hA;
    float s = 0.f;
    for (int d = lane; d < DD; d += 32)
        s += fabsf(t1[i*DD+d]-t1[j*DD+d]) * tw[d];
    #pragma unroll
    for (int o = 16; o; o >>= 1) s += __shfl_xor_sync(0xffffffffu, s, o);
    if (lane == 0) {
        float v = 1.f/(1.f+expf(-(s + tb[0])));
        if (i == j) v = 0.f;
        g_adj[i*TC+j] = v;
    }
}
__global__ void k_cg(const float* __restrict__ cw, const float* __restrict__ cb) {
    int i = blockIdx.x;
    int w = threadIdx.x >> 5, lane = threadIdx.x & 31;
    int j = blockIdx.y*4 + w;
    if (j >= NC) return;
    const float* c1 = g_hA + NT*DD;
    float s = 0.f;
    for (int d = lane; d < DD; d += 32)
        s += fabsf(c1[i*DD+d]-c1[j*DD+d]) * cw[d];
    #pragma unroll
    for (int o = 16; o; o >>= 1) s += __shfl_xor_sync(0xffffffffu, s, o);
    if (lane == 0) {
        float v = 1.f/(1.f+expf(-(s + cb[0])));
        if (i == j) v = 0.f;
        g_adj[(NT+i)*TC + NT+j] = v;
    }
}
__global__ void k_ae(float* out) {
    __shared__ float s[NC];
    int c = threadIdx.x;
    float a = 0.f;
    for (int t = 0; t < NT; t++) { float p = g_cross[t*NC+c]; a += p*logf(p); }
    s[c] = a;
    __syncthreads();
    if (c == 0) { float r = 0.f; for (int i = 0; i < NC; i++) r += s[i]; out[0] = r/(float)NC; }
}

// ---------------- tf32 GEMM (cp.async double-buffered, NO hot-loop CVT) ----
#define GEMM_SMEM ((2*128*36 + 2*32*136)*4)
#define AS(p,r,c) smp[(p)*4608 + (r)*36 + (c)]
#define BS(p,r,c) smp[9216 + (p)*4352 + (r)*136 + (c)]
__global__ void __launch_bounds__(256, 2) k_gemm3(
        int aSel, int bSel, const float* __restrict__ Bp, int cSel,
        int M, int N, int K, int lda, int ldb, int ldc,
        const float* __restrict__ bias, int relu,
        const float* __restrict__ tcw, const int* __restrict__ to,
        float* yout,
        int ySplit, int aSel2, const float* __restrict__ Bp2, int cSel2, int M2,
        int ySplit2, int aSel3, const float* __restrict__ Bp3, int cSel3, int M3) {
    extern __shared__ float smp[];
    int by = blockIdx.y;
    if (ySplit2 > 0 && by >= ySplit2) {
        aSel = aSel3; Bp = Bp3; cSel = cSel3; M = M3; by -= ySplit2;
    } else if (ySplit > 0 && by >= ySplit) {
        aSel = aSel2; Bp = Bp2; cSel = cSel2; M = M2; by -= ySplit;
    }
    const float* A = selA3(aSel);
    const float* B = selB3(bSel, Bp);
    float* C = yout ? yout : selC3(cSel);
    int tid = threadIdx.x;
    int w = tid >> 5, lane = tid & 31, g = lane >> 2, t = lane & 3;
    int wm = (w & 3) * 32, wn = (w >> 2) * 64;
    int m0 = by*128, n0 = blockIdx.x*128;
    uint32_t sb = (uint32_t)__cvta_generic_to_shared(smp);

    auto fillA = [&](int p, int k0) {
        #pragma unroll
        for (int r = 0; r < 4; r++) {
            int idx = tid + 256*r;
            int row = idx >> 3, fc = idx & 7;
            int gm = m0 + row, gk = k0 + fc*4;
            int sz = 16;
            if (gm >= M) sz = 0;
            int rem = (K - gk)*4;
            if (rem < sz) sz = rem < 0 ? 0 : rem;
            const float* src = sz > 0 ? &A[(size_t)gm*lda + gk] : A;
            cpa16(sb + (uint32_t)(p*4608 + row*36 + fc*4)*4u, src, sz);
        }
    };
    auto fillB = [&](int p, int k0) {
        #pragma unroll
        for (int r = 0; r < 4; r++) {
            int idx = tid + 256*r;
            int row = idx >> 5, c4 = (idx & 31)*4;
            int gk = k0 + row, gn = n0 + c4;
            int sz = 16;
            if (gk >= K) sz = 0;
            int rem = (N - gn)*4;
            if (rem < sz) sz = rem < 0 ? 0 : rem;
            const float* src = sz > 0 ? &B[(size_t)gk*ldb + gn] : B;
            cpa16(sb + (uint32_t)(9216 + p*4352 + row*136 + c4)*4u, src, sz);
        }
    };

    float acc[2][8][4] = {};
    int nk = (K + 31) >> 5;
    fillA(0, 0); fillB(0, 0); CPA_COMMIT();
    for (int kc = 0; kc < nk; kc++) {
        CPA_WAIT0();
        __syncthreads();
        if (kc + 1 < nk) { fillA((kc+1)&1, (kc+1)*32); fillB((kc+1)&1, (kc+1)*32); CPA_COMMIT(); }
        int p = kc & 1;
        #pragma unroll
        for (int kk = 0; kk < 32; kk += 8) {
            uint32_t a[2][4];
            #pragma unroll
            for (int mi = 0; mi < 2; mi++) {
                a[mi][0] = __float_as_uint(AS(p, wm+mi*16+g  , kk+t));
                a[mi][1] = __float_as_uint(AS(p, wm+mi*16+g+8, kk+t));
                a[mi][2] = __float_as_uint(AS(p, wm+mi*16+g  , kk+t+4));
                a[mi][3] = __float_as_uint(AS(p, wm+mi*16+g+8, kk+t+4));
            }
            uint32_t b[8][2];
            #pragma unroll
            for (int ni = 0; ni < 8; ni++) {
                b[ni][0] = __float_as_uint(BS(p, kk+t  , wn+ni*8+g));
                b[ni][1] = __float_as_uint(BS(p, kk+t+4, wn+ni*8+g));
            }
            #pragma unroll
            for (int mi = 0; mi < 2; mi++)
                #pragma unroll
                for (int ni = 0; ni < 8; ni++)
                    mma8(acc[mi][ni], a[mi][0], a[mi][1], a[mi][2], a[mi][3],
                         b[ni][0], b[ni][1]);
        }
    }
    #pragma unroll
    for (int mi = 0; mi < 2; mi++) {
        int r0 = m0 + wm + mi*16 + g, r1 = r0 + 8;
        #pragma unroll
        for (int ni = 0; ni < 8; ni++) {
            int n = n0 + wn + ni*8 + 2*t;
            float bv0 = 0.f, bv1 = 0.f;
            if (bias) { if (n < N) bv0 = bias[n]; if (n+1 < N) bv1 = bias[n+1]; }
            float v00 = acc[mi][ni][0] + bv0, v01 = acc[mi][ni][1] + bv1;
            float v10 = acc[mi][ni][2] + bv0, v11 = acc[mi][ni][3] + bv1;
            if (relu) {
                v00 = fmaxf(v00, 0.f); v01 = fmaxf(v01, 0.f);
                v10 = fmaxf(v10, 0.f); v11 = fmaxf(v11, 0.f);
            }
            if (yout) {
                if (r0 < M) {
                    if (n < N)   C[(size_t)r0*ldc + n]   = tcw[to[r0]*NC + n]   * v00;
                    if (n+1 < N) C[(size_t)r0*ldc + n+1] = tcw[to[r0]*NC + n+1] * v01;
                }
                if (r1 < M) {
                    if (n < N)   C[(size_t)r1*ldc + n]   = tcw[to[r1]*NC + n]   * v10;
                    if (n+1 < N) C[(size_t)r1*ldc + n+1] = tcw[to[r1]*NC + n+1] * v11;
                }
            } else {
                v00 = rtf(v00); v01 = rtf(v01); v10 = rtf(v10); v11 = rtf(v11);
                if (r0 < M) {
                    if (n < N)   C[(size_t)r0*ldc + n]   = v00;
                    if (n+1 < N) C[(size_t)r0*ldc + n+1] = v01;
                }
                if (r1 < M) {
                    if (n < N)   C[(size_t)r1*ldc + n]   = v10;
                    if (n+1 < N) C[(size_t)r1*ldc + n+1] = v11;
                }
            }
        }
    }
}

// ---------------- attention (cp.async, streaming softmax, raw loads) -------
#define ATTN_SMEM ((2*128*36*2)*4)
#define QS(p,r,c) smp[(p)*4608 + (r)*36 + (c)]
#define KS(p,r,c) smp[9216 + (p)*4608 + (r)*36 + (c)]
__global__ void __launch_bounds__(256, 2) k_attn3() {
    extern __shared__ float smp[];
    __shared__ float sm_m[2][128];
    __shared__ float sm_z[2][128];
    int tid = threadIdx.x;
    int w = tid >> 5, lane = tid & 31, g = lane >> 2, t = lane & 3;
    int wm = (w & 3) * 32, wn = (w >> 2) * 64;
    int half = w >> 2;
    int i0 = blockIdx.x*128;
    int split = blockIdx.y;
    const float sc = 0.044194173824159216f;   // 1/sqrt(512)
    uint32_t sb = (uint32_t)__cvta_generic_to_shared(smp);

    auto fillQ = [&](int p, int k0) {
        #pragma unroll
        for (int r = 0; r < 4; r++) {
            int idx = tid + 256*r;
            int row = idx >> 3, fc = idx & 7;
            cpa16(sb + (uint32_t)(p*4608 + row*36 + fc*4)*4u,
                  &g_q[(size_t)(i0+row)*DD + k0 + fc*4], 16);
        }
    };
    auto fillK = [&](int p, int j0v, int k0) {
        #pragma unroll
        for (int r = 0; r < 4; r++) {
            int idx = tid + 256*r;
            int row = idx >> 3, fc = idx & 7;
            int gj = j0v + row;
            int sz = gj < NS ? 16 : 0;
            const float* src = sz ? &g_kall[(size_t)gj*DD + k0 + fc*4] : g_kall;
            cpa16(sb + (uint32_t)(9216 + p*4608 + row*36 + fc*4)*4u, src, sz);
        }
    };

    float mr[2][2] = {{-1e30f,-1e30f},{-1e30f,-1e30f}};
    float zr[2][2] = {{0.f,0.f},{0.f,0.f}};
    int jt0 = split*JPT;
    int jt1 = jt0 + JPT; if (jt1 > NJT) jt1 = NJT;
    int cg = 0;
    fillQ(0, 0); fillK(0, jt0*128, 0); CPA_COMMIT();
    for (int jt = jt0; jt < jt1; jt++) {
        int j0 = jt*128;
        float acc[2][8][4] = {};
        for (int c = 0; c < 16; c++, cg++) {
            CPA_WAIT0();
            __syncthreads();
            int p = cg & 1;
            if (c < 15) {
                fillQ(p^1, (c+1)*32); fillK(p^1, j0, (c+1)*32); CPA_COMMIT();
            } else if (jt + 1 < jt1) {
                fillQ(p^1, 0); fillK(p^1, (jt+1)*128, 0); CPA_COMMIT();
            }
            #pragma unroll
            for (int kk = 0; kk < 32; kk += 8) {
                uint32_t a[2][4];
                #pragma unroll
                for (int mi = 0; mi < 2; mi++) {
                    a[mi][0] = __float_as_uint(QS(p, wm+mi*16+g  , kk+t));
                    a[mi][1] = __float_as_uint(QS(p, wm+mi*16+g+8, kk+t));
                    a[mi][2] = __float_as_uint(QS(p, wm+mi*16+g  , kk+t+4));
                    a[mi][3] = __float_as_uint(QS(p, wm+mi*16+g+8, kk+t+4));
                }
                uint32_t b[8][2];
                #pragma unroll
                for (int ni = 0; ni < 8; ni++) {
                    b[ni][0] = __float_as_uint(KS(p, wn+ni*8+g, kk+t));
                    b[ni][1] = __float_as_uint(KS(p, wn+ni*8+g, kk+t+4));
                }
                #pragma unroll
                for (int mi = 0; mi < 2; mi++)
                    #pragma unroll
                    for (int ni = 0; ni < 8; ni++)
                        mma8(acc[mi][ni], a[mi][0], a[mi][1], a[mi][2], a[mi][3],
                             b[ni][0], b[ni][1]);
            }
        }
        int doL = (split == 0 && jt == 0);
        #pragma unroll
        for (int mi = 0; mi < 2; mi++) {
            int r0g = i0 + wm + mi*16 + g, r1g = r0g + 8;
            float lm0 = -1e30f, lm1 = -1e30f;
            #pragma unroll
            for (int ni = 0; ni < 8; ni++) {
                int base = j0 + wn + ni*8 + 2*t;
                float v0 = (base   < NS) ? acc[mi][ni][0]*sc : -1e30f;
                float v1 = (base+1 < NS) ? acc[mi][ni][1]*sc : -1e30f;
                float v2 = (base   < NS) ? acc[mi][ni][2]*sc : -1e30f;
                float v3 = (base+1 < NS) ? acc[mi][ni][3]*sc : -1e30f;
                acc[mi][ni][0] = v0; acc[mi][ni][1] = v1;
                acc[mi][ni][2] = v2; acc[mi][ni][3] = v3;
                if (doL) {
                    int c0 = wn + ni*8 + 2*t;
                    if (c0 < TC) {
                        g_l69[(size_t)r0g*TC + c0] = v0;
                        g_l69[(size_t)r1g*TC + c0] = v2;
                    }
                    if (c0 + 1 < TC) {
                        g_l69[(size_t)r0g*TC + c0+1] = v1;
                        g_l69[(size_t)r1g*TC + c0+1] = v3;
                    }
                }
                lm0 = fmaxf(lm0, fmaxf(v0, v1));
                lm1 = fmaxf(lm1, fmaxf(v2, v3));
            }
            lm0 = fmaxf(lm0, __shfl_xor_sync(0xffffffffu, lm0, 1));
            lm0 = fmaxf(lm0, __shfl_xor_sync(0xffffffffu, lm0, 2));
            lm1 = fmaxf(lm1, __shfl_xor_sync(0xffffffffu, lm1, 1));
            lm1 = fmaxf(lm1, __shfl_xor_sync(0xffffffffu, lm1, 2));
            float nm0 = fmaxf(mr[mi][0], lm0), nm1 = fmaxf(mr[mi][1], lm1);
            float p0 = 0.f, p1 = 0.f;
            #pragma unroll
            for (int ni = 0; ni < 8; ni++) {
                p0 += __expf(acc[mi][ni][0]-nm0) + __expf(acc[mi][ni][1]-nm0);
                p1 += __expf(acc[mi][ni][2]-nm1) + __expf(acc[mi][ni][3]-nm1);
            }
            p0 += __shfl_xor_sync(0xffffffffu, p0, 1);
            p0 += __shfl_xor_sync(0xffffffffu, p0, 2);
            p1 += __shfl_xor_sync(0xffffffffu, p1, 1);
            p1 += __shfl_xor_sync(0xffffffffu, p1, 2);
            zr[mi][0] = zr[mi][0]*__expf(mr[mi][0] - nm0) + p0; mr[mi][0] = nm0;
            zr[mi][1] = zr[mi][1]*__expf(mr[mi][1] - nm1) + p1; mr[mi][1] = nm1;
        }
    }
    if (t == 0) {
        #pragma unroll
        for (int mi = 0; mi < 2; mi++) {
            int r = wm + mi*16 + g;
            sm_m[half][r]     = mr[mi][0];  sm_z[half][r]     = zr[mi][0];
            sm_m[half][r + 8] = mr[mi][1];  sm_z[half][r + 8] = zr[mi][1];
        }
    }
    __syncthreads();
    if (tid < 128) {
        float m0 = sm_m[0][tid], m1 = sm_m[1][tid];
        float m = fmaxf(m0, m1);
        float z = sm_z[0][tid]*__expf(m0 - m) + sm_z[1][tid]*__expf(m1 - m);
        g_mp[split*BN + i0 + tid] = m;
        g_zp[split*BN + i0 + tid] = z;
    }
}

// ---------------- combine splits + first-69 softmax -> cf (tf32) ----------
__global__ void k_cf() {
    int i = blockIdx.x;
    int j = threadIdx.x;
    __shared__ float sh[2];
    if (j == 0) {
        float m = -1e30f;
        #pragma unroll
        for (int s = 0; s < NSPL; s++) m = fmaxf(m, g_mp[s*BN + i]);
        float z = 0.f;
        #pragma unroll
        for (int s = 0; s < NSPL; s++) z += g_zp[s*BN + i]*__expf(g_mp[s*BN + i] - m);
        sh[0] = m; sh[1] = 1.f/z;
    }
    __syncthreads();
    if (j < CFLD)
        g_cf[i*CFLD + j] = (j < TC) ? rtf(__expf(g_l69[i*TC + j] - sh[0]) * sh[1]) : 0.f;
}

// ---------------- GNN tc-rows partial: C69 += cf^T @ hw_x ----------------
__global__ void k_outtc() {
    __shared__ float cfs[64][72];
    __shared__ float hws[64][64];
    int t = threadIdx.x, tx = t & 63, ty = t >> 6;
    int n0 = blockIdx.x*64;
    int b0 = blockIdx.y*256;
    float acc[18];
    #pragma unroll
    for (int k = 0; k < 18; k++) acc[k] = 0.f;
    for (int bc = 0; bc < 256; bc += 64) {
        int bb = b0 + bc;
        for (int i = t; i < 64*TC; i += 256) {
            int r = i/TC, k = i%TC;
            cfs[r][k] = g_cf[(size_t)(bb+r)*CFLD + k];
        }
        for (int i = t; i < 64*64; i += 256) {
            int r = i >> 6, n = i & 63;
            hws[r][n] = g_hw[(size_t)(TC+bb+r)*DD + n0 + n];
        }
        __syncthreads();
        for (int r = 0; r < 64; r++) {
            float hv = hws[r][tx];
            #pragma unroll
            for (int k = 0; k < 18; k++) {
                int m = ty + 4*k;
                if (m < TC) acc[k] += cfs[r][m]*hv;
            }
        }
        __syncthreads();
    }
    #pragma unroll
    for (int k = 0; k < 18; k++) {
        int m = ty + 4*k;
        if (m < TC) atomicAdd(&g_C69[m*DD + n0 + tx], acc[k]);
    }
}

// ---------------- finalize tc rows (layer 0 only), tf32-rounded ------------
__global__ void k_fintc(const float* __restrict__ gb) {
    int m = blockIdx.x;      // 69
    int n = threadIdx.x;     // 512
    float v = g_C69[m*DD + n];
    for (int j = 0; j < TC; j++)
        v += g_adj[m*TC+j] * g_hw[j*DD + n];
    v += gb[n];
    g_hB[m*DD + n] = rtf(fmaxf(v, 0.f));
}

// ---------------- labels ----------------
__global__ void k_labels(const int* __restrict__ lb, float* out, int off, int out_size) {
    int i = blockIdx.x*256 + threadIdx.x;
    if (i < BN && off + i < out_size) out[off + i] = (float)lb[i];
}

// ======================== host ========================
extern "C" void kernel_launch(void* const* d_in, const int* in_sizes, int n_in,
                              void* d_out, int out_size) {
    const float* x    = (const float*)d_in[0];
    const int*   lb   = (const int*)d_in[1];
    const int*   to   = (const int*)d_in[2];
    const float* trep = (const float*)d_in[3];
    const float* cpro = (const float*)d_in[4];
    const float* tw   = (const float*)d_in[5];
    const float* tb   = (const float*)d_in[6];
    const float* cw   = (const float*)d_in[7];
    const float* cb   = (const float*)d_in[8];
    const float* wq   = (const float*)d_in[9];
    const float* wk   = (const float*)d_in[10];
    const float* gw   = (const float*)d_in[11];
    const float* gb   = (const float*)d_in[12];
    const float* bw   = (const float*)d_in[13];
    const float* bb   = (const float*)d_in[14];
    const float* tcw  = (const float*)d_in[15];
    float* out = (float*)d_out;

    cudaFuncSetAttribute(k_gemm3, cudaFuncAttributeMaxDynamicSharedMemorySize, GEMM_SMEM);
    cudaFuncSetAttribute(k_attn3, cudaFuncAttributeMaxDynamicSharedMemorySize, ATTN_SMEM);

    float* wRp = nullptr;
    cudaGetSymbolAddress((void**)&wRp, g_wR);
    const float* wqR  = wRp;
    const float* wkR  = wRp + DD*DD;
    const float* gw1R = wRp + 2*DD*DD;
    const float* gw2R = wRp + 3*DD*DD;

    int y_off = (out_size > BN*NC) ? 1 : 0;
    int lbl_off = y_off + BN*NC;

    // FORK: capture-legal side-stream entry — side stream's first op must wait
    // on an event recorded in the origin (captured) stream.
    cudaEventRecord(g_eF, 0);
    cudaStreamWaitEvent(g_s1, g_eF, 0);
    // side: prep + count (independent of x/xm) run concurrent with xm
    k_prep<<<(DD*DD + 255)/256, 256, 0, g_s1>>>(wq, wk, gw, bw);
    k_count<<<16, 256, 0, g_s1>>>(to, lb);
    cudaEventRecord(g_e0, g_s1);
    // main: xm
    k_xm<<<16384, 128>>>(x);
    cudaEventRecord(g_e1, 0);
    // side: q = xm@wqR (needs xm + prep), concurrent with segsum/t1c1 on main
    cudaStreamWaitEvent(g_s1, g_e1, 0);
    k_gemm3<<<dim3(4, 32), 256, GEMM_SMEM, g_s1>>>(0, 0, wqR, 0, BN, DD, DD, DD, DD, DD,
                                                   nullptr, 0, nullptr, nullptr, nullptr,
                                                   0, 0, nullptr, 0, 0, 0, 0, nullptr, 0, 0);
    cudaEventRecord(g_e4, g_s1);
    // main: segsum (needs xm + prep/count) -> t1c1
    cudaStreamWaitEvent(0, g_e0, 0);
    k_segsum<<<dim3(8, 64), 256>>>(to, lb);
    k_t1c1<<<(TC*DD + 255)/256, 256>>>(trep, cpro);
    cudaEventRecord(g_e2, 0);
    // side: graph kernels (need t1c1), concurrent with kall/hw GEMM + attention
    cudaStreamWaitEvent(g_s1, g_e2, 0);
    k_d2cross<<<65, 128, 0, g_s1>>>();
    k_tg<<<16, 32, 0, g_s1>>>(tw, tb);
    k_cg<<<dim3(65, 17), 128, 0, g_s1>>>(cw, cb);
    if (y_off) k_ae<<<1, 65, 0, g_s1>>>(out);
    // main: fused kall = hA@wkR | hw = hA@gw1R
    k_gemm3<<<dim3(4, 66), 256, GEMM_SMEM>>>(1, 0, wkR, 1, NS, DD, DD, DD, DD, DD,
                                             nullptr, 0, nullptr, nullptr, nullptr,
                                             33, 1, gw1R, 2, NS, 0, 0, nullptr, 0, 0);
    // main: attention (needs q from side) + cf
    cudaStreamWaitEvent(0, g_e4, 0);
    k_attn3<<<dim3(32, NSPL), 256, ATTN_SMEM>>>();
    k_cf<<<4096, 96>>>();
    cudaEventRecord(g_e5, 0);
    // side: outtc + fintc (need cf + hw + adj)
    cudaStreamWaitEvent(g_s1, g_e5, 0);
    k_outtc<<<dim3(8, 16), 256, 0, g_s1>>>();
    k_fintc<<<69, 512, 0, g_s1>>>(gb);
    cudaEventRecord(g_e3, g_s1);
    // main: L0 x-rows = relu(cf@hw_tc + gb0), concurrent with outtc/fintc
    k_gemm3<<<dim3(4, 32), 256, GEMM_SMEM>>>(3, 1, nullptr, 3, BN, DD, CFLD, CFLD, DD, DD,
                                             gb, 1, nullptr, nullptr, nullptr,
                                             0, 0, nullptr, 0, 0, 0, 0, nullptr, 0, 0);
    // JOIN: hw2 needs hB rows 0..127 (fintc + L0 x-rows)
    cudaStreamWaitEvent(0, g_e3, 0);
    k_gemm3<<<dim3(4, 1), 256, GEMM_SMEM>>>(2, 0, gw2R, 2, 128, DD, DD, DD, DD, DD,
                                            nullptr, 0, nullptr, nullptr, nullptr,
                                            0, 0, nullptr, 0, 0, 0, 0, nullptr, 0, 0);
    k_gemm3<<<dim3(4, 32), 256, GEMM_SMEM>>>(3, 1, nullptr, 4, BN, DD, CFLD, CFLD, DD, DD,
                                             gb + DD, 1, nullptr, nullptr, nullptr,
                                             0, 0, nullptr, 0, 0, 0, 0, nullptr, 0, 0);
    // outputs
    k_gemm3<<<dim3(1, 32), 256, GEMM_SMEM>>>(4, 2, nullptr, 0, BN, NC, DD, DD, CFLD, NC,
                                             bb, 0, tcw, to, out + y_off,
                                             0, 0, nullptr, 0, 0, 0, 0, nullptr, 0, 0);
    k_labels<<<16, 256>>>(lb, out, lbl_off, out_size);
}

// round 13
// speedup vs baseline: 6.3133x; 1.0419x over previous
#include <cuda_runtime.h>
#include <math.h>
#include <stdint.h>

#define BN 4096
#define DD 512
#define NT 4
#define NC 65
#define TC 69          // NT + NC
#define NS 4165        // TC + BN
#define CFLD 72        // padded cf row stride
#define NSPL 9         // attention splits
#define NJT 33
#define JPT 4

// ---------------- scratch (device globals; no allocations) ----------------
__device__ float g_xm[BN*DD];
__device__ float g_q[BN*DD];
__device__ float g_kall[NS*DD];
__device__ float g_hA[NS*DD];
__device__ float g_hB[NS*DD];
__device__ float g_hw[NS*DD];
__device__ float g_hw2[72*DD];    // layer-1 (h1_tc @ gw2); rows 69..71 stay 0
__device__ float g_tsum[NT*DD];
__device__ float g_csum[NC*DD];
__device__ int   g_cntT[NT];
__device__ int   g_cntC[NC];
__device__ float g_adj[TC*TC];
__device__ float g_cross[NT*NC];
__device__ float g_cf[BN*CFLD];
__device__ float g_l69[BN*TC];
__device__ float g_mp[16*BN];
__device__ float g_zp[16*BN];
__device__ float g_C69[TC*DD];
__device__ float g_bwPad[DD*CFLD];
__device__ float g_wR[4*DD*DD];   // tf32-rounded: 0=wq 1=wk 2=gw1 3=gw2

// ---------------- static stream/event resources ----------------
static cudaStream_t g_s1;
static cudaEvent_t g_eF, g_e0, g_e1, g_e2, g_e4, g_e6;
static struct StreamInit {
    StreamInit() {
        cudaStreamCreateWithFlags(&g_s1, cudaStreamNonBlocking);
        cudaEventCreateWithFlags(&g_eF, cudaEventDisableTiming);
        cudaEventCreateWithFlags(&g_e0, cudaEventDisableTiming);
        cudaEventCreateWithFlags(&g_e1, cudaEventDisableTiming);
        cudaEventCreateWithFlags(&g_e2, cudaEventDisableTiming);
        cudaEventCreateWithFlags(&g_e4, cudaEventDisableTiming);
        cudaEventCreateWithFlags(&g_e6, cudaEventDisableTiming);
    }
} g_si;

// ---------------- tf32 / mma / cp.async helpers ----------------
__device__ __forceinline__ void mma8(float* c, uint32_t a0, uint32_t a1,
                                     uint32_t a2, uint32_t a3,
                                     uint32_t b0, uint32_t b1) {
    asm("mma.sync.aligned.m16n8k8.row.col.f32.tf32.tf32.f32 "
        "{%0,%1,%2,%3},{%4,%5,%6,%7},{%8,%9},{%0,%1,%2,%3};"
        : "+f"(c[0]), "+f"(c[1]), "+f"(c[2]), "+f"(c[3])
        : "r"(a0), "r"(a1), "r"(a2), "r"(a3), "r"(b0), "r"(b1));
}
__device__ __forceinline__ float rtf(float x) {
    uint32_t u;
    asm("cvt.rna.tf32.f32 %0, %1;" : "=r"(u) : "f"(x));
    return __uint_as_float(u);
}
__device__ __forceinline__ void cpa16(uint32_t dst, const float* src, int srcBytes) {
    asm volatile("cp.async.cg.shared.global [%0], [%1], 16, %2;"
                 :: "r"(dst), "l"(src), "r"(srcBytes));
}
#define CPA_COMMIT() asm volatile("cp.async.commit_group;" ::: "memory")
#define CPA_WAIT0()  asm volatile("cp.async.wait_group 0;" ::: "memory")

// ---------------- selectors ----------------
__device__ __forceinline__ const float* selA3(int s) {
    switch (s) {
        case 0: return g_xm;  case 1: return g_hA;  case 2: return g_hB;
        case 3: return g_cf;  case 4: return g_hA + TC*DD;
    }
    return g_xm;
}
__device__ __forceinline__ const float* selB3(int s, const float* Bp) {
    switch (s) { case 1: return g_hw; case 2: return g_bwPad; case 3: return g_hw2; }
    return Bp;
}
__device__ __forceinline__ float* selC3(int s) {
    switch (s) {
        case 0: return g_q;  case 1: return g_kall;  case 2: return g_hw;
        case 3: return g_hB + TC*DD;  case 4: return g_hA + TC*DD;
        case 5: return g_hw2;
    }
    return g_q;
}

// ---------------- xm = mean over 7x7 (tf32-rounded); src rows 69.. ---------
__global__ void k_xm(const float* __restrict__ x) {
    __shared__ float buf[4][32*49];
    int w = threadIdx.x >> 5, lane = threadIdx.x & 31;
    int base = (blockIdx.x*4 + w) * 32;
    const float* src = x + (size_t)base*49;
    float* b = buf[w];
    #pragma unroll
    for (int t = 0; t < 49; t++) b[lane + 32*t] = src[lane + 32*t];
    __syncwarp();
    float s = 0.f;
    #pragma unroll
    for (int t = 0; t < 49; t++) s += b[lane*49 + t];
    s = rtf(s * (1.f/49.f));
    int seg = base + lane;
    g_xm[seg] = s;
    g_hA[TC*DD + seg] = s;
}

// ---------------- prep: zeros, pad+round base_w, round all weights ---------
__global__ void k_prep(const float* __restrict__ wq, const float* __restrict__ wk,
                       const float* __restrict__ gw, const float* __restrict__ bw) {
    int i = blockIdx.x*256 + threadIdx.x;
    if (i < DD*DD) {
        g_wR[i]           = rtf(wq[i]);
        g_wR[DD*DD + i]   = rtf(wk[i]);
        g_wR[2*DD*DD + i] = rtf(gw[i]);
        g_wR[3*DD*DD + i] = rtf(gw[DD*DD + i]);
    }
    if (i < NT*DD) g_tsum[i] = 0.f;
    if (i < NC*DD) g_csum[i] = 0.f;
    if (i < NT) g_cntT[i] = 0;
    if (i < NC) g_cntC[i] = 0;
    if (i < TC*DD) g_C69[i] = 0.f;
    if (i < DD*CFLD) {
        int r = i / CFLD, c = i - r*CFLD;
        g_bwPad[i] = (c < NC) ? rtf(bw[r*NC + c]) : 0.f;
    }
}
__global__ void k_count(const int* __restrict__ to, const int* __restrict__ lb) {
    int i = blockIdx.x*256 + threadIdx.x;
    if (i < BN) { atomicAdd(&g_cntT[to[i]], 1); atomicAdd(&g_cntC[lb[i]], 1); }
}
__global__ void k_segsum(const int* __restrict__ to, const int* __restrict__ lb) {
    __shared__ float sT[NT][64];
    __shared__ float sC[NC][64];
    int t = threadIdx.x;
    int cr = t & 63, rr = t >> 6;
    int r0 = blockIdx.y * 64, c0 = blockIdx.x * 64;
    for (int i = t; i < NT*64; i += 256) ((float*)sT)[i] = 0.f;
    for (int i = t; i < NC*64; i += 256) ((float*)sC)[i] = 0.f;
    __syncthreads();
    for (int r = r0 + rr; r < r0 + 64; r += 4) {
        int tt = to[r], cc = lb[r];
        float v = g_xm[r*DD + c0 + cr];
        atomicAdd(&sT[tt][cr], v);
        atomicAdd(&sC[cc][cr], v);
    }
    __syncthreads();
    for (int i = t; i < NT*64; i += 256)
        atomicAdd(&g_tsum[(i>>6)*DD + c0 + (i&63)], ((float*)sT)[i]);
    for (int i = t; i < NC*64; i += 256)
        atomicAdd(&g_csum[(i>>6)*DD + c0 + (i&63)], ((float*)sC)[i]);
}
__global__ void k_t1c1(const float* __restrict__ trep, const float* __restrict__ cpro) {
    int i = blockIdx.x*256 + threadIdx.x;
    if (i >= TC*DD) return;
    int seg = i / DD, d = i % DD;
    float v;
    if (seg < NT) {
        float cnt = fmaxf((float)g_cntT[seg], 1.f);
        v = 0.9f*trep[i] + 0.1f*g_tsum[i]/cnt;
    } else {
        int c = seg - NT;
        float cnt = fmaxf((float)g_cntC[c], 1.f);
        v = 0.9f*cpro[c*DD+d] + 0.1f*g_csum[c*DD+d]/cnt;
    }
    g_hA[i] = rtf(v);
}

// ---------------- graph kernels ----------------
__global__ void k_d2cross() {
    int c = blockIdx.x;
    int w = threadIdx.x >> 5, lane = threadIdx.x & 31;
    __shared__ float sd2[NT];
    const float* t1 = g_hA;
    const float* c1 = g_hA + NT*DD;
    float s = 0.f;
    for (int d = lane; d < DD; d += 32) {
        float df = t1[w*DD+d] - c1[c*DD+d];
        s += df*df;
    }
    #pragma unroll
    for (int o = 16; o; o >>= 1) s += __shfl_xor_sync(0xffffffffu, s, o);
    if (lane == 0) sd2[w] = s;
    __syncthreads();
    if (threadIdx.x == 0) {
        float l[NT], mx = -1e30f;
        for (int t = 0; t < NT; t++) { l[t] = -sd2[t]*(1.f/16.f); mx = fmaxf(mx, l[t]); }
        float Z = 0.f;
        for (int t = 0; t < NT; t++) { l[t] = expf(l[t]-mx); Z += l[t]; }
        for (int t = 0; t < NT; t++) {
            float p = l[t]/Z;
            g_cross[t*NC + c] = p;
            g_adj[t*TC + NT + c] = p;
            g_adj[(NT+c)*TC + t] = p;
        }
    }
}
__global__ void k_tg(const float* __restrict__ tw, const float* __restrict__ tb) {
    int i = blockIdx.x >> 2, j = blockIdx.x & 3;
    int lane = threadIdx.x;
    const float* t1 = g_hA;
    float s = 0.f;
    for (int d = lane; d < DD; d += 32)
        s += fabsf(t1[i*DD+d]-t1[j*DD+d]) * tw[d];
    #pragma unroll
    for (int o = 16; o; o >>= 1) s += __shfl_xor_sync(0xffffffffu, s, o);
    if (lane == 0) {
        float v = 1.f/(1.f+expf(-(s + tb[0])));
        if (i == j) v = 0.f;
        g_adj[i*TC+j] = v;
    }
}
__global__ void k_cg(const float* __restrict__ cw, const float* __restrict__ cb) {
    int i = blockIdx.x;
    int w = threadIdx.x >> 5, lane = threadIdx.x & 31;
    int j = blockIdx.y*4 + w;
    if (j >= NC) return;
    const float* c1 = g_hA + NT*DD;
    float s = 0.f;
    for (int d = lane; d < DD; d += 32)
        s += fabsf(c1[i*DD+d]-c1[j*DD+d]) * cw[d];
    #pragma unroll
    for (int o = 16; o; o >>= 1) s += __shfl_xor_sync(0xffffffffu, s, o);
    if (lane == 0) {
        float v = 1.f/(1.f+expf(-(s + cb[0])));
        if (i == j) v = 0.f;
        g_adj[(NT+i)*TC + NT+j] = v;
    }
}
__global__ void k_ae(float* out) {
    __shared__ float s[NC];
    int c = threadIdx.x;
    float a = 0.f;
    for (int t = 0; t < NT; t++) { float p = g_cross[t*NC+c]; a += p*logf(p); }
    s[c] = a;
    __syncthreads();
    if (c == 0) { float r = 0.f; for (int i = 0; i < NC; i++) r += s[i]; out[0] = r/(float)NC; }
}

// ---------------- tf32 GEMM (cp.async double-buffered, NO hot-loop CVT) ----
#define GEMM_SMEM ((2*128*36 + 2*32*136)*4)
#define AS(p,r,c) smp[(p)*4608 + (r)*36 + (c)]
#define BS(p,r,c) smp[9216 + (p)*4352 + (r)*136 + (c)]
__global__ void __launch_bounds__(256, 2) k_gemm3(
        int aSel, int bSel, const float* __restrict__ Bp, int cSel,
        int M, int N, int K, int lda, int ldb, int ldc,
        const float* __restrict__ bias, int relu,
        const float* __restrict__ tcw, const int* __restrict__ to,
        float* yout,
        int ySplit, int aSel2, const float* __restrict__ Bp2, int cSel2, int M2,
        int ySplit2, int aSel3, const float* __restrict__ Bp3, int cSel3, int M3) {
    extern __shared__ float smp[];
    int by = blockIdx.y;
    if (ySplit2 > 0 && by >= ySplit2) {
        aSel = aSel3; Bp = Bp3; cSel = cSel3; M = M3; by -= ySplit2;
    } else if (ySplit > 0 && by >= ySplit) {
        aSel = aSel2; Bp = Bp2; cSel = cSel2; M = M2; by -= ySplit;
    }
    const float* A = selA3(aSel);
    const float* B = selB3(bSel, Bp);
    float* C = yout ? yout : selC3(cSel);
    int tid = threadIdx.x;
    int w = tid >> 5, lane = tid & 31, g = lane >> 2, t = lane & 3;
    int wm = (w & 3) * 32, wn = (w >> 2) * 64;
    int m0 = by*128, n0 = blockIdx.x*128;
    uint32_t sb = (uint32_t)__cvta_generic_to_shared(smp);

    auto fillA = [&](int p, int k0) {
        #pragma unroll
        for (int r = 0; r < 4; r++) {
            int idx = tid + 256*r;
            int row = idx >> 3, fc = idx & 7;
            int gm = m0 + row, gk = k0 + fc*4;
            int sz = 16;
            if (gm >= M) sz = 0;
            int rem = (K - gk)*4;
            if (rem < sz) sz = rem < 0 ? 0 : rem;
            const float* src = sz > 0 ? &A[(size_t)gm*lda + gk] : A;
            cpa16(sb + (uint32_t)(p*4608 + row*36 + fc*4)*4u, src, sz);
        }
    };
    auto fillB = [&](int p, int k0) {
        #pragma unroll
        for (int r = 0; r < 4; r++) {
            int idx = tid + 256*r;
            int row = idx >> 5, c4 = (idx & 31)*4;
            int gk = k0 + row, gn = n0 + c4;
            int sz = 16;
            if (gk >= K) sz = 0;
            int rem = (N - gn)*4;
            if (rem < sz) sz = rem < 0 ? 0 : rem;
            const float* src = sz > 0 ? &B[(size_t)gk*ldb + gn] : B;
            cpa16(sb + (uint32_t)(9216 + p*4352 + row*136 + c4)*4u, src, sz);
        }
    };

    float acc[2][8][4] = {};
    int nk = (K + 31) >> 5;
    fillA(0, 0); fillB(0, 0); CPA_COMMIT();
    for (int kc = 0; kc < nk; kc++) {
        CPA_WAIT0();
        __syncthreads();
        if (kc + 1 < nk) { fillA((kc+1)&1, (kc+1)*32); fillB((kc+1)&1, (kc+1)*32); CPA_COMMIT(); }
        int p = kc & 1;
        #pragma unroll
        for (int kk = 0; kk < 32; kk += 8) {
            uint32_t a[2][4];
            #pragma unroll
            for (int mi = 0; mi < 2; mi++) {
                a[mi][0] = __float_as_uint(AS(p, wm+mi*16+g  , kk+t));
                a[mi][1] = __float_as_uint(AS(p, wm+mi*16+g+8, kk+t));
                a[mi][2] = __float_as_uint(AS(p, wm+mi*16+g  , kk+t+4));
                a[mi][3] = __float_as_uint(AS(p, wm+mi*16+g+8, kk+t+4));
            }
            uint32_t b[8][2];
            #pragma unroll
            for (int ni = 0; ni < 8; ni++) {
                b[ni][0] = __float_as_uint(BS(p, kk+t  , wn+ni*8+g));
                b[ni][1] = __float_as_uint(BS(p, kk+t+4, wn+ni*8+g));
            }
            #pragma unroll
            for (int mi = 0; mi < 2; mi++)
                #pragma unroll
                for (int ni = 0; ni < 8; ni++)
                    mma8(acc[mi][ni], a[mi][0], a[mi][1], a[mi][2], a[mi][3],
                         b[ni][0], b[ni][1]);
        }
    }
    #pragma unroll
    for (int mi = 0; mi < 2; mi++) {
        int r0 = m0 + wm + mi*16 + g, r1 = r0 + 8;
        #pragma unroll
        for (int ni = 0; ni < 8; ni++) {
            int n = n0 + wn + ni*8 + 2*t;
            float bv0 = 0.f, bv1 = 0.f;
            if (bias) { if (n < N) bv0 = bias[n]; if (n+1 < N) bv1 = bias[n+1]; }
            float v00 = acc[mi][ni][0] + bv0, v01 = acc[mi][ni][1] + bv1;
            float v10 = acc[mi][ni][2] + bv0, v11 = acc[mi][ni][3] + bv1;
            if (relu) {
                v00 = fmaxf(v00, 0.f); v01 = fmaxf(v01, 0.f);
                v10 = fmaxf(v10, 0.f); v11 = fmaxf(v11, 0.f);
            }
            if (yout) {
                if (r0 < M) {
                    if (n < N)   C[(size_t)r0*ldc + n]   = tcw[to[r0]*NC + n]   * v00;
                    if (n+1 < N) C[(size_t)r0*ldc + n+1] = tcw[to[r0]*NC + n+1] * v01;
                }
                if (r1 < M) {
                    if (n < N)   C[(size_t)r1*ldc + n]   = tcw[to[r1]*NC + n]   * v10;
                    if (n+1 < N) C[(size_t)r1*ldc + n+1] = tcw[to[r1]*NC + n+1] * v11;
                }
            } else {
                v00 = rtf(v00); v01 = rtf(v01); v10 = rtf(v10); v11 = rtf(v11);
                if (r0 < M) {
                    if (n < N)   C[(size_t)r0*ldc + n]   = v00;
                    if (n+1 < N) C[(size_t)r0*ldc + n+1] = v01;
                }
                if (r1 < M) {
                    if (n < N)   C[(size_t)r1*ldc + n]   = v10;
                    if (n+1 < N) C[(size_t)r1*ldc + n+1] = v11;
                }
            }
        }
    }
}

// ---------------- attention (cp.async, streaming softmax, raw loads) -------
#define ATTN_SMEM ((2*128*36*2)*4)
#define QS(p,r,c) smp[(p)*4608 + (r)*36 + (c)]
#define KS(p,r,c) smp[9216 + (p)*4608 + (r)*36 + (c)]
__global__ void __launch_bounds__(256, 2) k_attn3() {
    extern __shared__ float smp[];
    __shared__ float sm_m[2][128];
    __shared__ float sm_z[2][128];
    int tid = threadIdx.x;
    int w = tid >> 5, lane = tid & 31, g = lane >> 2, t = lane & 3;
    int wm = (w & 3) * 32, wn = (w >> 2) * 64;
    int half = w >> 2;
    int i0 = blockIdx.x*128;
    int split = blockIdx.y;
    const float sc = 0.044194173824159216f;   // 1/sqrt(512)
    uint32_t sb = (uint32_t)__cvta_generic_to_shared(smp);

    auto fillQ = [&](int p, int k0) {
        #pragma unroll
        for (int r = 0; r < 4; r++) {
            int idx = tid + 256*r;
            int row = idx >> 3, fc = idx & 7;
            cpa16(sb + (uint32_t)(p*4608 + row*36 + fc*4)*4u,
                  &g_q[(size_t)(i0+row)*DD + k0 + fc*4], 16);
        }
    };
    auto fillK = [&](int p, int j0v, int k0) {
        #pragma unroll
        for (int r = 0; r < 4; r++) {
            int idx = tid + 256*r;
            int row = idx >> 3, fc = idx & 7;
            int gj = j0v + row;
            int sz = gj < NS ? 16 : 0;
            const float* src = sz ? &g_kall[(size_t)gj*DD + k0 + fc*4] : g_kall;
            cpa16(sb + (uint32_t)(9216 + p*4608 + row*36 + fc*4)*4u, src, sz);
        }
    };

    float mr[2][2] = {{-1e30f,-1e30f},{-1e30f,-1e30f}};
    float zr[2][2] = {{0.f,0.f},{0.f,0.f}};
    int jt0 = split*JPT;
    int jt1 = jt0 + JPT; if (jt1 > NJT) jt1 = NJT;
    int cg = 0;
    fillQ(0, 0); fillK(0, jt0*128, 0); CPA_COMMIT();
    for (int jt = jt0; jt < jt1; jt++) {
        int j0 = jt*128;
        float acc[2][8][4] = {};
        for (int c = 0; c < 16; c++, cg++) {
            CPA_WAIT0();
            __syncthreads();
            int p = cg & 1;
            if (c < 15) {
                fillQ(p^1, (c+1)*32); fillK(p^1, j0, (c+1)*32); CPA_COMMIT();
            } else if (jt + 1 < jt1) {
                fillQ(p^1, 0); fillK(p^1, (jt+1)*128, 0); CPA_COMMIT();
            }
            #pragma unroll
            for (int kk = 0; kk < 32; kk += 8) {
                uint32_t a[2][4];
                #pragma unroll
                for (int mi = 0; mi < 2; mi++) {
                    a[mi][0] = __float_as_uint(QS(p, wm+mi*16+g  , kk+t));
                    a[mi][1] = __float_as_uint(QS(p, wm+mi*16+g+8, kk+t));
                    a[mi][2] = __float_as_uint(QS(p, wm+mi*16+g  , kk+t+4));
                    a[mi][3] = __float_as_uint(QS(p, wm+mi*16+g+8, kk+t+4));
                }
                uint32_t b[8][2];
                #pragma unroll
                for (int ni = 0; ni < 8; ni++) {
                    b[ni][0] = __float_as_uint(KS(p, wn+ni*8+g, kk+t));
                    b[ni][1] = __float_as_uint(KS(p, wn+ni*8+g, kk+t+4));
                }
                #pragma unroll
                for (int mi = 0; mi < 2; mi++)
                    #pragma unroll
                    for (int ni = 0; ni < 8; ni++)
                        mma8(acc[mi][ni], a[mi][0], a[mi][1], a[mi][2], a[mi][3],
                             b[ni][0], b[ni][1]);
            }
        }
        int doL = (split == 0 && jt == 0);
        #pragma unroll
        for (int mi = 0; mi < 2; mi++) {
            int r0g = i0 + wm + mi*16 + g, r1g = r0g + 8;
            float lm0 = -1e30f, lm1 = -1e30f;
            #pragma unroll
            for (int ni = 0; ni < 8; ni++) {
                int base = j0 + wn + ni*8 + 2*t;
                float v0 = (base   < NS) ? acc[mi][ni][0]*sc : -1e30f;
                float v1 = (base+1 < NS) ? acc[mi][ni][1]*sc : -1e30f;
                float v2 = (base   < NS) ? acc[mi][ni][2]*sc : -1e30f;
                float v3 = (base+1 < NS) ? acc[mi][ni][3]*sc : -1e30f;
                acc[mi][ni][0] = v0; acc[mi][ni][1] = v1;
                acc[mi][ni][2] = v2; acc[mi][ni][3] = v3;
                if (doL) {
                    int c0 = wn + ni*8 + 2*t;
                    if (c0 < TC) {
                        g_l69[(size_t)r0g*TC + c0] = v0;
                        g_l69[(size_t)r1g*TC + c0] = v2;
                    }
                    if (c0 + 1 < TC) {
                        g_l69[(size_t)r0g*TC + c0+1] = v1;
                        g_l69[(size_t)r1g*TC + c0+1] = v3;
                    }
                }
                lm0 = fmaxf(lm0, fmaxf(v0, v1));
                lm1 = fmaxf(lm1, fmaxf(v2, v3));
            }
            lm0 = fmaxf(lm0, __shfl_xor_sync(0xffffffffu, lm0, 1));
            lm0 = fmaxf(lm0, __shfl_xor_sync(0xffffffffu, lm0, 2));
            lm1 = fmaxf(lm1, __shfl_xor_sync(0xffffffffu, lm1, 1));
            lm1 = fmaxf(lm1, __shfl_xor_sync(0xffffffffu, lm1, 2));
            float nm0 = fmaxf(mr[mi][0], lm0), nm1 = fmaxf(mr[mi][1], lm1);
            float p0 = 0.f, p1 = 0.f;
            #pragma unroll
            for (int ni = 0; ni < 8; ni++) {
                p0 += __expf(acc[mi][ni][0]-nm0) + __expf(acc[mi][ni][1]-nm0);
                p1 += __expf(acc[mi][ni][2]-nm1) + __expf(acc[mi][ni][3]-nm1);
            }
            p0 += __shfl_xor_sync(0xffffffffu, p0, 1);
            p0 += __shfl_xor_sync(0xffffffffu, p0, 2);
            p1 += __shfl_xor_sync(0xffffffffu, p1, 1);
            p1 += __shfl_xor_sync(0xffffffffu, p1, 2);
            zr[mi][0] = zr[mi][0]*__expf(mr[mi][0] - nm0) + p0; mr[mi][0] = nm0;
            zr[mi][1] = zr[mi][1]*__expf(mr[mi][1] - nm1) + p1; mr[mi][1] = nm1;
        }
    }
    if (t == 0) {
        #pragma unroll
        for (int mi = 0; mi < 2; mi++) {
            int r = wm + mi*16 + g;
            sm_m[half][r]     = mr[mi][0];  sm_z[half][r]     = zr[mi][0];
            sm_m[half][r + 8] = mr[mi][1];  sm_z[half][r + 8] = zr[mi][1];
        }
    }
    __syncthreads();
    if (tid < 128) {
        float m0 = sm_m[0][tid], m1 = sm_m[1][tid];
        float m = fmaxf(m0, m1);
        float z = sm_z[0][tid]*__expf(m0 - m) + sm_z[1][tid]*__expf(m1 - m);
        g_mp[split*BN + i0 + tid] = m;
        g_zp[split*BN + i0 + tid] = z;
    }
}

// ---------------- combine splits + first-69 softmax -> cf (tf32) ----------
__global__ void k_cf() {
    int i = blockIdx.x;
    int j = threadIdx.x;
    __shared__ float sh[2];
    if (j == 0) {
        float m = -1e30f;
        #pragma unroll
        for (int s = 0; s < NSPL; s++) m = fmaxf(m, g_mp[s*BN + i]);
        float z = 0.f;
        #pragma unroll
        for (int s = 0; s < NSPL; s++) z += g_zp[s*BN + i]*__expf(g_mp[s*BN + i] - m);
        sh[0] = m; sh[1] = 1.f/z;
    }
    __syncthreads();
    if (j < CFLD)
        g_cf[i*CFLD + j] = (j < TC) ? rtf(__expf(g_l69[i*TC + j] - sh[0]) * sh[1]) : 0.f;
}

// ---------------- GNN tc-rows partial: C69 += cf^T @ hw_x ----------------
__global__ void k_outtc() {
    __shared__ float cfs[64][72];
    __shared__ float hws[64][64];
    int t = threadIdx.x, tx = t & 63, ty = t >> 6;
    int n0 = blockIdx.x*64;
    int b0 = blockIdx.y*256;
    float acc[18];
    #pragma unroll
    for (int k = 0; k < 18; k++) acc[k] = 0.f;
    for (int bc = 0; bc < 256; bc += 64) {
        int bb = b0 + bc;
        for (int i = t; i < 64*TC; i += 256) {
            int r = i/TC, k = i%TC;
            cfs[r][k] = g_cf[(size_t)(bb+r)*CFLD + k];
        }
        for (int i = t; i < 64*64; i += 256) {
            int r = i >> 6, n = i & 63;
            hws[r][n] = g_hw[(size_t)(TC+bb+r)*DD + n0 + n];
        }
        __syncthreads();
        for (int r = 0; r < 64; r++) {
            float hv = hws[r][tx];
            #pragma unroll
            for (int k = 0; k < 18; k++) {
                int m = ty + 4*k;
                if (m < TC) acc[k] += cfs[r][m]*hv;
            }
        }
        __syncthreads();
    }
    #pragma unroll
    for (int k = 0; k < 18; k++) {
        int m = ty + 4*k;
        if (m < TC) atomicAdd(&g_C69[m*DD + n0 + tx], acc[k]);
    }
}

// ---------------- finalize tc rows (layer 0), tf32-rounded ------------
__global__ void k_fintc(const float* __restrict__ gb) {
    int m = blockIdx.x;      // 69
    int n = threadIdx.x;     // 512
    float v = g_C69[m*DD + n];
    for (int j = 0; j < TC; j++)
        v += g_adj[m*TC+j] * g_hw[j*DD + n];
    v += gb[n];
    g_hB[m*DD + n] = rtf(fmaxf(v, 0.f));
}

// ---------------- labels ----------------
__global__ void k_labels(const int* __restrict__ lb, float* out, int off, int out_size) {
    int i = blockIdx.x*256 + threadIdx.x;
    if (i < BN && off + i < out_size) out[off + i] = (float)lb[i];
}

// ======================== host ========================
extern "C" void kernel_launch(void* const* d_in, const int* in_sizes, int n_in,
                              void* d_out, int out_size) {
    const float* x    = (const float*)d_in[0];
    const int*   lb   = (const int*)d_in[1];
    const int*   to   = (const int*)d_in[2];
    const float* trep = (const float*)d_in[3];
    const float* cpro = (const float*)d_in[4];
    const float* tw   = (const float*)d_in[5];
    const float* tb   = (const float*)d_in[6];
    const float* cw   = (const float*)d_in[7];
    const float* cb   = (const float*)d_in[8];
    const float* wq   = (const float*)d_in[9];
    const float* wk   = (const float*)d_in[10];
    const float* gw   = (const float*)d_in[11];
    const float* gb   = (const float*)d_in[12];
    const float* bw   = (const float*)d_in[13];
    const float* bb   = (const float*)d_in[14];
    const float* tcw  = (const float*)d_in[15];
    float* out = (float*)d_out;

    cudaFuncSetAttribute(k_gemm3, cudaFuncAttributeMaxDynamicSharedMemorySize, GEMM_SMEM);
    cudaFuncSetAttribute(k_attn3, cudaFuncAttributeMaxDynamicSharedMemorySize, ATTN_SMEM);

    float* wRp = nullptr;
    cudaGetSymbolAddress((void**)&wRp, g_wR);
    const float* wqR  = wRp;
    const float* wkR  = wRp + DD*DD;
    const float* gw1R = wRp + 2*DD*DD;
    const float* gw2R = wRp + 3*DD*DD;

    int y_off = (out_size > BN*NC) ? 1 : 0;
    int lbl_off = y_off + BN*NC;

    // FORK (capture-legal side-stream entry)
    cudaEventRecord(g_eF, 0);
    cudaStreamWaitEvent(g_s1, g_eF, 0);
    // side: prep + count (independent of x/xm), concurrent with xm
    k_prep<<<(DD*DD + 255)/256, 256, 0, g_s1>>>(wq, wk, gw, bw);
    k_count<<<16, 256, 0, g_s1>>>(to, lb);
    cudaEventRecord(g_e0, g_s1);
    // main: xm
    k_xm<<<16384, 128>>>(x);
    cudaEventRecord(g_e1, 0);
    // side: q = xm@wqR, concurrent with segsum/t1c1 on main
    cudaStreamWaitEvent(g_s1, g_e1, 0);
    k_gemm3<<<dim3(4, 32), 256, GEMM_SMEM, g_s1>>>(0, 0, wqR, 0, BN, DD, DD, DD, DD, DD,
                                                   nullptr, 0, nullptr, nullptr, nullptr,
                                                   0, 0, nullptr, 0, 0, 0, 0, nullptr, 0, 0);
    cudaEventRecord(g_e4, g_s1);
    // main: segsum -> t1c1
    cudaStreamWaitEvent(0, g_e0, 0);
    k_segsum<<<dim3(8, 64), 256>>>(to, lb);
    k_t1c1<<<(TC*DD + 255)/256, 256>>>(trep, cpro);
    cudaEventRecord(g_e2, 0);
    // side: graphs + hw = hA@gw1R, concurrent with kall GEMM + attention on main
    cudaStreamWaitEvent(g_s1, g_e2, 0);
    k_d2cross<<<65, 128, 0, g_s1>>>();
    k_tg<<<16, 32, 0, g_s1>>>(tw, tb);
    k_cg<<<dim3(65, 17), 128, 0, g_s1>>>(cw, cb);
    if (y_off) k_ae<<<1, 65, 0, g_s1>>>(out);
    k_gemm3<<<dim3(4, 33), 256, GEMM_SMEM, g_s1>>>(1, 0, gw1R, 2, NS, DD, DD, DD, DD, DD,
                                                   nullptr, 0, nullptr, nullptr, nullptr,
                                                   0, 0, nullptr, 0, 0, 0, 0, nullptr, 0, 0);
    cudaEventRecord(g_e6, g_s1);
    // main: kall = hA@wkR
    k_gemm3<<<dim3(4, 33), 256, GEMM_SMEM>>>(1, 0, wkR, 1, NS, DD, DD, DD, DD, DD,
                                             nullptr, 0, nullptr, nullptr, nullptr,
                                             0, 0, nullptr, 0, 0, 0, 0, nullptr, 0, 0);
    // main: attention (needs q) + cf
    cudaStreamWaitEvent(0, g_e4, 0);
    k_attn3<<<dim3(32, NSPL), 256, ATTN_SMEM>>>();
    k_cf<<<4096, 96>>>();
    // main tail (needs hw + adj from side): outtc -> fintc -> hw2 -> L1x -> y
    cudaStreamWaitEvent(0, g_e6, 0);
    k_outtc<<<dim3(8, 16), 256>>>();
    k_fintc<<<69, 512>>>(gb);
    // hw2 = hB[0:69] @ gw2 -> g_hw2 (rows 69..71 stay zero; cf pad is zero)
    k_gemm3<<<dim3(4, 1), 256, GEMM_SMEM>>>(2, 0, gw2R, 5, TC, DD, DD, DD, DD, DD,
                                            nullptr, 0, nullptr, nullptr, nullptr,
                                            0, 0, nullptr, 0, 0, 0, 0, nullptr, 0, 0);
    // L1 x-rows: hA_x = relu(cf @ hw2 + gb1)
    k_gemm3<<<dim3(4, 32), 256, GEMM_SMEM>>>(3, 3, nullptr, 4, BN, DD, CFLD, CFLD, DD, DD,
                                             gb + DD, 1, nullptr, nullptr, nullptr,
                                             0, 0, nullptr, 0, 0, 0, 0, nullptr, 0, 0);
    // outputs: y = (hA_x @ bwPad + bb) * tcw[to], labels
    k_gemm3<<<dim3(1, 32), 256, GEMM_SMEM>>>(4, 2, nullptr, 0, BN, NC, DD, DD, CFLD, NC,
                                             bb, 0, tcw, to, out + y_off,
                                             0, 0, nullptr, 0, 0, 0, 0, nullptr, 0, 0);
    k_labels<<<16, 256>>>(lb, out, lbl_off, out_size);
}

// round 14
// speedup vs baseline: 6.3316x; 1.0029x over previous
#include <cuda_runtime.h>
#include <math.h>
#include <stdint.h>

#define BN 4096
#define DD 512
#define NT 4
#define NC 65
#define TC 69          // NT + NC
#define NS 4165        // TC + BN
#define CFLD 72        // padded cf row stride
#define NSPL 9         // attention splits
#define NJT 33
#define JPT 4

// ---------------- scratch (device globals; no allocations) ----------------
__device__ float g_xm[BN*DD];
__device__ float g_q[BN*DD];
__device__ float g_kall[NS*DD];
__device__ float g_hA[NS*DD];
__device__ float g_hB[NS*DD];
__device__ float g_hw[NS*DD];
__device__ float g_hw2[72*DD];    // layer-1 (h1_tc @ gw2); rows 69..71 stay 0
__device__ float g_tsum[NT*DD];
__device__ float g_csum[NC*DD];
__device__ int   g_cntT[NT];
__device__ int   g_cntC[NC];
__device__ float g_adj[TC*TC];
__device__ float g_cross[NT*NC];
__device__ float g_cf[BN*CFLD];
__device__ float g_l69[BN*TC];
__device__ float g_mp[16*BN];
__device__ float g_zp[16*BN];
__device__ float g_C69[TC*DD];
__device__ float g_bwPad[DD*CFLD];
__device__ float g_wR[4*DD*DD];   // tf32-rounded: 0=wq 1=wk 2=gw1 3=gw2

// ---------------- static stream/event resources ----------------
static cudaStream_t g_s1;
static cudaEvent_t g_eF, g_e0, g_e1, g_e2, g_e4, g_e6;
static struct StreamInit {
    StreamInit() {
        cudaStreamCreateWithFlags(&g_s1, cudaStreamNonBlocking);
        cudaEventCreateWithFlags(&g_eF, cudaEventDisableTiming);
        cudaEventCreateWithFlags(&g_e0, cudaEventDisableTiming);
        cudaEventCreateWithFlags(&g_e1, cudaEventDisableTiming);
        cudaEventCreateWithFlags(&g_e2, cudaEventDisableTiming);
        cudaEventCreateWithFlags(&g_e4, cudaEventDisableTiming);
        cudaEventCreateWithFlags(&g_e6, cudaEventDisableTiming);
    }
} g_si;

// ---------------- tf32 / mma / cp.async helpers ----------------
__device__ __forceinline__ void mma8(float* c, uint32_t a0, uint32_t a1,
                                     uint32_t a2, uint32_t a3,
                                     uint32_t b0, uint32_t b1) {
    asm("mma.sync.aligned.m16n8k8.row.col.f32.tf32.tf32.f32 "
        "{%0,%1,%2,%3},{%4,%5,%6,%7},{%8,%9},{%0,%1,%2,%3};"
        : "+f"(c[0]), "+f"(c[1]), "+f"(c[2]), "+f"(c[3])
        : "r"(a0), "r"(a1), "r"(a2), "r"(a3), "r"(b0), "r"(b1));
}
__device__ __forceinline__ float rtf(float x) {
    uint32_t u;
    asm("cvt.rna.tf32.f32 %0, %1;" : "=r"(u) : "f"(x));
    return __uint_as_float(u);
}
__device__ __forceinline__ void cpa16(uint32_t dst, const float* src, int srcBytes) {
    asm volatile("cp.async.cg.shared.global [%0], [%1], 16, %2;"
                 :: "r"(dst), "l"(src), "r"(srcBytes));
}
#define CPA_COMMIT() asm volatile("cp.async.commit_group;" ::: "memory")
#define CPA_WAIT0()  asm volatile("cp.async.wait_group 0;" ::: "memory")

// ---------------- selectors ----------------
__device__ __forceinline__ const float* selA3(int s) {
    switch (s) {
        case 0: return g_xm;  case 1: return g_hA;  case 2: return g_hB;
        case 3: return g_cf;  case 4: return g_hA + TC*DD;
    }
    return g_xm;
}
__device__ __forceinline__ const float* selB3(int s, const float* Bp) {
    switch (s) { case 1: return g_hw; case 2: return g_bwPad; case 3: return g_hw2; }
    return Bp;
}
__device__ __forceinline__ float* selC3(int s) {
    switch (s) {
        case 0: return g_q;  case 1: return g_kall;  case 2: return g_hw;
        case 3: return g_hB + TC*DD;  case 4: return g_hA + TC*DD;
        case 5: return g_hw2;
    }
    return g_q;
}

// ---------------- xm = mean over 7x7 (tf32-rounded); src rows 69.. ---------
__global__ void k_xm(const float* __restrict__ x) {
    __shared__ float buf[4][32*49];
    int w = threadIdx.x >> 5, lane = threadIdx.x & 31;
    int base = (blockIdx.x*4 + w) * 32;
    const float* src = x + (size_t)base*49;
    float* b = buf[w];
    #pragma unroll
    for (int t = 0; t < 49; t++) b[lane + 32*t] = src[lane + 32*t];
    __syncwarp();
    float s = 0.f;
    #pragma unroll
    for (int t = 0; t < 49; t++) s += b[lane*49 + t];
    s = rtf(s * (1.f/49.f));
    int seg = base + lane;
    g_xm[seg] = s;
    g_hA[TC*DD + seg] = s;
}

// ---------------- prep: zeros, pad+round base_w, round all weights ---------
__global__ void k_prep(const float* __restrict__ wq, const float* __restrict__ wk,
                       const float* __restrict__ gw, const float* __restrict__ bw) {
    int i = blockIdx.x*256 + threadIdx.x;
    if (i < DD*DD) {
        g_wR[i]           = rtf(wq[i]);
        g_wR[DD*DD + i]   = rtf(wk[i]);
        g_wR[2*DD*DD + i] = rtf(gw[i]);
        g_wR[3*DD*DD + i] = rtf(gw[DD*DD + i]);
    }
    if (i < NT*DD) g_tsum[i] = 0.f;
    if (i < NC*DD) g_csum[i] = 0.f;
    if (i < NT) g_cntT[i] = 0;
    if (i < NC) g_cntC[i] = 0;
    if (i < TC*DD) g_C69[i] = 0.f;
    if (i < DD*CFLD) {
        int r = i / CFLD, c = i - r*CFLD;
        g_bwPad[i] = (c < NC) ? rtf(bw[r*NC + c]) : 0.f;
    }
}
__global__ void k_count(const int* __restrict__ to, const int* __restrict__ lb) {
    int i = blockIdx.x*256 + threadIdx.x;
    if (i < BN) { atomicAdd(&g_cntT[to[i]], 1); atomicAdd(&g_cntC[lb[i]], 1); }
}
__global__ void k_segsum(const int* __restrict__ to, const int* __restrict__ lb) {
    __shared__ float sT[NT][64];
    __shared__ float sC[NC][64];
    int t = threadIdx.x;
    int cr = t & 63, rr = t >> 6;
    int r0 = blockIdx.y * 64, c0 = blockIdx.x * 64;
    for (int i = t; i < NT*64; i += 256) ((float*)sT)[i] = 0.f;
    for (int i = t; i < NC*64; i += 256) ((float*)sC)[i] = 0.f;
    __syncthreads();
    for (int r = r0 + rr; r < r0 + 64; r += 4) {
        int tt = to[r], cc = lb[r];
        float v = g_xm[r*DD + c0 + cr];
        atomicAdd(&sT[tt][cr], v);
        atomicAdd(&sC[cc][cr], v);
    }
    __syncthreads();
    for (int i = t; i < NT*64; i += 256)
        atomicAdd(&g_tsum[(i>>6)*DD + c0 + (i&63)], ((float*)sT)[i]);
    for (int i = t; i < NC*64; i += 256)
        atomicAdd(&g_csum[(i>>6)*DD + c0 + (i&63)], ((float*)sC)[i]);
}
__global__ void k_t1c1(const float* __restrict__ trep, const float* __restrict__ cpro) {
    int i = blockIdx.x*256 + threadIdx.x;
    if (i >= TC*DD) return;
    int seg = i / DD, d = i % DD;
    float v;
    if (seg < NT) {
        float cnt = fmaxf((float)g_cntT[seg], 1.f);
        v = 0.9f*trep[i] + 0.1f*g_tsum[i]/cnt;
    } else {
        int c = seg - NT;
        float cnt = fmaxf((float)g_cntC[c], 1.f);
        v = 0.9f*cpro[c*DD+d] + 0.1f*g_csum[c*DD+d]/cnt;
    }
    g_hA[i] = rtf(v);
}

// ---------------- graph kernels ----------------
__global__ void k_d2cross() {
    int c = blockIdx.x;
    int w = threadIdx.x >> 5, lane = threadIdx.x & 31;
    __shared__ float sd2[NT];
    const float* t1 = g_hA;
    const float* c1 = g_hA + NT*DD;
    float s = 0.f;
    for (int d = lane; d < DD; d += 32) {
        float df = t1[w*DD+d] - c1[c*DD+d];
        s += df*df;
    }
    #pragma unroll
    for (int o = 16; o; o >>= 1) s += __shfl_xor_sync(0xffffffffu, s, o);
    if (lane == 0) sd2[w] = s;
    __syncthreads();
    if (threadIdx.x == 0) {
        float l[NT], mx = -1e30f;
        for (int t = 0; t < NT; t++) { l[t] = -sd2[t]*(1.f/16.f); mx = fmaxf(mx, l[t]); }
        float Z = 0.f;
        for (int t = 0; t < NT; t++) { l[t] = expf(l[t]-mx); Z += l[t]; }
        for (int t = 0; t < NT; t++) {
            float p = l[t]/Z;
            g_cross[t*NC + c] = p;
            g_adj[t*TC + NT + c] = p;
            g_adj[(NT+c)*TC + t] = p;
        }
    }
}
__global__ void k_tg(const float* __restrict__ tw, const float* __restrict__ tb) {
    int i = blockIdx.x >> 2, j = blockIdx.x & 3;
    int lane = threadIdx.x;
    const float* t1 = g_hA;
    float s = 0.f;
    for (int d = lane; d < DD; d += 32)
        s += fabsf(t1[i*DD+d]-t1[j*DD+d]) * tw[d];
    #pragma unroll
    for (int o = 16; o; o >>= 1) s += __shfl_xor_sync(0xffffffffu, s, o);
    if (lane == 0) {
        float v = 1.f/(1.f+expf(-(s + tb[0])));
        if (i == j) v = 0.f;
        g_adj[i*TC+j] = v;
    }
}
__global__ void k_cg(const float* __restrict__ cw, const float* __restrict__ cb) {
    int i = blockIdx.x;
    int w = threadIdx.x >> 5, lane = threadIdx.x & 31;
    int j = blockIdx.y*4 + w;
    if (j >= NC) return;
    const float* c1 = g_hA + NT*DD;
    float s = 0.f;
    for (int d = lane; d < DD; d += 32)
        s += fabsf(c1[i*DD+d]-c1[j*DD+d]) * cw[d];
    #pragma unroll
    for (int o = 16; o; o >>= 1) s += __shfl_xor_sync(0xffffffffu, s, o);
    if (lane == 0) {
        float v = 1.f/(1.f+expf(-(s + cb[0])));
        if (i == j) v = 0.f;
        g_adj[(NT+i)*TC + NT+j] = v;
    }
}
__global__ void k_ae(float* out) {
    __shared__ float s[NC];
    int c = threadIdx.x;
    float a = 0.f;
    for (int t = 0; t < NT; t++) { float p = g_cross[t*NC+c]; a += p*logf(p); }
    s[c] = a;
    __syncthreads();
    if (c == 0) { float r = 0.f; for (int i = 0; i < NC; i++) r += s[i]; out[0] = r/(float)NC; }
}

// ---------------- tf32 GEMM: block tile 64x128 (grid doubles, 2+ blocks/SM)
// 8 warps: wm=(w&3)*16, wn=(w>>2)*64; warp tile 16x64, acc[8][4].
#define GEMM_SMEM ((2*64*36 + 2*32*136)*4)
#define AS(p,r,c) smp[(p)*2304 + (r)*36 + (c)]
#define BS(p,r,c) smp[4608 + (p)*4352 + (r)*136 + (c)]
__global__ void __launch_bounds__(256, 2) k_gemm3(
        int aSel, int bSel, const float* __restrict__ Bp, int cSel,
        int M, int N, int K, int lda, int ldb, int ldc,
        const float* __restrict__ bias, int relu,
        const float* __restrict__ tcw, const int* __restrict__ to,
        float* yout,
        int ySplit, int aSel2, const float* __restrict__ Bp2, int cSel2, int M2,
        int ySplit2, int aSel3, const float* __restrict__ Bp3, int cSel3, int M3) {
    extern __shared__ float smp[];
    int by = blockIdx.y;
    if (ySplit2 > 0 && by >= ySplit2) {
        aSel = aSel3; Bp = Bp3; cSel = cSel3; M = M3; by -= ySplit2;
    } else if (ySplit > 0 && by >= ySplit) {
        aSel = aSel2; Bp = Bp2; cSel = cSel2; M = M2; by -= ySplit;
    }
    const float* A = selA3(aSel);
    const float* B = selB3(bSel, Bp);
    float* C = yout ? yout : selC3(cSel);
    int tid = threadIdx.x;
    int w = tid >> 5, lane = tid & 31, g = lane >> 2, t = lane & 3;
    int wm = (w & 3) * 16, wn = (w >> 2) * 64;
    int m0 = by*64, n0 = blockIdx.x*128;
    uint32_t sb = (uint32_t)__cvta_generic_to_shared(smp);

    auto fillA = [&](int p, int k0) {
        #pragma unroll
        for (int r = 0; r < 2; r++) {
            int idx = tid + 256*r;
            int row = idx >> 3, fc = idx & 7;
            int gm = m0 + row, gk = k0 + fc*4;
            int sz = 16;
            if (gm >= M) sz = 0;
            int rem = (K - gk)*4;
            if (rem < sz) sz = rem < 0 ? 0 : rem;
            const float* src = sz > 0 ? &A[(size_t)gm*lda + gk] : A;
            cpa16(sb + (uint32_t)(p*2304 + row*36 + fc*4)*4u, src, sz);
        }
    };
    auto fillB = [&](int p, int k0) {
        #pragma unroll
        for (int r = 0; r < 4; r++) {
            int idx = tid + 256*r;
            int row = idx >> 5, c4 = (idx & 31)*4;
            int gk = k0 + row, gn = n0 + c4;
            int sz = 16;
            if (gk >= K) sz = 0;
            int rem = (N - gn)*4;
            if (rem < sz) sz = rem < 0 ? 0 : rem;
            const float* src = sz > 0 ? &B[(size_t)gk*ldb + gn] : B;
            cpa16(sb + (uint32_t)(4608 + p*4352 + row*136 + c4)*4u, src, sz);
        }
    };

    float acc[8][4] = {};
    int nk = (K + 31) >> 5;
    fillA(0, 0); fillB(0, 0); CPA_COMMIT();
    for (int kc = 0; kc < nk; kc++) {
        CPA_WAIT0();
        __syncthreads();
        if (kc + 1 < nk) { fillA((kc+1)&1, (kc+1)*32); fillB((kc+1)&1, (kc+1)*32); CPA_COMMIT(); }
        int p = kc & 1;
        #pragma unroll
        for (int kk = 0; kk < 32; kk += 8) {
            uint32_t a0 = __float_as_uint(AS(p, wm+g  , kk+t));
            uint32_t a1 = __float_as_uint(AS(p, wm+g+8, kk+t));
            uint32_t a2 = __float_as_uint(AS(p, wm+g  , kk+t+4));
            uint32_t a3 = __float_as_uint(AS(p, wm+g+8, kk+t+4));
            uint32_t b[8][2];
            #pragma unroll
            for (int ni = 0; ni < 8; ni++) {
                b[ni][0] = __float_as_uint(BS(p, kk+t  , wn+ni*8+g));
                b[ni][1] = __float_as_uint(BS(p, kk+t+4, wn+ni*8+g));
            }
            #pragma unroll
            for (int ni = 0; ni < 8; ni++)
                mma8(acc[ni], a0, a1, a2, a3, b[ni][0], b[ni][1]);
        }
    }
    int r0 = m0 + wm + g, r1 = r0 + 8;
    #pragma unroll
    for (int ni = 0; ni < 8; ni++) {
        int n = n0 + wn + ni*8 + 2*t;
        float bv0 = 0.f, bv1 = 0.f;
        if (bias) { if (n < N) bv0 = bias[n]; if (n+1 < N) bv1 = bias[n+1]; }
        float v00 = acc[ni][0] + bv0, v01 = acc[ni][1] + bv1;
        float v10 = acc[ni][2] + bv0, v11 = acc[ni][3] + bv1;
        if (relu) {
            v00 = fmaxf(v00, 0.f); v01 = fmaxf(v01, 0.f);
            v10 = fmaxf(v10, 0.f); v11 = fmaxf(v11, 0.f);
        }
        if (yout) {
            if (r0 < M) {
                if (n < N)   C[(size_t)r0*ldc + n]   = tcw[to[r0]*NC + n]   * v00;
                if (n+1 < N) C[(size_t)r0*ldc + n+1] = tcw[to[r0]*NC + n+1] * v01;
            }
            if (r1 < M) {
                if (n < N)   C[(size_t)r1*ldc + n]   = tcw[to[r1]*NC + n]   * v10;
                if (n+1 < N) C[(size_t)r1*ldc + n+1] = tcw[to[r1]*NC + n+1] * v11;
            }
        } else {
            v00 = rtf(v00); v01 = rtf(v01); v10 = rtf(v10); v11 = rtf(v11);
            if (r0 < M) {
                if (n < N)   C[(size_t)r0*ldc + n]   = v00;
                if (n+1 < N) C[(size_t)r0*ldc + n+1] = v01;
            }
            if (r1 < M) {
                if (n < N)   C[(size_t)r1*ldc + n]   = v10;
                if (n+1 < N) C[(size_t)r1*ldc + n+1] = v11;
            }
        }
    }
}

// ---------------- attention (cp.async, streaming softmax, raw loads) -------
#define ATTN_SMEM ((2*128*36*2)*4)
#define QS(p,r,c) smp[(p)*4608 + (r)*36 + (c)]
#define KS(p,r,c) smp[9216 + (p)*4608 + (r)*36 + (c)]
__global__ void __launch_bounds__(256, 2) k_attn3() {
    extern __shared__ float smp[];
    __shared__ float sm_m[2][128];
    __shared__ float sm_z[2][128];
    int tid = threadIdx.x;
    int w = tid >> 5, lane = tid & 31, g = lane >> 2, t = lane & 3;
    int wm = (w & 3) * 32, wn = (w >> 2) * 64;
    int half = w >> 2;
    int i0 = blockIdx.x*128;
    int split = blockIdx.y;
    const float sc = 0.044194173824159216f;   // 1/sqrt(512)
    uint32_t sb = (uint32_t)__cvta_generic_to_shared(smp);

    auto fillQ = [&](int p, int k0) {
        #pragma unroll
        for (int r = 0; r < 4; r++) {
            int idx = tid + 256*r;
            int row = idx >> 3, fc = idx & 7;
            cpa16(sb + (uint32_t)(p*4608 + row*36 + fc*4)*4u,
                  &g_q[(size_t)(i0+row)*DD + k0 + fc*4], 16);
        }
    };
    auto fillK = [&](int p, int j0v, int k0) {
        #pragma unroll
        for (int r = 0; r < 4; r++) {
            int idx = tid + 256*r;
            int row = idx >> 3, fc = idx & 7;
            int gj = j0v + row;
            int sz = gj < NS ? 16 : 0;
            const float* src = sz ? &g_kall[(size_t)gj*DD + k0 + fc*4] : g_kall;
            cpa16(sb + (uint32_t)(9216 + p*4608 + row*36 + fc*4)*4u, src, sz);
        }
    };

    float mr[2][2] = {{-1e30f,-1e30f},{-1e30f,-1e30f}};
    float zr[2][2] = {{0.f,0.f},{0.f,0.f}};
    int jt0 = split*JPT;
    int jt1 = jt0 + JPT; if (jt1 > NJT) jt1 = NJT;
    int cg = 0;
    fillQ(0, 0); fillK(0, jt0*128, 0); CPA_COMMIT();
    for (int jt = jt0; jt < jt1; jt++) {
        int j0 = jt*128;
        float acc[2][8][4] = {};
        for (int c = 0; c < 16; c++, cg++) {
            CPA_WAIT0();
            __syncthreads();
            int p = cg & 1;
            if (c < 15) {
                fillQ(p^1, (c+1)*32); fillK(p^1, j0, (c+1)*32); CPA_COMMIT();
            } else if (jt + 1 < jt1) {
                fillQ(p^1, 0); fillK(p^1, (jt+1)*128, 0); CPA_COMMIT();
            }
            #pragma unroll
            for (int kk = 0; kk < 32; kk += 8) {
                uint32_t a[2][4];
                #pragma unroll
                for (int mi = 0; mi < 2; mi++) {
                    a[mi][0] = __float_as_uint(QS(p, wm+mi*16+g  , kk+t));
                    a[mi][1] = __float_as_uint(QS(p, wm+mi*16+g+8, kk+t));
                    a[mi][2] = __float_as_uint(QS(p, wm+mi*16+g  , kk+t+4));
                    a[mi][3] = __float_as_uint(QS(p, wm+mi*16+g+8, kk+t+4));
                }
                uint32_t b[8][2];
                #pragma unroll
                for (int ni = 0; ni < 8; ni++) {
                    b[ni][0] = __float_as_uint(KS(p, wn+ni*8+g, kk+t));
                    b[ni][1] = __float_as_uint(KS(p, wn+ni*8+g, kk+t+4));
                }
                #pragma unroll
                for (int mi = 0; mi < 2; mi++)
                    #pragma unroll
                    for (int ni = 0; ni < 8; ni++)
                        mma8(acc[mi][ni], a[mi][0], a[mi][1], a[mi][2], a[mi][3],
                             b[ni][0], b[ni][1]);
            }
        }
        int doL = (split == 0 && jt == 0);
        #pragma unroll
        for (int mi = 0; mi < 2; mi++) {
            int r0g = i0 + wm + mi*16 + g, r1g = r0g + 8;
            float lm0 = -1e30f, lm1 = -1e30f;
            #pragma unroll
            for (int ni = 0; ni < 8; ni++) {
                int base = j0 + wn + ni*8 + 2*t;
                float v0 = (base   < NS) ? acc[mi][ni][0]*sc : -1e30f;
                float v1 = (base+1 < NS) ? acc[mi][ni][1]*sc : -1e30f;
                float v2 = (base   < NS) ? acc[mi][ni][2]*sc : -1e30f;
                float v3 = (base+1 < NS) ? acc[mi][ni][3]*sc : -1e30f;
                acc[mi][ni][0] = v0; acc[mi][ni][1] = v1;
                acc[mi][ni][2] = v2; acc[mi][ni][3] = v3;
                if (doL) {
                    int c0 = wn + ni*8 + 2*t;
                    if (c0 < TC) {
                        g_l69[(size_t)r0g*TC + c0] = v0;
                        g_l69[(size_t)r1g*TC + c0] = v2;
                    }
                    if (c0 + 1 < TC) {
                        g_l69[(size_t)r0g*TC + c0+1] = v1;
                        g_l69[(size_t)r1g*TC + c0+1] = v3;
                    }
                }
                lm0 = fmaxf(lm0, fmaxf(v0, v1));
                lm1 = fmaxf(lm1, fmaxf(v2, v3));
            }
            lm0 = fmaxf(lm0, __shfl_xor_sync(0xffffffffu, lm0, 1));
            lm0 = fmaxf(lm0, __shfl_xor_sync(0xffffffffu, lm0, 2));
            lm1 = fmaxf(lm1, __shfl_xor_sync(0xffffffffu, lm1, 1));
            lm1 = fmaxf(lm1, __shfl_xor_sync(0xffffffffu, lm1, 2));
            float nm0 = fmaxf(mr[mi][0], lm0), nm1 = fmaxf(mr[mi][1], lm1);
            float p0 = 0.f, p1 = 0.f;
            #pragma unroll
            for (int ni = 0; ni < 8; ni++) {
                p0 += __expf(acc[mi][ni][0]-nm0) + __expf(acc[mi][ni][1]-nm0);
                p1 += __expf(acc[mi][ni][2]-nm1) + __expf(acc[mi][ni][3]-nm1);
            }
            p0 += __shfl_xor_sync(0xffffffffu, p0, 1);
            p0 += __shfl_xor_sync(0xffffffffu, p0, 2);
            p1 += __shfl_xor_sync(0xffffffffu, p1, 1);
            p1 += __shfl_xor_sync(0xffffffffu, p1, 2);
            zr[mi][0] = zr[mi][0]*__expf(mr[mi][0] - nm0) + p0; mr[mi][0] = nm0;
            zr[mi][1] = zr[mi][1]*__expf(mr[mi][1] - nm1) + p1; mr[mi][1] = nm1;
        }
    }
    if (t == 0) {
        #pragma unroll
        for (int mi = 0; mi < 2; mi++) {
            int r = wm + mi*16 + g;
            sm_m[half][r]     = mr[mi][0];  sm_z[half][r]     = zr[mi][0];
            sm_m[half][r + 8] = mr[mi][1];  sm_z[half][r + 8] = zr[mi][1];
        }
    }
    __syncthreads();
    if (tid < 128) {
        float m0 = sm_m[0][tid], m1 = sm_m[1][tid];
        float m = fmaxf(m0, m1);
        float z = sm_z[0][tid]*__expf(m0 - m) + sm_z[1][tid]*__expf(m1 - m);
        g_mp[split*BN + i0 + tid] = m;
        g_zp[split*BN + i0 + tid] = z;
    }
}

// ---------------- combine splits + first-69 softmax -> cf (tf32) ----------
__global__ void k_cf() {
    int i = blockIdx.x;
    int j = threadIdx.x;
    __shared__ float sh[2];
    if (j == 0) {
        float m = -1e30f;
        #pragma unroll
        for (int s = 0; s < NSPL; s++) m = fmaxf(m, g_mp[s*BN + i]);
        float z = 0.f;
        #pragma unroll
        for (int s = 0; s < NSPL; s++) z += g_zp[s*BN + i]*__expf(g_mp[s*BN + i] - m);
        sh[0] = m; sh[1] = 1.f/z;
    }
    __syncthreads();
    if (j < CFLD)
        g_cf[i*CFLD + j] = (j < TC) ? rtf(__expf(g_l69[i*TC + j] - sh[0]) * sh[1]) : 0.f;
}

// ---------------- GNN tc-rows partial: C69 += cf^T @ hw_x ----------------
__global__ void k_outtc() {
    __shared__ float cfs[64][72];
    __shared__ float hws[64][64];
    int t = threadIdx.x, tx = t & 63, ty = t >> 6;
    int n0 = blockIdx.x*64;
    int b0 = blockIdx.y*256;
    float acc[18];
    #pragma unroll
    for (int k = 0; k < 18; k++) acc[k] = 0.f;
    for (int bc = 0; bc < 256; bc += 64) {
        int bb = b0 + bc;
        for (int i = t; i < 64*TC; i += 256) {
            int r = i/TC, k = i%TC;
            cfs[r][k] = g_cf[(size_t)(bb+r)*CFLD + k];
        }
        for (int i = t; i < 64*64; i += 256) {
            int r = i >> 6, n = i & 63;
            hws[r][n] = g_hw[(size_t)(TC+bb+r)*DD + n0 + n];
        }
        __syncthreads();
        for (int r = 0; r < 64; r++) {
            float hv = hws[r][tx];
            #pragma unroll
            for (int k = 0; k < 18; k++) {
                int m = ty + 4*k;
                if (m < TC) acc[k] += cfs[r][m]*hv;
            }
        }
        __syncthreads();
    }
    #pragma unroll
    for (int k = 0; k < 18; k++) {
        int m = ty + 4*k;
        if (m < TC) atomicAdd(&g_C69[m*DD + n0 + tx], acc[k]);
    }
}

// ---------------- finalize tc rows (layer 0), tf32-rounded ------------
__global__ void k_fintc(const float* __restrict__ gb) {
    int m = blockIdx.x;      // 69
    int n = threadIdx.x;     // 512
    float v = g_C69[m*DD + n];
    for (int j = 0; j < TC; j++)
        v += g_adj[m*TC+j] * g_hw[j*DD + n];
    v += gb[n];
    g_hB[m*DD + n] = rtf(fmaxf(v, 0.f));
}

// ---------------- labels ----------------
__global__ void k_labels(const int* __restrict__ lb, float* out, int off, int out_size) {
    int i = blockIdx.x*256 + threadIdx.x;
    if (i < BN && off + i < out_size) out[off + i] = (float)lb[i];
}

// ======================== host ========================
extern "C" void kernel_launch(void* const* d_in, const int* in_sizes, int n_in,
                              void* d_out, int out_size) {
    const float* x    = (const float*)d_in[0];
    const int*   lb   = (const int*)d_in[1];
    const int*   to   = (const int*)d_in[2];
    const float* trep = (const float*)d_in[3];
    const float* cpro = (const float*)d_in[4];
    const float* tw   = (const float*)d_in[5];
    const float* tb   = (const float*)d_in[6];
    const float* cw   = (const float*)d_in[7];
    const float* cb   = (const float*)d_in[8];
    const float* wq   = (const float*)d_in[9];
    const float* wk   = (const float*)d_in[10];
    const float* gw   = (const float*)d_in[11];
    const float* gb   = (const float*)d_in[12];
    const float* bw   = (const float*)d_in[13];
    const float* bb   = (const float*)d_in[14];
    const float* tcw  = (const float*)d_in[15];
    float* out = (float*)d_out;

    cudaFuncSetAttribute(k_gemm3, cudaFuncAttributeMaxDynamicSharedMemorySize, GEMM_SMEM);
    cudaFuncSetAttribute(k_attn3, cudaFuncAttributeMaxDynamicSharedMemorySize, ATTN_SMEM);

    float* wRp = nullptr;
    cudaGetSymbolAddress((void**)&wRp, g_wR);
    const float* wqR  = wRp;
    const float* wkR  = wRp + DD*DD;
    const float* gw1R = wRp + 2*DD*DD;
    const float* gw2R = wRp + 3*DD*DD;

    int y_off = (out_size > BN*NC) ? 1 : 0;
    int lbl_off = y_off + BN*NC;

    // FORK (capture-legal side-stream entry)
    cudaEventRecord(g_eF, 0);
    cudaStreamWaitEvent(g_s1, g_eF, 0);
    // side: prep + count (independent of x/xm), concurrent with xm
    k_prep<<<(DD*DD + 255)/256, 256, 0, g_s1>>>(wq, wk, gw, bw);
    k_count<<<16, 256, 0, g_s1>>>(to, lb);
    cudaEventRecord(g_e0, g_s1);
    // main: xm
    k_xm<<<16384, 128>>>(x);
    cudaEventRecord(g_e1, 0);
    // side: q = xm@wqR, concurrent with segsum/t1c1 on main
    cudaStreamWaitEvent(g_s1, g_e1, 0);
    k_gemm3<<<dim3(4, 64), 256, GEMM_SMEM, g_s1>>>(0, 0, wqR, 0, BN, DD, DD, DD, DD, DD,
                                                   nullptr, 0, nullptr, nullptr, nullptr,
                                                   0, 0, nullptr, 0, 0, 0, 0, nullptr, 0, 0);
    cudaEventRecord(g_e4, g_s1);
    // main: segsum -> t1c1
    cudaStreamWaitEvent(0, g_e0, 0);
    k_segsum<<<dim3(8, 64), 256>>>(to, lb);
    k_t1c1<<<(TC*DD + 255)/256, 256>>>(trep, cpro);
    cudaEventRecord(g_e2, 0);
    // side: graphs + hw = hA@gw1R, concurrent with kall GEMM + attention on main
    cudaStreamWaitEvent(g_s1, g_e2, 0);
    k_d2cross<<<65, 128, 0, g_s1>>>();
    k_tg<<<16, 32, 0, g_s1>>>(tw, tb);
    k_cg<<<dim3(65, 17), 128, 0, g_s1>>>(cw, cb);
    if (y_off) k_ae<<<1, 65, 0, g_s1>>>(out);
    k_gemm3<<<dim3(4, 66), 256, GEMM_SMEM, g_s1>>>(1, 0, gw1R, 2, NS, DD, DD, DD, DD, DD,
                                                   nullptr, 0, nullptr, nullptr, nullptr,
                                                   0, 0, nullptr, 0, 0, 0, 0, nullptr, 0, 0);
    cudaEventRecord(g_e6, g_s1);
    // main: kall = hA@wkR
    k_gemm3<<<dim3(4, 66), 256, GEMM_SMEM>>>(1, 0, wkR, 1, NS, DD, DD, DD, DD, DD,
                                             nullptr, 0, nullptr, nullptr, nullptr,
                                             0, 0, nullptr, 0, 0, 0, 0, nullptr, 0, 0);
    // main: attention (needs q) + cf
    cudaStreamWaitEvent(0, g_e4, 0);
    k_attn3<<<dim3(32, NSPL), 256, ATTN_SMEM>>>();
    k_cf<<<4096, 96>>>();
    // main tail (needs hw + adj from side): outtc -> fintc -> hw2 -> L1x -> y
    cudaStreamWaitEvent(0, g_e6, 0);
    k_outtc<<<dim3(8, 16), 256>>>();
    k_fintc<<<69, 512>>>(gb);
    // hw2 = hB[0:69] @ gw2 -> g_hw2 (rows 69..71 stay zero; cf pad is zero)
    k_gemm3<<<dim3(4, 2), 256, GEMM_SMEM>>>(2, 0, gw2R, 5, TC, DD, DD, DD, DD, DD,
                                            nullptr, 0, nullptr, nullptr, nullptr,
                                            0, 0, nullptr, 0, 0, 0, 0, nullptr, 0, 0);
    // L1 x-rows: hA_x = relu(cf @ hw2 + gb1)
    k_gemm3<<<dim3(4, 64), 256, GEMM_SMEM>>>(3, 3, nullptr, 4, BN, DD, CFLD, CFLD, DD, DD,
                                             gb + DD, 1, nullptr, nullptr, nullptr,
                                             0, 0, nullptr, 0, 0, 0, 0, nullptr, 0, 0);
    // outputs: y = (hA_x @ bwPad + bb) * tcw[to], labels
    k_gemm3<<<dim3(1, 64), 256, GEMM_SMEM>>>(4, 2, nullptr, 0, BN, NC, DD, DD, CFLD, NC,
                                             bb, 0, tcw, to, out + y_off,
                                             0, 0, nullptr, 0, 0, 0, 0, nullptr, 0, 0);
    k_labels<<<16, 256>>>(lb, out, lbl_off, out_size);
}